// round 7
// baseline (speedup 1.0000x reference)
#include <cuda_runtime.h>
#include <cuda_fp16.h>
#include <cstdint>
#include <math.h>

#define BATCH 16
#define S1 61
#define SEQ 3721
#define DMODEL 128
#define HEADS 8
#define DH 16
#define NLAYER 4
#define FFDIM 512
#define PCH 49
#define MROWS (BATCH * SEQ) // 59536
#define MTILES ((MROWS + 127) / 128) // 466

// ---------------------------------------------------------------- scratch
__device__ __half g_p[MROWS * 64];
__device__ float  g_h[MROWS * 128];
__device__ __half g_ln[MROWS * 128];
__device__ __half g_qkv[(size_t)MROWS * 384];
__device__ __half g_att[MROWS * 128];
__device__ __half g_ff[(size_t)MROWS * 512];
__device__ __half g_hh[MROWS * 128];
__device__ __half g_wlt[128 * 64];
__device__ __half g_wqkv[NLAYER * 384 * 128];
__device__ __half g_wo[NLAYER * 128 * 128];
__device__ __half g_wf1[NLAYER * 512 * 128];
__device__ __half g_wf2[NLAYER * 128 * 512];
__device__ __half g_wp1[128 * 128];

// ---------------------------------------------------------------- helpers
__device__ __forceinline__ uint32_t smem_u32(const void* p) {
    uint32_t a;
    asm("{ .reg .u64 t; cvta.to.shared.u64 t, %1; cvt.u32.u64 %0, t; }" : "=r"(a) : "l"(p));
    return a;
}
__device__ __forceinline__ void ldsm4(uint32_t* r, uint32_t addr) {
    asm volatile("ldmatrix.sync.aligned.m8n8.x4.shared.b16 {%0,%1,%2,%3}, [%4];"
                 : "=r"(r[0]), "=r"(r[1]), "=r"(r[2]), "=r"(r[3]) : "r"(addr));
}
__device__ __forceinline__ void mma16816(float* c, const uint32_t* a, uint32_t b0, uint32_t b1) {
    asm volatile("mma.sync.aligned.m16n8k16.row.col.f32.f16.f16.f32 "
                 "{%0,%1,%2,%3}, {%4,%5,%6,%7}, {%8,%9}, {%0,%1,%2,%3};"
                 : "+f"(c[0]), "+f"(c[1]), "+f"(c[2]), "+f"(c[3])
                 : "r"(a[0]), "r"(a[1]), "r"(a[2]), "r"(a[3]), "r"(b0), "r"(b1));
}
__device__ __forceinline__ void cpasync16(uint32_t saddr, const void* g, uint32_t ssz) {
    asm volatile("cp.async.cg.shared.global [%0], [%1], 16, %2;"
                 :: "r"(saddr), "l"(g), "r"(ssz));
}
#define CP_COMMIT() asm volatile("cp.async.commit_group;" ::: "memory")
#define CP_WAIT(n)  asm volatile("cp.async.wait_group %0;" :: "n"(n) : "memory")

// ------------------------------------------- single fused weight prep --------
__global__ void prep_all(const float* __restrict__ lt_w, const float* __restrict__ wq,
                         const float* __restrict__ wk, const float* __restrict__ wv,
                         const float* __restrict__ wo, const float* __restrict__ ff_w1,
                         const float* __restrict__ ff_w2, const float* __restrict__ pre_w1,
                         __half* __restrict__ wlt, __half* __restrict__ wqkv,
                         __half* __restrict__ woh, __half* __restrict__ wf1,
                         __half* __restrict__ wf2, __half* __restrict__ wp1) {
    long t = (long)blockIdx.x * blockDim.x + threadIdx.x;
    if (t < 8192) {                       // lt: [128][64] <- [49,128]
        int n = (int)(t >> 6), kk = (int)(t & 63);
        wlt[t] = __float2half(kk < 49 ? lt_w[kk * 128 + n] : 0.f);
        return;
    }
    t -= 8192;
    if (t < 196608) {                     // qkv: [L][384][128]
        int l = (int)(t / 49152), r = (int)(t % 49152);
        int n = r >> 7, kk = r & 127;
        int s = n >> 7, nn = n & 127;
        const float* W = (s == 0 ? wq : s == 1 ? wk : wv) + (long)l * 16384;
        wqkv[t] = __float2half(W[kk * 128 + nn]);
        return;
    }
    t -= 196608;
    if (t < 65536) {                      // wo: [L][128][128]
        int l = (int)(t / 16384), r = (int)(t % 16384);
        int n = r >> 7, kk = r & 127;
        woh[t] = __float2half(wo[(long)l * 16384 + kk * 128 + n]);
        return;
    }
    t -= 65536;
    if (t < 262144) {                     // ff1: [L][512][128] <- [128,512]
        int l = (int)(t / 65536), r = (int)(t % 65536);
        int n = r >> 7, kk = r & 127;
        wf1[t] = __float2half(ff_w1[(long)l * 65536 + (long)kk * 512 + n]);
        return;
    }
    t -= 262144;
    if (t < 262144) {                     // ff2: [L][128][512] <- [512,128]
        int l = (int)(t / 65536), r = (int)(t % 65536);
        int n = r / 512, kk = r % 512;
        wf2[t] = __float2half(ff_w2[(long)l * 65536 + (long)kk * 128 + n]);
        return;
    }
    t -= 262144;
    if (t < 16384) {                      // pre_w1: [128][128]
        int n = (int)(t >> 7), kk = (int)(t & 127);
        wp1[t] = __float2half(pre_w1[kk * 128 + n]);
    }
}
#define PREP_TOTAL (8192 + 196608 + 65536 + 262144 + 262144 + 16384)

// ---------------- conv 7x7 'same' + relu -> fp16 [M,64] ----------------------
__global__ void conv_k(const float* __restrict__ x, const float* __restrict__ cw,
                       const float* __restrict__ cb, __half* __restrict__ p) {
    int t = blockIdx.x * blockDim.x + threadIdx.x;
    if (t >= MROWS * 64) return;
    int o = t & 63;
    float sum = 0.f;
    if (o < PCH) {
        int s = (t >> 6) % SEQ;
        int b = (t >> 6) / SEQ;
        int y = s / S1, xx = s % S1;
        const float* xb = x + (long)b * SEQ;
        const float* wo = cw + o * 49;
        sum = cb[o];
#pragma unroll
        for (int dy = 0; dy < 7; dy++) {
            int iy = y + dy - 3;
            if (iy < 0 || iy >= S1) continue;
#pragma unroll
            for (int dx = 0; dx < 7; dx++) {
                int ix = xx + dx - 3;
                if (ix < 0 || ix >= S1) continue;
                sum += xb[iy * S1 + ix] * wo[dy * 7 + dx];
            }
        }
        sum = fmaxf(sum, 0.f);
    }
    p[t] = __float2half(sum);
}

// =============== A-resident fp16 GEMM (K<=128), N-loop inside ================
// EPI: 0 -> fp16 Ch (qkv); 2 +bias+pos -> fp32 C (+LN->lnout);
//      3 +bias+res -> fp32 C (+LN->lnout); 4 gelu(+bias)->fp16 Ch;
//      5 head row-reduce
template <int EPI, int NK>
__global__ void __launch_bounds__(256, 2)
tgemmA(const __half* __restrict__ A, const __half* __restrict__ B,
       const float* __restrict__ bias, const float* __restrict__ res,
       const float* __restrict__ pos, const float* __restrict__ w2,
       float* __restrict__ C, __half* __restrict__ Ch,
       const float* __restrict__ lnsc, const float* __restrict__ lnbi,
       __half* __restrict__ lnout, int M, int Nfull, int NT) {
    extern __shared__ char sm[];
    __shared__ float red[2][128];
    __shared__ float lnred[2][128][2];
    uint32_t sb = smem_u32(sm);
    const int K = NK * 64;
    const uint32_t ABYTES = (uint32_t)NK * 16384u;
    int tid = threadIdx.x;
    int w = tid >> 5, lane = tid & 31;
    int wm = w & 3, wn = w >> 2;
    int m0 = blockIdx.y * 128;

    int rA[2], rB[4];
#pragma unroll
    for (int mi = 0; mi < 2; mi++) rA[mi] = wm * 32 + mi * 16 + (lane & 15);
#pragma unroll
    for (int ng = 0; ng < 4; ng++)
        rB[ng] = wn * 64 + ng * 16 + ((lane >> 4) << 3) + (lane & 7);
    int cA = lane >> 4;
    int cB = (lane >> 3) & 1;

#pragma unroll
    for (int t = 0; t < NK * 4; t++) {
        int slot = t * 256 + tid;
        int tile = slot >> 10;
        int idx = slot & 1023;
        int row = idx >> 3, c16 = idx & 7;
        long grow = m0 + row;
        bool ok = grow < M;
        if (!ok) grow = 0;
        cpasync16(sb + (uint32_t)tile * 16384u + row * 128 + (((uint32_t)c16 ^ (row & 7)) << 4),
                  A + grow * K + tile * 64 + c16 * 8, ok ? 16u : 0u);
    }
    CP_COMMIT();

    auto loadB = [&](int nt) {
#pragma unroll
        for (int t = 0; t < NK * 4; t++) {
            int slot = t * 256 + tid;
            int tile = slot >> 10;
            int idx = slot & 1023;
            int row = idx >> 3, c16 = idx & 7;
            long grow = (long)(nt * 128 + row);
            cpasync16(sb + ABYTES + (uint32_t)(nt & 1) * ABYTES + (uint32_t)tile * 16384u +
                          row * 128 + (((uint32_t)c16 ^ (row & 7)) << 4),
                      B + grow * K + tile * 64 + c16 * 8, 16u);
        }
        CP_COMMIT();
    };
    loadB(0);

    for (int nt = 0; nt < NT; nt++) {
        if (nt + 1 < NT) { loadB(nt + 1); CP_WAIT(1); }
        else             { CP_WAIT(0); }
        __syncthreads();

        float acc[2][8][4];
#pragma unroll
        for (int i = 0; i < 2; i++)
#pragma unroll
            for (int j = 0; j < 8; j++)
#pragma unroll
                for (int q = 0; q < 4; q++) acc[i][j][q] = 0.f;

        uint32_t Bbase = sb + ABYTES + (uint32_t)(nt & 1) * ABYTES;
#pragma unroll
        for (int i = 0; i < NK * 4; i++) {
            int chunk = i >> 2, ks = i & 3, kc = ks * 2;
            uint32_t Ab = sb + (uint32_t)chunk * 16384u;
            uint32_t Bb = Bbase + (uint32_t)chunk * 16384u;
            uint32_t fa[2][4], fb[4][4];
#pragma unroll
            for (int mi = 0; mi < 2; mi++) {
                int row = rA[mi];
                ldsm4(fa[mi], Ab + row * 128 + ((((uint32_t)(kc + cA)) ^ (row & 7)) << 4));
            }
#pragma unroll
            for (int ng = 0; ng < 4; ng++) {
                int row = rB[ng];
                ldsm4(fb[ng], Bb + row * 128 + ((((uint32_t)(kc + cB)) ^ (row & 7)) << 4));
            }
#pragma unroll
            for (int ng = 0; ng < 4; ng++)
#pragma unroll
                for (int mi = 0; mi < 2; mi++) {
                    mma16816(acc[mi][ng * 2],     fa[mi], fb[ng][0], fb[ng][1]);
                    mma16816(acc[mi][ng * 2 + 1], fa[mi], fb[ng][2], fb[ng][3]);
                }
        }
        __syncthreads();

        int n0 = nt * 128;
        int tg = lane >> 2;
        int tc = (lane & 3) * 2;

        if (EPI == 5) {
            float p[2][2] = {};
#pragma unroll
            for (int mi = 0; mi < 2; mi++)
#pragma unroll
                for (int ni = 0; ni < 8; ni++) {
                    int col = wn * 64 + ni * 8 + tc;
                    float b0 = bias[col], b1 = bias[col + 1];
                    float w20 = w2[col], w21 = w2[col + 1];
                    p[mi][0] += fmaxf(acc[mi][ni][0] + b0, 0.f) * w20 +
                                fmaxf(acc[mi][ni][1] + b1, 0.f) * w21;
                    p[mi][1] += fmaxf(acc[mi][ni][2] + b0, 0.f) * w20 +
                                fmaxf(acc[mi][ni][3] + b1, 0.f) * w21;
                }
#pragma unroll
            for (int mi = 0; mi < 2; mi++)
#pragma unroll
                for (int hf = 0; hf < 2; hf++) {
                    float v = p[mi][hf];
                    v += __shfl_xor_sync(~0u, v, 1);
                    v += __shfl_xor_sync(~0u, v, 2);
                    if ((lane & 3) == 0) red[wn][wm * 32 + mi * 16 + hf * 8 + tg] = v;
                }
            __syncthreads();
            if (tid < 128) {
                int row = m0 + tid;
                if (row < M) C[row] = red[0][tid] + red[1][tid] + pos[0];
            }
            continue;
        }

        if (EPI == 0 || EPI == 4) {
#pragma unroll
            for (int mi = 0; mi < 2; mi++)
#pragma unroll
                for (int hf = 0; hf < 2; hf++) {
                    int row = m0 + wm * 32 + mi * 16 + hf * 8 + tg;
                    if (row >= M) continue;
#pragma unroll
                    for (int ni = 0; ni < 8; ni++) {
                        int col = n0 + wn * 64 + ni * 8 + tc;
                        float v0 = acc[mi][ni][hf * 2 + 0];
                        float v1 = acc[mi][ni][hf * 2 + 1];
                        if (EPI == 4) {
                            v0 += bias[col];
                            v1 += bias[col + 1];
                            v0 = 0.5f * v0 * (1.f + erff(v0 * 0.70710678118654752f));
                            v1 = 0.5f * v1 * (1.f + erff(v1 * 0.70710678118654752f));
                        }
                        __half hl[2] = {__float2half(v0), __float2half(v1)};
                        *(uint32_t*)&Ch[(long)row * Nfull + col] = *(uint32_t*)hl;
                    }
                }
            continue;
        }

        // EPI 2/3: finalize into acc, write fp32 C, accumulate LN stats
        float s1[2][2] = {}, s2[2][2] = {};
#pragma unroll
        for (int mi = 0; mi < 2; mi++)
#pragma unroll
            for (int hf = 0; hf < 2; hf++) {
                int row = m0 + wm * 32 + mi * 16 + hf * 8 + tg;
                bool rok = row < M;
                long pr = (EPI == 2 && rok) ? (long)(row % SEQ) * 128 : 0;
#pragma unroll
                for (int ni = 0; ni < 8; ni++) {
                    int col = n0 + wn * 64 + ni * 8 + tc;
                    float v0 = acc[mi][ni][hf * 2 + 0] + bias[col];
                    float v1 = acc[mi][ni][hf * 2 + 1] + bias[col + 1];
                    if (rok) {
                        if (EPI == 2) {
                            v0 += pos[pr + col];
                            v1 += pos[pr + col + 1];
                        } else {
                            v0 += res[(long)row * Nfull + col];
                            v1 += res[(long)row * Nfull + col + 1];
                        }
                        *(float2*)&C[(long)row * Nfull + col] = make_float2(v0, v1);
                    }
                    acc[mi][ni][hf * 2 + 0] = v0;
                    acc[mi][ni][hf * 2 + 1] = v1;
                    s1[mi][hf] += v0 + v1;
                    s2[mi][hf] += v0 * v0 + v1 * v1;
                }
            }
        if (lnout) {
#pragma unroll
            for (int mi = 0; mi < 2; mi++)
#pragma unroll
                for (int hf = 0; hf < 2; hf++) {
                    float a = s1[mi][hf], b = s2[mi][hf];
                    a += __shfl_xor_sync(~0u, a, 1);
                    a += __shfl_xor_sync(~0u, a, 2);
                    b += __shfl_xor_sync(~0u, b, 1);
                    b += __shfl_xor_sync(~0u, b, 2);
                    if ((lane & 3) == 0) {
                        int ri = wm * 32 + mi * 16 + hf * 8 + tg;
                        lnred[wn][ri][0] = a;
                        lnred[wn][ri][1] = b;
                    }
                }
            __syncthreads();
#pragma unroll
            for (int mi = 0; mi < 2; mi++)
#pragma unroll
                for (int hf = 0; hf < 2; hf++) {
                    int ri = wm * 32 + mi * 16 + hf * 8 + tg;
                    int row = m0 + ri;
                    if (row >= M) continue;
                    float m1 = (lnred[0][ri][0] + lnred[1][ri][0]) * (1.f / 128.f);
                    float m2 = (lnred[0][ri][1] + lnred[1][ri][1]) * (1.f / 128.f);
                    float inv = rsqrtf(m2 - m1 * m1 + 1e-5f);
#pragma unroll
                    for (int ni = 0; ni < 8; ni++) {
                        int col = wn * 64 + ni * 8 + tc;
                        float v0 = (acc[mi][ni][hf * 2 + 0] - m1) * inv * lnsc[col] + lnbi[col];
                        float v1 = (acc[mi][ni][hf * 2 + 1] - m1) * inv * lnsc[col + 1] + lnbi[col + 1];
                        __half hl[2] = {__float2half(v0), __float2half(v1)};
                        *(uint32_t*)&lnout[(long)row * 128 + col] = *(uint32_t*)hl;
                    }
                }
        }
    }
}

// =============== chunked fp16 GEMM for K=512 (ff2) + fused LN/out ============
#define CSTAGE_B 32768u

__global__ void __launch_bounds__(256, 2)
tgemmC(const __half* __restrict__ A, const __half* __restrict__ B,
       const float* __restrict__ bias, const float* __restrict__ res,
       float* __restrict__ C, const float* __restrict__ lnsc,
       const float* __restrict__ lnbi, __half* __restrict__ lnout,
       int M, int N, int K) {
    extern __shared__ char sm[];
    __shared__ float lnred[2][128][2];
    uint32_t sb = smem_u32(sm);
    int tid = threadIdx.x;
    int w = tid >> 5, lane = tid & 31;
    int wm = w & 3, wn = w >> 2;
    int m0 = blockIdx.y * 128, n0 = blockIdx.x * 128;
    int nk = K >> 6;

    float acc[2][8][4];
#pragma unroll
    for (int i = 0; i < 2; i++)
#pragma unroll
        for (int j = 0; j < 8; j++)
#pragma unroll
            for (int q = 0; q < 4; q++) acc[i][j][q] = 0.f;

    int rA[2], rB[4];
#pragma unroll
    for (int mi = 0; mi < 2; mi++) rA[mi] = wm * 32 + mi * 16 + (lane & 15);
#pragma unroll
    for (int ng = 0; ng < 4; ng++)
        rB[ng] = wn * 64 + ng * 16 + ((lane >> 4) << 3) + (lane & 7);
    int cA = lane >> 4;
    int cB = (lane >> 3) & 1;

    auto load_stage = [&](int c, int buf) {
#pragma unroll
        for (int it = 0; it < 8; it++) {
            int slot = it * 256 + tid;
            int t = it >> 2;
            int row = (slot >> 3) & 127;
            int chunk = slot & 7;
            const __half* src = t ? B : A;
            long grow = t ? (long)(n0 + row) : (long)(m0 + row);
            bool ok = t ? true : (m0 + row < M);
            if (!ok) grow = 0;
            const void* g = (const void*)(src + grow * K + ((long)c << 6) + chunk * 8);
            uint32_t saddr = sb + buf * CSTAGE_B + (uint32_t)t * 16384u + row * 128 +
                             ((chunk ^ (row & 7)) << 4);
            cpasync16(saddr, g, ok ? 16u : 0u);
        }
        CP_COMMIT();
    };

#pragma unroll
    for (int p = 0; p < 2; p++) load_stage(p, p);

    for (int c = 0; c < nk; c++) {
        int nxt = c + 2;
        if (nxt < nk) load_stage(nxt, nxt % 3);
        int allow = (nxt < nk ? nxt : nk - 1) - c;
        if (allow >= 2) CP_WAIT(2);
        else if (allow == 1) CP_WAIT(1);
        else CP_WAIT(0);
        __syncthreads();

        uint32_t st = sb + (c % 3) * CSTAGE_B;
#pragma unroll
        for (int ks = 0; ks < 4; ks++) {
            int kc = ks * 2;
            uint32_t fa[2][4], fb[4][4];
#pragma unroll
            for (int mi = 0; mi < 2; mi++) {
                int row = rA[mi];
                ldsm4(fa[mi], st + row * 128 + ((((uint32_t)(kc + cA)) ^ (row & 7)) << 4));
            }
#pragma unroll
            for (int ng = 0; ng < 4; ng++) {
                int row = rB[ng];
                ldsm4(fb[ng], st + 16384u + row * 128 + ((((uint32_t)(kc + cB)) ^ (row & 7)) << 4));
            }
#pragma unroll
            for (int ng = 0; ng < 4; ng++)
#pragma unroll
                for (int mi = 0; mi < 2; mi++) {
                    mma16816(acc[mi][ng * 2],     fa[mi], fb[ng][0], fb[ng][1]);
                    mma16816(acc[mi][ng * 2 + 1], fa[mi], fb[ng][2], fb[ng][3]);
                }
        }
        __syncthreads();
    }

    int tg = lane >> 2;
    int tc = (lane & 3) * 2;
    float s1[2][2] = {}, s2[2][2] = {};
#pragma unroll
    for (int mi = 0; mi < 2; mi++)
#pragma unroll
        for (int hf = 0; hf < 2; hf++) {
            int row = m0 + wm * 32 + mi * 16 + hf * 8 + tg;
            bool rok = row < M;
#pragma unroll
            for (int ni = 0; ni < 8; ni++) {
                int col = n0 + wn * 64 + ni * 8 + tc;
                float v0 = acc[mi][ni][hf * 2 + 0] + bias[col];
                float v1 = acc[mi][ni][hf * 2 + 1] + bias[col + 1];
                if (rok) {
                    v0 += res[(long)row * N + col];
                    v1 += res[(long)row * N + col + 1];
                    *(float2*)&C[(long)row * N + col] = make_float2(v0, v1);
                }
                acc[mi][ni][hf * 2 + 0] = v0;
                acc[mi][ni][hf * 2 + 1] = v1;
                s1[mi][hf] += v0 + v1;
                s2[mi][hf] += v0 * v0 + v1 * v1;
            }
        }
    if (lnout && lnsc) {
#pragma unroll
        for (int mi = 0; mi < 2; mi++)
#pragma unroll
            for (int hf = 0; hf < 2; hf++) {
                float a = s1[mi][hf], b = s2[mi][hf];
                a += __shfl_xor_sync(~0u, a, 1);
                a += __shfl_xor_sync(~0u, a, 2);
                b += __shfl_xor_sync(~0u, b, 1);
                b += __shfl_xor_sync(~0u, b, 2);
                if ((lane & 3) == 0) {
                    int ri = wm * 32 + mi * 16 + hf * 8 + tg;
                    lnred[wn][ri][0] = a;
                    lnred[wn][ri][1] = b;
                }
            }
        __syncthreads();
#pragma unroll
        for (int mi = 0; mi < 2; mi++)
#pragma unroll
            for (int hf = 0; hf < 2; hf++) {
                int ri = wm * 32 + mi * 16 + hf * 8 + tg;
                int row = m0 + ri;
                if (row >= M) continue;
                float m1 = (lnred[0][ri][0] + lnred[1][ri][0]) * (1.f / 128.f);
                float m2 = (lnred[0][ri][1] + lnred[1][ri][1]) * (1.f / 128.f);
                float inv = rsqrtf(m2 - m1 * m1 + 1e-5f);
#pragma unroll
                for (int ni = 0; ni < 8; ni++) {
                    int col = wn * 64 + ni * 8 + tc;
                    float v0 = (acc[mi][ni][hf * 2 + 0] - m1) * inv * lnsc[col] + lnbi[col];
                    float v1 = (acc[mi][ni][hf * 2 + 1] - m1) * inv * lnsc[col + 1] + lnbi[col + 1];
                    __half hl[2] = {__float2half(v0), __float2half(v1)};
                    *(uint32_t*)&lnout[(long)row * 128 + col] = *(uint32_t*)hl;
                }
            }
    } else if (lnout) {   // plain fp16 copy (hh for head)
#pragma unroll
        for (int mi = 0; mi < 2; mi++)
#pragma unroll
            for (int hf = 0; hf < 2; hf++) {
                int row = m0 + wm * 32 + mi * 16 + hf * 8 + tg;
                if (row >= M) continue;
#pragma unroll
                for (int ni = 0; ni < 8; ni++) {
                    int col = n0 + wn * 64 + ni * 8 + tc;
                    __half hl[2] = {__float2half(acc[mi][ni][hf * 2 + 0]),
                                    __float2half(acc[mi][ni][hf * 2 + 1])};
                    *(uint32_t*)&lnout[(long)row * 128 + col] = *(uint32_t*)hl;
                }
            }
    }
}

// ---------------- local windowed attention (fp16 qkv) ------------------------
__global__ void attn_k(const __half* __restrict__ qkv, __half* __restrict__ o) {
    __shared__ float qs[S1][17];
    __shared__ float ks[3 * S1][17];
    __shared__ float vs[3 * S1][17];
    __shared__ float ps[8][192];
    int w = blockIdx.x;
    int bh = blockIdx.y;
    int b = bh >> 3, h = bh & 7;
    int tid = threadIdx.x;
    int jstart = (w > 0) ? 0 : S1;
    int jend = (w < S1 - 1) ? 3 * S1 : 2 * S1;
    long rb = (long)b * SEQ;

    for (int idx = tid; idx < S1 * DH; idx += 256) {
        int i = idx >> 4, d = idx & 15;
        qs[i][d] = __half2float(qkv[(rb + w * S1 + i) * 384 + h * 16 + d]) * 0.25f;
    }
    int cnt = jend - jstart;
    for (int idx = tid; idx < cnt * DH; idx += 256) {
        int j = jstart + (idx >> 4), d = idx & 15;
        long r = rb + (long)(w - 1) * S1 + j;
        ks[j][d] = __half2float(qkv[r * 384 + 128 + h * 16 + d]);
        vs[j][d] = __half2float(qkv[r * 384 + 256 + h * 16 + d]);
    }
    __syncthreads();

    int warp = tid >> 5, lane = tid & 31;
    for (int i = warp; i < S1; i += 8) {
        float ql[DH];
#pragma unroll
        for (int d = 0; d < DH; d++) ql[d] = qs[i][d];
        float sc[6];
        float mx = -1e30f;
        int c = 0;
        for (int j = jstart + lane; j < jend; j += 32) {
            float s = 0.f;
#pragma unroll
            for (int d = 0; d < DH; d++) s += ql[d] * ks[j][d];
            sc[c++] = s;
            mx = fmaxf(mx, s);
        }
#pragma unroll
        for (int off = 16; off; off >>= 1) mx = fmaxf(mx, __shfl_xor_sync(~0u, mx, off));
        float se = 0.f;
        c = 0;
        for (int j = jstart + lane; j < jend; j += 32) {
            float p = __expf(sc[c] - mx);
            sc[c++] = p;
            se += p;
        }
#pragma unroll
        for (int off = 16; off; off >>= 1) se += __shfl_xor_sync(~0u, se, off);
        float inv = 1.f / se;
        c = 0;
        for (int j = jstart + lane; j < jend; j += 32) ps[warp][j - jstart] = sc[c++] * inv;
        __syncwarp();
        int d = lane & 15, half = lane >> 4;
        float accv = 0.f;
        for (int jj = half; jj < cnt; jj += 2) accv += ps[warp][jj] * vs[jstart + jj][d];
        accv += __shfl_xor_sync(~0u, accv, 16);
        if (lane < 16) o[(rb + w * S1 + i) * 128 + h * 16 + d] = __float2half(accv);
        __syncwarp();
    }
}

// ---------------- launch ------------------------------------------------------
extern "C" void kernel_launch(void* const* d_in, const int* in_sizes, int n_in,
                              void* d_out, int out_size) {
    const float* x      = (const float*)d_in[0];
    const float* conv_w = (const float*)d_in[1];
    const float* conv_b = (const float*)d_in[2];
    const float* lt_w   = (const float*)d_in[3];
    const float* lt_b   = (const float*)d_in[4];
    const float* pos    = (const float*)d_in[5];
    const float* ln1_s  = (const float*)d_in[6];
    const float* ln1_b  = (const float*)d_in[7];
    const float* wq     = (const float*)d_in[8];
    const float* wk     = (const float*)d_in[9];
    const float* wv     = (const float*)d_in[10];
    const float* wo     = (const float*)d_in[11];
    const float* wo_b   = (const float*)d_in[12];
    const float* ln2_s  = (const float*)d_in[13];
    const float* ln2_b  = (const float*)d_in[14];
    const float* ff_w1  = (const float*)d_in[15];
    const float* ff_b1  = (const float*)d_in[16];
    const float* ff_w2  = (const float*)d_in[17];
    const float* ff_b2  = (const float*)d_in[18];
    const float* pre_w1 = (const float*)d_in[19];
    const float* pre_b1 = (const float*)d_in[20];
    const float* pre_w2 = (const float*)d_in[21];
    const float* pre_b2 = (const float*)d_in[22];
    float* out = (float*)d_out;

    static bool attr_done = false;
    if (!attr_done) {
        cudaFuncSetAttribute(tgemmA<0,2>, cudaFuncAttributeMaxDynamicSharedMemorySize, 98304);
        cudaFuncSetAttribute(tgemmA<2,1>, cudaFuncAttributeMaxDynamicSharedMemorySize, 49152);
        cudaFuncSetAttribute(tgemmA<3,2>, cudaFuncAttributeMaxDynamicSharedMemorySize, 98304);
        cudaFuncSetAttribute(tgemmA<4,2>, cudaFuncAttributeMaxDynamicSharedMemorySize, 98304);
        cudaFuncSetAttribute(tgemmA<5,2>, cudaFuncAttributeMaxDynamicSharedMemorySize, 98304);
        cudaFuncSetAttribute(tgemmC, cudaFuncAttributeMaxDynamicSharedMemorySize, 98304);
        attr_done = true;
    }

    __half *p, *lnb, *att, *ff, *hh, *wlt, *wqkv, *woh, *wf1, *wf2, *wp1, *qkvh;
    float *h;
    cudaGetSymbolAddress((void**)&p, g_p);       cudaGetSymbolAddress((void**)&h, g_h);
    cudaGetSymbolAddress((void**)&lnb, g_ln);    cudaGetSymbolAddress((void**)&qkvh, g_qkv);
    cudaGetSymbolAddress((void**)&att, g_att);   cudaGetSymbolAddress((void**)&ff, g_ff);
    cudaGetSymbolAddress((void**)&hh, g_hh);     cudaGetSymbolAddress((void**)&wlt, g_wlt);
    cudaGetSymbolAddress((void**)&wqkv, g_wqkv); cudaGetSymbolAddress((void**)&woh, g_wo);
    cudaGetSymbolAddress((void**)&wf1, g_wf1);   cudaGetSymbolAddress((void**)&wf2, g_wf2);
    cudaGetSymbolAddress((void**)&wp1, g_wp1);

    const int M = MROWS;
    dim3 gA(1, MTILES);

    // 1: all weight prep in one launch
    prep_all<<<(PREP_TOTAL + 255) / 256, 256>>>(lt_w, wq, wk, wv, wo, ff_w1, ff_w2, pre_w1,
                                                wlt, wqkv, woh, wf1, wf2, wp1);
    // 2: conv
    conv_k<<<(MROWS * 64 + 255) / 256, 256>>>(x, conv_w, conv_b, p);
    // 3: embed GEMM + fused ln1[0]
    tgemmA<2,1><<<gA, 256, 49152>>>(p, wlt, lt_b, nullptr, pos, nullptr,
                                    h, nullptr, ln1_s, ln1_b, lnb, M, 128, 1);

    for (int i = 0; i < NLAYER; i++) {
        // 4 (i==0): qkv GEMM -> fp16
        tgemmA<0,2><<<gA, 256, 98304>>>(lnb, wqkv + (long)i * 49152,
            nullptr, nullptr, nullptr, nullptr, nullptr, qkvh,
            nullptr, nullptr, nullptr, M, 384, 3);
        attn_k<<<dim3(S1, BATCH * HEADS), 256>>>(qkvh, att);
        // wo GEMM + res + fused ln2[i]
        tgemmA<3,2><<<gA, 256, 98304>>>(att, woh + (long)i * 16384,
            wo_b + i * 128, h, nullptr, nullptr, h, nullptr,
            ln2_s + i * 128, ln2_b + i * 128, lnb, M, 128, 1);
        // ff1 gelu -> fp16
        tgemmA<4,2><<<gA, 256, 98304>>>(lnb, wf1 + (long)i * 65536,
            ff_b1 + i * 512, nullptr, nullptr, nullptr, nullptr, ff,
            nullptr, nullptr, nullptr, M, 512, 4);
        // ff2 + res + fused ln1[i+1] (or hh fp16 on last layer)
        bool last = (i == NLAYER - 1);
        tgemmC<<<dim3(1, MTILES), 256, 98304>>>(ff, wf2 + (long)i * 65536,
            ff_b2 + i * 128, h, h,
            last ? nullptr : ln1_s + (i + 1) * 128,
            last ? nullptr : ln1_b + (i + 1) * 128,
            last ? hh : lnb, M, 128, 512);
    }

    tgemmA<5,2><<<gA, 256, 98304>>>(hh, wp1, pre_b1, nullptr, pre_b2, pre_w2,
                                    out, nullptr, nullptr, nullptr, nullptr, M, 128, 1);
}

// round 8
// speedup vs baseline: 1.3463x; 1.3463x over previous
#include <cuda_runtime.h>
#include <cuda_fp16.h>
#include <cstdint>
#include <math.h>

#define BATCH 16
#define S1 61
#define SEQ 3721
#define DMODEL 128
#define HEADS 8
#define DH 16
#define NLAYER 4
#define FFDIM 512
#define PCH 49
#define MROWS (BATCH * SEQ) // 59536
#define MTILES ((MROWS + 127) / 128) // 466

// ---------------------------------------------------------------- scratch
__device__ __half g_p[MROWS * 64];
__device__ float  g_h[MROWS * 128];
__device__ __half g_ln[MROWS * 128];
__device__ __half g_qkv[(size_t)MROWS * 384];
__device__ __half g_att[MROWS * 128];
__device__ __half g_ff[(size_t)MROWS * 512];
__device__ __half g_hh[MROWS * 128];
__device__ __half g_wlt[128 * 64];
__device__ __half g_wqkv[NLAYER * 384 * 128];
__device__ __half g_wo[NLAYER * 128 * 128];
__device__ __half g_wf1[NLAYER * 512 * 128];
__device__ __half g_wf2[NLAYER * 128 * 512];
__device__ __half g_wp1[128 * 128];

// ---------------------------------------------------------------- helpers
__device__ __forceinline__ uint32_t smem_u32(const void* p) {
    uint32_t a;
    asm("{ .reg .u64 t; cvta.to.shared.u64 t, %1; cvt.u32.u64 %0, t; }" : "=r"(a) : "l"(p));
    return a;
}
__device__ __forceinline__ void ldsm4(uint32_t* r, uint32_t addr) {
    asm volatile("ldmatrix.sync.aligned.m8n8.x4.shared.b16 {%0,%1,%2,%3}, [%4];"
                 : "=r"(r[0]), "=r"(r[1]), "=r"(r[2]), "=r"(r[3]) : "r"(addr));
}
__device__ __forceinline__ void mma16816(float* c, const uint32_t* a, uint32_t b0, uint32_t b1) {
    asm volatile("mma.sync.aligned.m16n8k16.row.col.f32.f16.f16.f32 "
                 "{%0,%1,%2,%3}, {%4,%5,%6,%7}, {%8,%9}, {%0,%1,%2,%3};"
                 : "+f"(c[0]), "+f"(c[1]), "+f"(c[2]), "+f"(c[3])
                 : "r"(a[0]), "r"(a[1]), "r"(a[2]), "r"(a[3]), "r"(b0), "r"(b1));
}
__device__ __forceinline__ void cpasync16(uint32_t saddr, const void* g, uint32_t ssz) {
    asm volatile("cp.async.cg.shared.global [%0], [%1], 16, %2;"
                 :: "r"(saddr), "l"(g), "r"(ssz));
}
#define CP_COMMIT() asm volatile("cp.async.commit_group;" ::: "memory")
#define CP_WAIT(n)  asm volatile("cp.async.wait_group %0;" :: "n"(n) : "memory")

// ------------------------------------------- single fused weight prep --------
__global__ void prep_all(const float* __restrict__ lt_w, const float* __restrict__ wq,
                         const float* __restrict__ wk, const float* __restrict__ wv,
                         const float* __restrict__ wo, const float* __restrict__ ff_w1,
                         const float* __restrict__ ff_w2, const float* __restrict__ pre_w1,
                         __half* __restrict__ wlt, __half* __restrict__ wqkv,
                         __half* __restrict__ woh, __half* __restrict__ wf1,
                         __half* __restrict__ wf2, __half* __restrict__ wp1) {
    long t = (long)blockIdx.x * blockDim.x + threadIdx.x;
    if (t < 8192) {
        int n = (int)(t >> 6), kk = (int)(t & 63);
        wlt[t] = __float2half(kk < 49 ? lt_w[kk * 128 + n] : 0.f);
        return;
    }
    t -= 8192;
    if (t < 196608) {
        int l = (int)(t / 49152), r = (int)(t % 49152);
        int n = r >> 7, kk = r & 127;
        int s = n >> 7, nn = n & 127;
        const float* W = (s == 0 ? wq : s == 1 ? wk : wv) + (long)l * 16384;
        wqkv[t] = __float2half(W[kk * 128 + nn]);
        return;
    }
    t -= 196608;
    if (t < 65536) {
        int l = (int)(t / 16384), r = (int)(t % 16384);
        int n = r >> 7, kk = r & 127;
        woh[t] = __float2half(wo[(long)l * 16384 + kk * 128 + n]);
        return;
    }
    t -= 65536;
    if (t < 262144) {
        int l = (int)(t / 65536), r = (int)(t % 65536);
        int n = r >> 7, kk = r & 127;
        wf1[t] = __float2half(ff_w1[(long)l * 65536 + (long)kk * 512 + n]);
        return;
    }
    t -= 262144;
    if (t < 262144) {
        int l = (int)(t / 65536), r = (int)(t % 65536);
        int n = r / 512, kk = r % 512;
        wf2[t] = __float2half(ff_w2[(long)l * 65536 + (long)kk * 128 + n]);
        return;
    }
    t -= 262144;
    if (t < 16384) {
        int n = (int)(t >> 7), kk = (int)(t & 127);
        wp1[t] = __float2half(pre_w1[kk * 128 + n]);
    }
}
#define PREP_TOTAL (8192 + 196608 + 65536 + 262144 + 262144 + 16384)

// ---------------- conv 7x7 'same' + relu -> fp16 [M,64] ----------------------
__global__ void conv_k(const float* __restrict__ x, const float* __restrict__ cw,
                       const float* __restrict__ cb, __half* __restrict__ p) {
    int t = blockIdx.x * blockDim.x + threadIdx.x;
    if (t >= MROWS * 64) return;
    int o = t & 63;
    float sum = 0.f;
    if (o < PCH) {
        int s = (t >> 6) % SEQ;
        int b = (t >> 6) / SEQ;
        int y = s / S1, xx = s % S1;
        const float* xb = x + (long)b * SEQ;
        const float* wo = cw + o * 49;
        sum = cb[o];
#pragma unroll
        for (int dy = 0; dy < 7; dy++) {
            int iy = y + dy - 3;
            if (iy < 0 || iy >= S1) continue;
#pragma unroll
            for (int dx = 0; dx < 7; dx++) {
                int ix = xx + dx - 3;
                if (ix < 0 || ix >= S1) continue;
                sum += xb[iy * S1 + ix] * wo[dy * 7 + dx];
            }
        }
        sum = fmaxf(sum, 0.f);
    }
    p[t] = __float2half(sum);
}

// =============== A-resident fp16 GEMM (K<=128), N-loop inside ================
template <int EPI, int NK>
__global__ void __launch_bounds__(256, 2)
tgemmA(const __half* __restrict__ A, const __half* __restrict__ B,
       const float* __restrict__ bias, const float* __restrict__ res,
       const float* __restrict__ pos, const float* __restrict__ w2,
       float* __restrict__ C, __half* __restrict__ Ch,
       const float* __restrict__ lnsc, const float* __restrict__ lnbi,
       __half* __restrict__ lnout, int M, int Nfull, int NT) {
    extern __shared__ char sm[];
    __shared__ float red[2][128];
    __shared__ float lnred[2][128][2];
    uint32_t sb = smem_u32(sm);
    const int K = NK * 64;
    const uint32_t ABYTES = (uint32_t)NK * 16384u;
    int tid = threadIdx.x;
    int w = tid >> 5, lane = tid & 31;
    int wm = w & 3, wn = w >> 2;
    int m0 = blockIdx.y * 128;

    int rA[2], rB[4];
#pragma unroll
    for (int mi = 0; mi < 2; mi++) rA[mi] = wm * 32 + mi * 16 + (lane & 15);
#pragma unroll
    for (int ng = 0; ng < 4; ng++)
        rB[ng] = wn * 64 + ng * 16 + ((lane >> 4) << 3) + (lane & 7);
    int cA = lane >> 4;
    int cB = (lane >> 3) & 1;

#pragma unroll
    for (int t = 0; t < NK * 4; t++) {
        int slot = t * 256 + tid;
        int tile = slot >> 10;
        int idx = slot & 1023;
        int row = idx >> 3, c16 = idx & 7;
        long grow = m0 + row;
        bool ok = grow < M;
        if (!ok) grow = 0;
        cpasync16(sb + (uint32_t)tile * 16384u + row * 128 + (((uint32_t)c16 ^ (row & 7)) << 4),
                  A + grow * K + tile * 64 + c16 * 8, ok ? 16u : 0u);
    }
    CP_COMMIT();

    auto loadB = [&](int nt) {
#pragma unroll
        for (int t = 0; t < NK * 4; t++) {
            int slot = t * 256 + tid;
            int tile = slot >> 10;
            int idx = slot & 1023;
            int row = idx >> 3, c16 = idx & 7;
            long grow = (long)(nt * 128 + row);
            cpasync16(sb + ABYTES + (uint32_t)(nt & 1) * ABYTES + (uint32_t)tile * 16384u +
                          row * 128 + (((uint32_t)c16 ^ (row & 7)) << 4),
                      B + grow * K + tile * 64 + c16 * 8, 16u);
        }
        CP_COMMIT();
    };
    loadB(0);

    for (int nt = 0; nt < NT; nt++) {
        if (nt + 1 < NT) { loadB(nt + 1); CP_WAIT(1); }
        else             { CP_WAIT(0); }
        __syncthreads();

        float acc[2][8][4];
#pragma unroll
        for (int i = 0; i < 2; i++)
#pragma unroll
            for (int j = 0; j < 8; j++)
#pragma unroll
                for (int q = 0; q < 4; q++) acc[i][j][q] = 0.f;

        uint32_t Bbase = sb + ABYTES + (uint32_t)(nt & 1) * ABYTES;
#pragma unroll
        for (int i = 0; i < NK * 4; i++) {
            int chunk = i >> 2, ks = i & 3, kc = ks * 2;
            uint32_t Ab = sb + (uint32_t)chunk * 16384u;
            uint32_t Bb = Bbase + (uint32_t)chunk * 16384u;
            uint32_t fa[2][4], fb[4][4];
#pragma unroll
            for (int mi = 0; mi < 2; mi++) {
                int row = rA[mi];
                ldsm4(fa[mi], Ab + row * 128 + ((((uint32_t)(kc + cA)) ^ (row & 7)) << 4));
            }
#pragma unroll
            for (int ng = 0; ng < 4; ng++) {
                int row = rB[ng];
                ldsm4(fb[ng], Bb + row * 128 + ((((uint32_t)(kc + cB)) ^ (row & 7)) << 4));
            }
#pragma unroll
            for (int ng = 0; ng < 4; ng++)
#pragma unroll
                for (int mi = 0; mi < 2; mi++) {
                    mma16816(acc[mi][ng * 2],     fa[mi], fb[ng][0], fb[ng][1]);
                    mma16816(acc[mi][ng * 2 + 1], fa[mi], fb[ng][2], fb[ng][3]);
                }
        }
        __syncthreads();

        int n0 = nt * 128;
        int tg = lane >> 2;
        int tc = (lane & 3) * 2;

        if (EPI == 5) {
            float p[2][2] = {};
#pragma unroll
            for (int mi = 0; mi < 2; mi++)
#pragma unroll
                for (int ni = 0; ni < 8; ni++) {
                    int col = wn * 64 + ni * 8 + tc;
                    float b0 = bias[col], b1 = bias[col + 1];
                    float w20 = w2[col], w21 = w2[col + 1];
                    p[mi][0] += fmaxf(acc[mi][ni][0] + b0, 0.f) * w20 +
                                fmaxf(acc[mi][ni][1] + b1, 0.f) * w21;
                    p[mi][1] += fmaxf(acc[mi][ni][2] + b0, 0.f) * w20 +
                                fmaxf(acc[mi][ni][3] + b1, 0.f) * w21;
                }
#pragma unroll
            for (int mi = 0; mi < 2; mi++)
#pragma unroll
                for (int hf = 0; hf < 2; hf++) {
                    float v = p[mi][hf];
                    v += __shfl_xor_sync(~0u, v, 1);
                    v += __shfl_xor_sync(~0u, v, 2);
                    if ((lane & 3) == 0) red[wn][wm * 32 + mi * 16 + hf * 8 + tg] = v;
                }
            __syncthreads();
            if (tid < 128) {
                int row = m0 + tid;
                if (row < M) C[row] = red[0][tid] + red[1][tid] + pos[0];
            }
            continue;
        }

        if (EPI == 0 || EPI == 4) {
#pragma unroll
            for (int mi = 0; mi < 2; mi++)
#pragma unroll
                for (int hf = 0; hf < 2; hf++) {
                    int row = m0 + wm * 32 + mi * 16 + hf * 8 + tg;
                    if (row >= M) continue;
#pragma unroll
                    for (int ni = 0; ni < 8; ni++) {
                        int col = n0 + wn * 64 + ni * 8 + tc;
                        float v0 = acc[mi][ni][hf * 2 + 0];
                        float v1 = acc[mi][ni][hf * 2 + 1];
                        if (EPI == 4) {
                            v0 += bias[col];
                            v1 += bias[col + 1];
                            v0 = 0.5f * v0 * (1.f + erff(v0 * 0.70710678118654752f));
                            v1 = 0.5f * v1 * (1.f + erff(v1 * 0.70710678118654752f));
                        }
                        __half hl[2] = {__float2half(v0), __float2half(v1)};
                        *(uint32_t*)&Ch[(long)row * Nfull + col] = *(uint32_t*)hl;
                    }
                }
            continue;
        }

        // EPI 2/3
        float s1[2][2] = {}, s2[2][2] = {};
#pragma unroll
        for (int mi = 0; mi < 2; mi++)
#pragma unroll
            for (int hf = 0; hf < 2; hf++) {
                int row = m0 + wm * 32 + mi * 16 + hf * 8 + tg;
                bool rok = row < M;
                long pr = (EPI == 2 && rok) ? (long)(row % SEQ) * 128 : 0;
#pragma unroll
                for (int ni = 0; ni < 8; ni++) {
                    int col = n0 + wn * 64 + ni * 8 + tc;
                    float v0 = acc[mi][ni][hf * 2 + 0] + bias[col];
                    float v1 = acc[mi][ni][hf * 2 + 1] + bias[col + 1];
                    if (rok) {
                        if (EPI == 2) {
                            v0 += pos[pr + col];
                            v1 += pos[pr + col + 1];
                        } else {
                            v0 += res[(long)row * Nfull + col];
                            v1 += res[(long)row * Nfull + col + 1];
                        }
                        *(float2*)&C[(long)row * Nfull + col] = make_float2(v0, v1);
                    }
                    acc[mi][ni][hf * 2 + 0] = v0;
                    acc[mi][ni][hf * 2 + 1] = v1;
                    s1[mi][hf] += v0 + v1;
                    s2[mi][hf] += v0 * v0 + v1 * v1;
                }
            }
        if (lnout) {
#pragma unroll
            for (int mi = 0; mi < 2; mi++)
#pragma unroll
                for (int hf = 0; hf < 2; hf++) {
                    float a = s1[mi][hf], b = s2[mi][hf];
                    a += __shfl_xor_sync(~0u, a, 1);
                    a += __shfl_xor_sync(~0u, a, 2);
                    b += __shfl_xor_sync(~0u, b, 1);
                    b += __shfl_xor_sync(~0u, b, 2);
                    if ((lane & 3) == 0) {
                        int ri = wm * 32 + mi * 16 + hf * 8 + tg;
                        lnred[wn][ri][0] = a;
                        lnred[wn][ri][1] = b;
                    }
                }
            __syncthreads();
#pragma unroll
            for (int mi = 0; mi < 2; mi++)
#pragma unroll
                for (int hf = 0; hf < 2; hf++) {
                    int ri = wm * 32 + mi * 16 + hf * 8 + tg;
                    int row = m0 + ri;
                    if (row >= M) continue;
                    float m1 = (lnred[0][ri][0] + lnred[1][ri][0]) * (1.f / 128.f);
                    float m2 = (lnred[0][ri][1] + lnred[1][ri][1]) * (1.f / 128.f);
                    float inv = rsqrtf(m2 - m1 * m1 + 1e-5f);
#pragma unroll
                    for (int ni = 0; ni < 8; ni++) {
                        int col = wn * 64 + ni * 8 + tc;
                        float v0 = (acc[mi][ni][hf * 2 + 0] - m1) * inv * lnsc[col] + lnbi[col];
                        float v1 = (acc[mi][ni][hf * 2 + 1] - m1) * inv * lnsc[col + 1] + lnbi[col + 1];
                        __half hl[2] = {__float2half(v0), __float2half(v1)};
                        *(uint32_t*)&lnout[(long)row * 128 + col] = *(uint32_t*)hl;
                    }
                }
        }
    }
}

// =============== chunked fp16 GEMM for K=512 (ff2) + fused LN/out ============
#define CSTAGE_B 32768u

__global__ void __launch_bounds__(256, 2)
tgemmC(const __half* __restrict__ A, const __half* __restrict__ B,
       const float* __restrict__ bias, const float* __restrict__ res,
       float* __restrict__ C, const float* __restrict__ lnsc,
       const float* __restrict__ lnbi, __half* __restrict__ lnout,
       int M, int N, int K) {
    extern __shared__ char sm[];
    __shared__ float lnred[2][128][2];
    uint32_t sb = smem_u32(sm);
    int tid = threadIdx.x;
    int w = tid >> 5, lane = tid & 31;
    int wm = w & 3, wn = w >> 2;
    int m0 = blockIdx.y * 128, n0 = blockIdx.x * 128;
    int nk = K >> 6;

    float acc[2][8][4];
#pragma unroll
    for (int i = 0; i < 2; i++)
#pragma unroll
        for (int j = 0; j < 8; j++)
#pragma unroll
            for (int q = 0; q < 4; q++) acc[i][j][q] = 0.f;

    int rA[2], rB[4];
#pragma unroll
    for (int mi = 0; mi < 2; mi++) rA[mi] = wm * 32 + mi * 16 + (lane & 15);
#pragma unroll
    for (int ng = 0; ng < 4; ng++)
        rB[ng] = wn * 64 + ng * 16 + ((lane >> 4) << 3) + (lane & 7);
    int cA = lane >> 4;
    int cB = (lane >> 3) & 1;

    auto load_stage = [&](int c, int buf) {
#pragma unroll
        for (int it = 0; it < 8; it++) {
            int slot = it * 256 + tid;
            int t = it >> 2;
            int row = (slot >> 3) & 127;
            int chunk = slot & 7;
            const __half* src = t ? B : A;
            long grow = t ? (long)(n0 + row) : (long)(m0 + row);
            bool ok = t ? true : (m0 + row < M);
            if (!ok) grow = 0;
            const void* g = (const void*)(src + grow * K + ((long)c << 6) + chunk * 8);
            uint32_t saddr = sb + buf * CSTAGE_B + (uint32_t)t * 16384u + row * 128 +
                             ((chunk ^ (row & 7)) << 4);
            cpasync16(saddr, g, ok ? 16u : 0u);
        }
        CP_COMMIT();
    };

#pragma unroll
    for (int p = 0; p < 2; p++) load_stage(p, p);

    for (int c = 0; c < nk; c++) {
        int nxt = c + 2;
        if (nxt < nk) load_stage(nxt, nxt % 3);
        int allow = (nxt < nk ? nxt : nk - 1) - c;
        if (allow >= 2) CP_WAIT(2);
        else if (allow == 1) CP_WAIT(1);
        else CP_WAIT(0);
        __syncthreads();

        uint32_t st = sb + (c % 3) * CSTAGE_B;
#pragma unroll
        for (int ks = 0; ks < 4; ks++) {
            int kc = ks * 2;
            uint32_t fa[2][4], fb[4][4];
#pragma unroll
            for (int mi = 0; mi < 2; mi++) {
                int row = rA[mi];
                ldsm4(fa[mi], st + row * 128 + ((((uint32_t)(kc + cA)) ^ (row & 7)) << 4));
            }
#pragma unroll
            for (int ng = 0; ng < 4; ng++) {
                int row = rB[ng];
                ldsm4(fb[ng], st + 16384u + row * 128 + ((((uint32_t)(kc + cB)) ^ (row & 7)) << 4));
            }
#pragma unroll
            for (int ng = 0; ng < 4; ng++)
#pragma unroll
                for (int mi = 0; mi < 2; mi++) {
                    mma16816(acc[mi][ng * 2],     fa[mi], fb[ng][0], fb[ng][1]);
                    mma16816(acc[mi][ng * 2 + 1], fa[mi], fb[ng][2], fb[ng][3]);
                }
        }
        __syncthreads();
    }

    int tg = lane >> 2;
    int tc = (lane & 3) * 2;
    float s1[2][2] = {}, s2[2][2] = {};
#pragma unroll
    for (int mi = 0; mi < 2; mi++)
#pragma unroll
        for (int hf = 0; hf < 2; hf++) {
            int row = m0 + wm * 32 + mi * 16 + hf * 8 + tg;
            bool rok = row < M;
#pragma unroll
            for (int ni = 0; ni < 8; ni++) {
                int col = n0 + wn * 64 + ni * 8 + tc;
                float v0 = acc[mi][ni][hf * 2 + 0] + bias[col];
                float v1 = acc[mi][ni][hf * 2 + 1] + bias[col + 1];
                if (rok) {
                    v0 += res[(long)row * N + col];
                    v1 += res[(long)row * N + col + 1];
                    *(float2*)&C[(long)row * N + col] = make_float2(v0, v1);
                }
                acc[mi][ni][hf * 2 + 0] = v0;
                acc[mi][ni][hf * 2 + 1] = v1;
                s1[mi][hf] += v0 + v1;
                s2[mi][hf] += v0 * v0 + v1 * v1;
            }
        }
    if (lnout && lnsc) {
#pragma unroll
        for (int mi = 0; mi < 2; mi++)
#pragma unroll
            for (int hf = 0; hf < 2; hf++) {
                float a = s1[mi][hf], b = s2[mi][hf];
                a += __shfl_xor_sync(~0u, a, 1);
                a += __shfl_xor_sync(~0u, a, 2);
                b += __shfl_xor_sync(~0u, b, 1);
                b += __shfl_xor_sync(~0u, b, 2);
                if ((lane & 3) == 0) {
                    int ri = wm * 32 + mi * 16 + hf * 8 + tg;
                    lnred[wn][ri][0] = a;
                    lnred[wn][ri][1] = b;
                }
            }
        __syncthreads();
#pragma unroll
        for (int mi = 0; mi < 2; mi++)
#pragma unroll
            for (int hf = 0; hf < 2; hf++) {
                int ri = wm * 32 + mi * 16 + hf * 8 + tg;
                int row = m0 + ri;
                if (row >= M) continue;
                float m1 = (lnred[0][ri][0] + lnred[1][ri][0]) * (1.f / 128.f);
                float m2 = (lnred[0][ri][1] + lnred[1][ri][1]) * (1.f / 128.f);
                float inv = rsqrtf(m2 - m1 * m1 + 1e-5f);
#pragma unroll
                for (int ni = 0; ni < 8; ni++) {
                    int col = wn * 64 + ni * 8 + tc;
                    float v0 = (acc[mi][ni][hf * 2 + 0] - m1) * inv * lnsc[col] + lnbi[col];
                    float v1 = (acc[mi][ni][hf * 2 + 1] - m1) * inv * lnsc[col + 1] + lnbi[col + 1];
                    __half hl[2] = {__float2half(v0), __float2half(v1)};
                    *(uint32_t*)&lnout[(long)row * 128 + col] = *(uint32_t*)hl;
                }
            }
    } else if (lnout) {
#pragma unroll
        for (int mi = 0; mi < 2; mi++)
#pragma unroll
            for (int hf = 0; hf < 2; hf++) {
                int row = m0 + wm * 32 + mi * 16 + hf * 8 + tg;
                if (row >= M) continue;
#pragma unroll
                for (int ni = 0; ni < 8; ni++) {
                    int col = n0 + wn * 64 + ni * 8 + tc;
                    __half hl[2] = {__float2half(acc[mi][ni][hf * 2 + 0]),
                                    __float2half(acc[mi][ni][hf * 2 + 1])};
                    *(uint32_t*)&lnout[(long)row * 128 + col] = *(uint32_t*)hl;
                }
            }
    }
}

// ---------------- local windowed attention: K-in-registers -------------------
// block = (window w, batch*head); 8 warps; lane owns keys jstart+lane+32t.
__global__ void __launch_bounds__(256, 2)
attn_k(const __half* __restrict__ qkv, __half* __restrict__ o) {
    __shared__ uint32_t q_s[S1 * 8];          // 61 rows x 8 half2
    __shared__ uint32_t k_s[3 * S1 * 12];     // pitch 12 uints (8 data + 4 pad)
    __shared__ uint32_t v_s[3 * S1 * 12];
    int w = blockIdx.x;
    int bh = blockIdx.y;
    int b = bh >> 3, h = bh & 7;
    int tid = threadIdx.x;
    int warp = tid >> 5, lane = tid & 31;
    int jstart = (w > 0) ? 0 : S1;
    int jend = (w < S1 - 1) ? 3 * S1 : 2 * S1;
    int cnt = jend - jstart;
    long rb = (long)b * SEQ;

    // stage q/k/v rows (uint4 = 8 halves; row = 2 uint4)
    const uint4* qg = (const uint4*)qkv;
    int total = S1 + 2 * cnt;
    for (int idx = tid; idx < total; idx += 256) {
        if (idx < S1) {
            long grow = (rb + (long)w * S1 + idx) * 48 + h * 2;
            uint4 a = qg[grow], c = qg[grow + 1];
            *(uint4*)&q_s[idx * 8] = a;
            *(uint4*)&q_s[idx * 8 + 4] = c;
        } else {
            int r = idx - S1;
            int which = (r >= cnt);
            int j = jstart + (which ? r - cnt : r);
            long grow = (rb + (long)(w - 1) * S1 + j) * 48 + h * 2 + (which ? 32 : 16);
            uint4 a = qg[grow], c = qg[grow + 1];
            uint32_t* dst = (which ? v_s : k_s) + j * 12;
            *(uint4*)dst = a;
            *(uint4*)&dst[4] = c;
        }
    }
    __syncthreads();

    // lane-owned K rows into registers
    uint32_t kreg[6][8];
    int jl[6];
    bool val[6];
#pragma unroll
    for (int t = 0; t < 6; t++) {
        int j = jstart + lane + 32 * t;
        val[t] = (j < jend);
        jl[t] = val[t] ? j : jstart;
        uint4 a = *(uint4*)&k_s[jl[t] * 12];
        uint4 c = *(uint4*)&k_s[jl[t] * 12 + 4];
        kreg[t][0] = a.x; kreg[t][1] = a.y; kreg[t][2] = a.z; kreg[t][3] = a.w;
        kreg[t][4] = c.x; kreg[t][5] = c.y; kreg[t][6] = c.z; kreg[t][7] = c.w;
    }

    for (int i = warp; i < S1; i += 8) {
        // q broadcast
        float qf[16];
#pragma unroll
        for (int dp = 0; dp < 8; dp++) {
            float2 f = __half22float2(*(__half2*)&q_s[i * 8 + dp]);
            qf[dp * 2] = f.x;
            qf[dp * 2 + 1] = f.y;
        }
        // scores
        float sc[6];
#pragma unroll
        for (int t = 0; t < 6; t++) {
            float s = 0.f;
#pragma unroll
            for (int dp = 0; dp < 8; dp++) {
                float2 kf = __half22float2(*(__half2*)&kreg[t][dp]);
                s += qf[dp * 2] * kf.x + qf[dp * 2 + 1] * kf.y;
            }
            sc[t] = val[t] ? s * 0.25f : -1e30f;
        }
        float mx = sc[0];
#pragma unroll
        for (int t = 1; t < 6; t++) mx = fmaxf(mx, sc[t]);
#pragma unroll
        for (int off = 16; off; off >>= 1) mx = fmaxf(mx, __shfl_xor_sync(~0u, mx, off));
        float se = 0.f;
#pragma unroll
        for (int t = 0; t < 6; t++) {
            float p = __expf(sc[t] - mx);
            sc[t] = p;
            se += p;
        }
#pragma unroll
        for (int off = 16; off; off >>= 1) se += __shfl_xor_sync(~0u, se, off);
        // PV (fp32 accumulate, V from smem)
        float acc[16];
#pragma unroll
        for (int d = 0; d < 16; d++) acc[d] = 0.f;
#pragma unroll
        for (int t = 0; t < 6; t++) {
            if (!val[t]) continue;
            float p = sc[t];
            uint4 a = *(uint4*)&v_s[jl[t] * 12];
            uint4 c = *(uint4*)&v_s[jl[t] * 12 + 4];
            uint32_t vr[8] = {a.x, a.y, a.z, a.w, c.x, c.y, c.z, c.w};
#pragma unroll
            for (int dp = 0; dp < 8; dp++) {
                float2 vf = __half22float2(*(__half2*)&vr[dp]);
                acc[dp * 2] += p * vf.x;
                acc[dp * 2 + 1] += p * vf.y;
            }
        }
#pragma unroll
        for (int off = 16; off; off >>= 1)
#pragma unroll
            for (int d = 0; d < 16; d++)
                acc[d] += __shfl_xor_sync(~0u, acc[d], off);
        if (lane == 0) {
            float inv = 1.f / se;
            __half ov[16];
#pragma unroll
            for (int d = 0; d < 16; d++) ov[d] = __float2half(acc[d] * inv);
            uint4* dst = (uint4*)(o + (rb + (long)w * S1 + i) * 128 + h * 16);
            dst[0] = *(uint4*)&ov[0];
            dst[1] = *(uint4*)&ov[8];
        }
    }
}

// ---------------- launch ------------------------------------------------------
extern "C" void kernel_launch(void* const* d_in, const int* in_sizes, int n_in,
                              void* d_out, int out_size) {
    const float* x      = (const float*)d_in[0];
    const float* conv_w = (const float*)d_in[1];
    const float* conv_b = (const float*)d_in[2];
    const float* lt_w   = (const float*)d_in[3];
    const float* lt_b   = (const float*)d_in[4];
    const float* pos    = (const float*)d_in[5];
    const float* ln1_s  = (const float*)d_in[6];
    const float* ln1_b  = (const float*)d_in[7];
    const float* wq     = (const float*)d_in[8];
    const float* wk     = (const float*)d_in[9];
    const float* wv     = (const float*)d_in[10];
    const float* wo     = (const float*)d_in[11];
    const float* wo_b   = (const float*)d_in[12];
    const float* ln2_s  = (const float*)d_in[13];
    const float* ln2_b  = (const float*)d_in[14];
    const float* ff_w1  = (const float*)d_in[15];
    const float* ff_b1  = (const float*)d_in[16];
    const float* ff_w2  = (const float*)d_in[17];
    const float* ff_b2  = (const float*)d_in[18];
    const float* pre_w1 = (const float*)d_in[19];
    const float* pre_b1 = (const float*)d_in[20];
    const float* pre_w2 = (const float*)d_in[21];
    const float* pre_b2 = (const float*)d_in[22];
    float* out = (float*)d_out;

    static bool attr_done = false;
    if (!attr_done) {
        cudaFuncSetAttribute(tgemmA<0,2>, cudaFuncAttributeMaxDynamicSharedMemorySize, 98304);
        cudaFuncSetAttribute(tgemmA<2,1>, cudaFuncAttributeMaxDynamicSharedMemorySize, 49152);
        cudaFuncSetAttribute(tgemmA<3,2>, cudaFuncAttributeMaxDynamicSharedMemorySize, 98304);
        cudaFuncSetAttribute(tgemmA<4,2>, cudaFuncAttributeMaxDynamicSharedMemorySize, 98304);
        cudaFuncSetAttribute(tgemmA<5,2>, cudaFuncAttributeMaxDynamicSharedMemorySize, 98304);
        cudaFuncSetAttribute(tgemmC, cudaFuncAttributeMaxDynamicSharedMemorySize, 98304);
        attr_done = true;
    }

    __half *p, *lnb, *att, *ff, *hh, *wlt, *wqkv, *woh, *wf1, *wf2, *wp1, *qkvh;
    float *h;
    cudaGetSymbolAddress((void**)&p, g_p);       cudaGetSymbolAddress((void**)&h, g_h);
    cudaGetSymbolAddress((void**)&lnb, g_ln);    cudaGetSymbolAddress((void**)&qkvh, g_qkv);
    cudaGetSymbolAddress((void**)&att, g_att);   cudaGetSymbolAddress((void**)&ff, g_ff);
    cudaGetSymbolAddress((void**)&hh, g_hh);     cudaGetSymbolAddress((void**)&wlt, g_wlt);
    cudaGetSymbolAddress((void**)&wqkv, g_wqkv); cudaGetSymbolAddress((void**)&woh, g_wo);
    cudaGetSymbolAddress((void**)&wf1, g_wf1);   cudaGetSymbolAddress((void**)&wf2, g_wf2);
    cudaGetSymbolAddress((void**)&wp1, g_wp1);

    const int M = MROWS;
    dim3 gA(1, MTILES);

    prep_all<<<(PREP_TOTAL + 255) / 256, 256>>>(lt_w, wq, wk, wv, wo, ff_w1, ff_w2, pre_w1,
                                                wlt, wqkv, woh, wf1, wf2, wp1);
    conv_k<<<(MROWS * 64 + 255) / 256, 256>>>(x, conv_w, conv_b, p);
    tgemmA<2,1><<<gA, 256, 49152>>>(p, wlt, lt_b, nullptr, pos, nullptr,
                                    h, nullptr, ln1_s, ln1_b, lnb, M, 128, 1);

    for (int i = 0; i < NLAYER; i++) {
        tgemmA<0,2><<<gA, 256, 98304>>>(lnb, wqkv + (long)i * 49152,
            nullptr, nullptr, nullptr, nullptr, nullptr, qkvh,
            nullptr, nullptr, nullptr, M, 384, 3);
        attn_k<<<dim3(S1, BATCH * HEADS), 256>>>(qkvh, att);
        tgemmA<3,2><<<gA, 256, 98304>>>(att, woh + (long)i * 16384,
            wo_b + i * 128, h, nullptr, nullptr, h, nullptr,
            ln2_s + i * 128, ln2_b + i * 128, lnb, M, 128, 1);
        tgemmA<4,2><<<gA, 256, 98304>>>(lnb, wf1 + (long)i * 65536,
            ff_b1 + i * 512, nullptr, nullptr, nullptr, nullptr, ff,
            nullptr, nullptr, nullptr, M, 512, 4);
        bool last = (i == NLAYER - 1);
        tgemmC<<<dim3(1, MTILES), 256, 98304>>>(ff, wf2 + (long)i * 65536,
            ff_b2 + i * 128, h, h,
            last ? nullptr : ln1_s + (i + 1) * 128,
            last ? nullptr : ln1_b + (i + 1) * 128,
            last ? hh : lnb, M, 128, 512);
    }

    tgemmA<5,2><<<gA, 256, 98304>>>(hh, wp1, pre_b1, nullptr, pre_b2, pre_w2,
                                    out, nullptr, nullptr, nullptr, nullptr, M, 128, 1);
}

// round 10
// speedup vs baseline: 2.8733x; 2.1342x over previous
#include <cuda_runtime.h>
#include <cuda_fp16.h>
#include <cstdint>
#include <math.h>

#define BATCH 16
#define S1 61
#define SEQ 3721
#define DMODEL 128
#define HEADS 8
#define DH 16
#define NLAYER 4
#define FFDIM 512
#define PCH 49
#define MROWS (BATCH * SEQ) // 59536
#define MTILES ((MROWS + 127) / 128) // 466

// ---------------------------------------------------------------- scratch
__device__ __half g_p[MROWS * 64];
__device__ float  g_h[MROWS * 128];
__device__ __half g_ln[MROWS * 128];
__device__ __half g_qkv[(size_t)MROWS * 384];
__device__ __half g_att[MROWS * 128];
__device__ __half g_ff[(size_t)MROWS * 512];
__device__ __half g_hh[MROWS * 128];
__device__ __half g_wlt[128 * 64];
__device__ __half g_wqkv[NLAYER * 384 * 128];
__device__ __half g_wo[NLAYER * 128 * 128];
__device__ __half g_wf1[NLAYER * 512 * 128];
__device__ __half g_wf2[NLAYER * 128 * 512];
__device__ __half g_wp1[128 * 128];

// ---------------------------------------------------------------- helpers
__device__ __forceinline__ uint32_t smem_u32(const void* p) {
    uint32_t a;
    asm("{ .reg .u64 t; cvta.to.shared.u64 t, %1; cvt.u32.u64 %0, t; }" : "=r"(a) : "l"(p));
    return a;
}
__device__ __forceinline__ void ldsm4(uint32_t* r, uint32_t addr) {
    asm volatile("ldmatrix.sync.aligned.m8n8.x4.shared.b16 {%0,%1,%2,%3}, [%4];"
                 : "=r"(r[0]), "=r"(r[1]), "=r"(r[2]), "=r"(r[3]) : "r"(addr));
}
__device__ __forceinline__ void ldsm4t(uint32_t* r, uint32_t addr) {
    asm volatile("ldmatrix.sync.aligned.m8n8.x4.trans.shared.b16 {%0,%1,%2,%3}, [%4];"
                 : "=r"(r[0]), "=r"(r[1]), "=r"(r[2]), "=r"(r[3]) : "r"(addr));
}
__device__ __forceinline__ void mma16816(float* c, const uint32_t* a, uint32_t b0, uint32_t b1) {
    asm volatile("mma.sync.aligned.m16n8k16.row.col.f32.f16.f16.f32 "
                 "{%0,%1,%2,%3}, {%4,%5,%6,%7}, {%8,%9}, {%0,%1,%2,%3};"
                 : "+f"(c[0]), "+f"(c[1]), "+f"(c[2]), "+f"(c[3])
                 : "r"(a[0]), "r"(a[1]), "r"(a[2]), "r"(a[3]), "r"(b0), "r"(b1));
}
__device__ __forceinline__ void cpasync16(uint32_t saddr, const void* g, uint32_t ssz) {
    asm volatile("cp.async.cg.shared.global [%0], [%1], 16, %2;"
                 :: "r"(saddr), "l"(g), "r"(ssz));
}
#define CP_COMMIT() asm volatile("cp.async.commit_group;" ::: "memory")
#define CP_WAIT(n)  asm volatile("cp.async.wait_group %0;" :: "n"(n) : "memory")

// ------------------------------------------- single fused weight prep --------
__global__ void prep_all(const float* __restrict__ lt_w, const float* __restrict__ wq,
                         const float* __restrict__ wk, const float* __restrict__ wv,
                         const float* __restrict__ wo, const float* __restrict__ ff_w1,
                         const float* __restrict__ ff_w2, const float* __restrict__ pre_w1,
                         __half* __restrict__ wlt, __half* __restrict__ wqkv,
                         __half* __restrict__ woh, __half* __restrict__ wf1,
                         __half* __restrict__ wf2, __half* __restrict__ wp1) {
    long t = (long)blockIdx.x * blockDim.x + threadIdx.x;
    if (t < 8192) {
        int n = (int)(t >> 6), kk = (int)(t & 63);
        wlt[t] = __float2half(kk < 49 ? lt_w[kk * 128 + n] : 0.f);
        return;
    }
    t -= 8192;
    if (t < 196608) {
        int l = (int)(t / 49152), r = (int)(t % 49152);
        int n = r >> 7, kk = r & 127;
        int s = n >> 7, nn = n & 127;
        const float* W = (s == 0 ? wq : s == 1 ? wk : wv) + (long)l * 16384;
        wqkv[t] = __float2half(W[kk * 128 + nn]);
        return;
    }
    t -= 196608;
    if (t < 65536) {
        int l = (int)(t / 16384), r = (int)(t % 16384);
        int n = r >> 7, kk = r & 127;
        woh[t] = __float2half(wo[(long)l * 16384 + kk * 128 + n]);
        return;
    }
    t -= 65536;
    if (t < 262144) {
        int l = (int)(t / 65536), r = (int)(t % 65536);
        int n = r >> 7, kk = r & 127;
        wf1[t] = __float2half(ff_w1[(long)l * 65536 + (long)kk * 512 + n]);
        return;
    }
    t -= 262144;
    if (t < 262144) {
        int l = (int)(t / 65536), r = (int)(t % 65536);
        int n = r / 512, kk = r % 512;
        wf2[t] = __float2half(ff_w2[(long)l * 65536 + (long)kk * 128 + n]);
        return;
    }
    t -= 262144;
    if (t < 16384) {
        int n = (int)(t >> 7), kk = (int)(t & 127);
        wp1[t] = __float2half(pre_w1[kk * 128 + n]);
    }
}
#define PREP_TOTAL (8192 + 196608 + 65536 + 262144 + 262144 + 16384)

// ---------------- conv 7x7 'same' + relu -> fp16 [M,64] ----------------------
__global__ void conv_k(const float* __restrict__ x, const float* __restrict__ cw,
                       const float* __restrict__ cb, __half* __restrict__ p) {
    int t = blockIdx.x * blockDim.x + threadIdx.x;
    if (t >= MROWS * 64) return;
    int o = t & 63;
    float sum = 0.f;
    if (o < PCH) {
        int s = (t >> 6) % SEQ;
        int b = (t >> 6) / SEQ;
        int y = s / S1, xx = s % S1;
        const float* xb = x + (long)b * SEQ;
        const float* wo = cw + o * 49;
        sum = cb[o];
#pragma unroll
        for (int dy = 0; dy < 7; dy++) {
            int iy = y + dy - 3;
            if (iy < 0 || iy >= S1) continue;
#pragma unroll
            for (int dx = 0; dx < 7; dx++) {
                int ix = xx + dx - 3;
                if (ix < 0 || ix >= S1) continue;
                sum += xb[iy * S1 + ix] * wo[dy * 7 + dx];
            }
        }
        sum = fmaxf(sum, 0.f);
    }
    p[t] = __float2half(sum);
}

// =============== A-resident fp16 GEMM (K<=128), N-loop inside ================
template <int EPI, int NK>
__global__ void __launch_bounds__(256, 2)
tgemmA(const __half* __restrict__ A, const __half* __restrict__ B,
       const float* __restrict__ bias, const float* __restrict__ res,
       const float* __restrict__ pos, const float* __restrict__ w2,
       float* __restrict__ C, __half* __restrict__ Ch,
       const float* __restrict__ lnsc, const float* __restrict__ lnbi,
       __half* __restrict__ lnout, int M, int Nfull, int NT) {
    extern __shared__ char sm[];
    __shared__ float red[2][128];
    __shared__ float lnred[2][128][2];
    uint32_t sb = smem_u32(sm);
    const int K = NK * 64;
    const uint32_t ABYTES = (uint32_t)NK * 16384u;
    int tid = threadIdx.x;
    int w = tid >> 5, lane = tid & 31;
    int wm = w & 3, wn = w >> 2;
    int m0 = blockIdx.y * 128;

    int rA[2], rB[4];
#pragma unroll
    for (int mi = 0; mi < 2; mi++) rA[mi] = wm * 32 + mi * 16 + (lane & 15);
#pragma unroll
    for (int ng = 0; ng < 4; ng++)
        rB[ng] = wn * 64 + ng * 16 + ((lane >> 4) << 3) + (lane & 7);
    int cA = lane >> 4;
    int cB = (lane >> 3) & 1;

#pragma unroll
    for (int t = 0; t < NK * 4; t++) {
        int slot = t * 256 + tid;
        int tile = slot >> 10;
        int idx = slot & 1023;
        int row = idx >> 3, c16 = idx & 7;
        long grow = m0 + row;
        bool ok = grow < M;
        if (!ok) grow = 0;
        cpasync16(sb + (uint32_t)tile * 16384u + row * 128 + (((uint32_t)c16 ^ (row & 7)) << 4),
                  A + grow * K + tile * 64 + c16 * 8, ok ? 16u : 0u);
    }
    CP_COMMIT();

    auto loadB = [&](int nt) {
#pragma unroll
        for (int t = 0; t < NK * 4; t++) {
            int slot = t * 256 + tid;
            int tile = slot >> 10;
            int idx = slot & 1023;
            int row = idx >> 3, c16 = idx & 7;
            long grow = (long)(nt * 128 + row);
            cpasync16(sb + ABYTES + (uint32_t)(nt & 1) * ABYTES + (uint32_t)tile * 16384u +
                          row * 128 + (((uint32_t)c16 ^ (row & 7)) << 4),
                      B + grow * K + tile * 64 + c16 * 8, 16u);
        }
        CP_COMMIT();
    };
    loadB(0);

    for (int nt = 0; nt < NT; nt++) {
        if (nt + 1 < NT) { loadB(nt + 1); CP_WAIT(1); }
        else             { CP_WAIT(0); }
        __syncthreads();

        float acc[2][8][4];
#pragma unroll
        for (int i = 0; i < 2; i++)
#pragma unroll
            for (int j = 0; j < 8; j++)
#pragma unroll
                for (int q = 0; q < 4; q++) acc[i][j][q] = 0.f;

        uint32_t Bbase = sb + ABYTES + (uint32_t)(nt & 1) * ABYTES;
#pragma unroll
        for (int i = 0; i < NK * 4; i++) {
            int chunk = i >> 2, ks = i & 3, kc = ks * 2;
            uint32_t Ab = sb + (uint32_t)chunk * 16384u;
            uint32_t Bb = Bbase + (uint32_t)chunk * 16384u;
            uint32_t fa[2][4], fb[4][4];
#pragma unroll
            for (int mi = 0; mi < 2; mi++) {
                int row = rA[mi];
                ldsm4(fa[mi], Ab + row * 128 + ((((uint32_t)(kc + cA)) ^ (row & 7)) << 4));
            }
#pragma unroll
            for (int ng = 0; ng < 4; ng++) {
                int row = rB[ng];
                ldsm4(fb[ng], Bb + row * 128 + ((((uint32_t)(kc + cB)) ^ (row & 7)) << 4));
            }
#pragma unroll
            for (int ng = 0; ng < 4; ng++)
#pragma unroll
                for (int mi = 0; mi < 2; mi++) {
                    mma16816(acc[mi][ng * 2],     fa[mi], fb[ng][0], fb[ng][1]);
                    mma16816(acc[mi][ng * 2 + 1], fa[mi], fb[ng][2], fb[ng][3]);
                }
        }
        __syncthreads();

        int n0 = nt * 128;
        int tg = lane >> 2;
        int tc = (lane & 3) * 2;

        if (EPI == 5) {
            float p[2][2] = {};
#pragma unroll
            for (int mi = 0; mi < 2; mi++)
#pragma unroll
                for (int ni = 0; ni < 8; ni++) {
                    int col = wn * 64 + ni * 8 + tc;
                    float b0 = bias[col], b1 = bias[col + 1];
                    float w20 = w2[col], w21 = w2[col + 1];
                    p[mi][0] += fmaxf(acc[mi][ni][0] + b0, 0.f) * w20 +
                                fmaxf(acc[mi][ni][1] + b1, 0.f) * w21;
                    p[mi][1] += fmaxf(acc[mi][ni][2] + b0, 0.f) * w20 +
                                fmaxf(acc[mi][ni][3] + b1, 0.f) * w21;
                }
#pragma unroll
            for (int mi = 0; mi < 2; mi++)
#pragma unroll
                for (int hf = 0; hf < 2; hf++) {
                    float v = p[mi][hf];
                    v += __shfl_xor_sync(~0u, v, 1);
                    v += __shfl_xor_sync(~0u, v, 2);
                    if ((lane & 3) == 0) red[wn][wm * 32 + mi * 16 + hf * 8 + tg] = v;
                }
            __syncthreads();
            if (tid < 128) {
                int row = m0 + tid;
                if (row < M) C[row] = red[0][tid] + red[1][tid] + pos[0];
            }
            continue;
        }

        if (EPI == 0 || EPI == 4) {
#pragma unroll
            for (int mi = 0; mi < 2; mi++)
#pragma unroll
                for (int hf = 0; hf < 2; hf++) {
                    int row = m0 + wm * 32 + mi * 16 + hf * 8 + tg;
                    if (row >= M) continue;
#pragma unroll
                    for (int ni = 0; ni < 8; ni++) {
                        int col = n0 + wn * 64 + ni * 8 + tc;
                        float v0 = acc[mi][ni][hf * 2 + 0];
                        float v1 = acc[mi][ni][hf * 2 + 1];
                        if (EPI == 4) {
                            v0 += bias[col];
                            v1 += bias[col + 1];
                            v0 = 0.5f * v0 * (1.f + erff(v0 * 0.70710678118654752f));
                            v1 = 0.5f * v1 * (1.f + erff(v1 * 0.70710678118654752f));
                        }
                        __half hl[2] = {__float2half(v0), __float2half(v1)};
                        *(uint32_t*)&Ch[(long)row * Nfull + col] = *(uint32_t*)hl;
                    }
                }
            continue;
        }

        // EPI 2/3
        float s1[2][2] = {}, s2[2][2] = {};
#pragma unroll
        for (int mi = 0; mi < 2; mi++)
#pragma unroll
            for (int hf = 0; hf < 2; hf++) {
                int row = m0 + wm * 32 + mi * 16 + hf * 8 + tg;
                bool rok = row < M;
                long pr = (EPI == 2 && rok) ? (long)(row % SEQ) * 128 : 0;
#pragma unroll
                for (int ni = 0; ni < 8; ni++) {
                    int col = n0 + wn * 64 + ni * 8 + tc;
                    float v0 = acc[mi][ni][hf * 2 + 0] + bias[col];
                    float v1 = acc[mi][ni][hf * 2 + 1] + bias[col + 1];
                    if (rok) {
                        if (EPI == 2) {
                            v0 += pos[pr + col];
                            v1 += pos[pr + col + 1];
                        } else {
                            v0 += res[(long)row * Nfull + col];
                            v1 += res[(long)row * Nfull + col + 1];
                        }
                        *(float2*)&C[(long)row * Nfull + col] = make_float2(v0, v1);
                    }
                    acc[mi][ni][hf * 2 + 0] = v0;
                    acc[mi][ni][hf * 2 + 1] = v1;
                    s1[mi][hf] += v0 + v1;
                    s2[mi][hf] += v0 * v0 + v1 * v1;
                }
            }
        if (lnout) {
#pragma unroll
            for (int mi = 0; mi < 2; mi++)
#pragma unroll
                for (int hf = 0; hf < 2; hf++) {
                    float a = s1[mi][hf], b = s2[mi][hf];
                    a += __shfl_xor_sync(~0u, a, 1);
                    a += __shfl_xor_sync(~0u, a, 2);
                    b += __shfl_xor_sync(~0u, b, 1);
                    b += __shfl_xor_sync(~0u, b, 2);
                    if ((lane & 3) == 0) {
                        int ri = wm * 32 + mi * 16 + hf * 8 + tg;
                        lnred[wn][ri][0] = a;
                        lnred[wn][ri][1] = b;
                    }
                }
            __syncthreads();
#pragma unroll
            for (int mi = 0; mi < 2; mi++)
#pragma unroll
                for (int hf = 0; hf < 2; hf++) {
                    int ri = wm * 32 + mi * 16 + hf * 8 + tg;
                    int row = m0 + ri;
                    if (row >= M) continue;
                    float m1 = (lnred[0][ri][0] + lnred[1][ri][0]) * (1.f / 128.f);
                    float m2 = (lnred[0][ri][1] + lnred[1][ri][1]) * (1.f / 128.f);
                    float inv = rsqrtf(m2 - m1 * m1 + 1e-5f);
#pragma unroll
                    for (int ni = 0; ni < 8; ni++) {
                        int col = wn * 64 + ni * 8 + tc;
                        float v0 = (acc[mi][ni][hf * 2 + 0] - m1) * inv * lnsc[col] + lnbi[col];
                        float v1 = (acc[mi][ni][hf * 2 + 1] - m1) * inv * lnsc[col + 1] + lnbi[col + 1];
                        __half hl[2] = {__float2half(v0), __float2half(v1)};
                        *(uint32_t*)&lnout[(long)row * 128 + col] = *(uint32_t*)hl;
                    }
                }
        }
    }
}

// =============== chunked fp16 GEMM for K=512 (ff2) + fused LN/out ============
#define CSTAGE_B 32768u

__global__ void __launch_bounds__(256, 2)
tgemmC(const __half* __restrict__ A, const __half* __restrict__ B,
       const float* __restrict__ bias, const float* __restrict__ res,
       float* __restrict__ C, const float* __restrict__ lnsc,
       const float* __restrict__ lnbi, __half* __restrict__ lnout,
       int M, int N, int K) {
    extern __shared__ char sm[];
    __shared__ float lnred[2][128][2];
    uint32_t sb = smem_u32(sm);
    int tid = threadIdx.x;
    int w = tid >> 5, lane = tid & 31;
    int wm = w & 3, wn = w >> 2;
    int m0 = blockIdx.y * 128, n0 = blockIdx.x * 128;
    int nk = K >> 6;

    float acc[2][8][4];
#pragma unroll
    for (int i = 0; i < 2; i++)
#pragma unroll
        for (int j = 0; j < 8; j++)
#pragma unroll
            for (int q = 0; q < 4; q++) acc[i][j][q] = 0.f;

    int rA[2], rB[4];
#pragma unroll
    for (int mi = 0; mi < 2; mi++) rA[mi] = wm * 32 + mi * 16 + (lane & 15);
#pragma unroll
    for (int ng = 0; ng < 4; ng++)
        rB[ng] = wn * 64 + ng * 16 + ((lane >> 4) << 3) + (lane & 7);
    int cA = lane >> 4;
    int cB = (lane >> 3) & 1;

    auto load_stage = [&](int c, int buf) {
#pragma unroll
        for (int it = 0; it < 8; it++) {
            int slot = it * 256 + tid;
            int t = it >> 2;
            int row = (slot >> 3) & 127;
            int chunk = slot & 7;
            const __half* src = t ? B : A;
            long grow = t ? (long)(n0 + row) : (long)(m0 + row);
            bool ok = t ? true : (m0 + row < M);
            if (!ok) grow = 0;
            const void* g = (const void*)(src + grow * K + ((long)c << 6) + chunk * 8);
            uint32_t saddr = sb + buf * CSTAGE_B + (uint32_t)t * 16384u + row * 128 +
                             ((chunk ^ (row & 7)) << 4);
            cpasync16(saddr, g, ok ? 16u : 0u);
        }
        CP_COMMIT();
    };

#pragma unroll
    for (int p = 0; p < 2; p++) load_stage(p, p);

    for (int c = 0; c < nk; c++) {
        int nxt = c + 2;
        if (nxt < nk) load_stage(nxt, nxt % 3);
        int allow = (nxt < nk ? nxt : nk - 1) - c;
        if (allow >= 2) CP_WAIT(2);
        else if (allow == 1) CP_WAIT(1);
        else CP_WAIT(0);
        __syncthreads();

        uint32_t st = sb + (c % 3) * CSTAGE_B;
#pragma unroll
        for (int ks = 0; ks < 4; ks++) {
            int kc = ks * 2;
            uint32_t fa[2][4], fb[4][4];
#pragma unroll
            for (int mi = 0; mi < 2; mi++) {
                int row = rA[mi];
                ldsm4(fa[mi], st + row * 128 + ((((uint32_t)(kc + cA)) ^ (row & 7)) << 4));
            }
#pragma unroll
            for (int ng = 0; ng < 4; ng++) {
                int row = rB[ng];
                ldsm4(fb[ng], st + 16384u + row * 128 + ((((uint32_t)(kc + cB)) ^ (row & 7)) << 4));
            }
#pragma unroll
            for (int ng = 0; ng < 4; ng++)
#pragma unroll
                for (int mi = 0; mi < 2; mi++) {
                    mma16816(acc[mi][ng * 2],     fa[mi], fb[ng][0], fb[ng][1]);
                    mma16816(acc[mi][ng * 2 + 1], fa[mi], fb[ng][2], fb[ng][3]);
                }
        }
        __syncthreads();
    }

    int tg = lane >> 2;
    int tc = (lane & 3) * 2;
    float s1[2][2] = {}, s2[2][2] = {};
#pragma unroll
    for (int mi = 0; mi < 2; mi++)
#pragma unroll
        for (int hf = 0; hf < 2; hf++) {
            int row = m0 + wm * 32 + mi * 16 + hf * 8 + tg;
            bool rok = row < M;
#pragma unroll
            for (int ni = 0; ni < 8; ni++) {
                int col = n0 + wn * 64 + ni * 8 + tc;
                float v0 = acc[mi][ni][hf * 2 + 0] + bias[col];
                float v1 = acc[mi][ni][hf * 2 + 1] + bias[col + 1];
                if (rok) {
                    v0 += res[(long)row * N + col];
                    v1 += res[(long)row * N + col + 1];
                    *(float2*)&C[(long)row * N + col] = make_float2(v0, v1);
                }
                acc[mi][ni][hf * 2 + 0] = v0;
                acc[mi][ni][hf * 2 + 1] = v1;
                s1[mi][hf] += v0 + v1;
                s2[mi][hf] += v0 * v0 + v1 * v1;
            }
        }
    if (lnout && lnsc) {
#pragma unroll
        for (int mi = 0; mi < 2; mi++)
#pragma unroll
            for (int hf = 0; hf < 2; hf++) {
                float a = s1[mi][hf], b = s2[mi][hf];
                a += __shfl_xor_sync(~0u, a, 1);
                a += __shfl_xor_sync(~0u, a, 2);
                b += __shfl_xor_sync(~0u, b, 1);
                b += __shfl_xor_sync(~0u, b, 2);
                if ((lane & 3) == 0) {
                    int ri = wm * 32 + mi * 16 + hf * 8 + tg;
                    lnred[wn][ri][0] = a;
                    lnred[wn][ri][1] = b;
                }
            }
        __syncthreads();
#pragma unroll
        for (int mi = 0; mi < 2; mi++)
#pragma unroll
            for (int hf = 0; hf < 2; hf++) {
                int ri = wm * 32 + mi * 16 + hf * 8 + tg;
                int row = m0 + ri;
                if (row >= M) continue;
                float m1 = (lnred[0][ri][0] + lnred[1][ri][0]) * (1.f / 128.f);
                float m2 = (lnred[0][ri][1] + lnred[1][ri][1]) * (1.f / 128.f);
                float inv = rsqrtf(m2 - m1 * m1 + 1e-5f);
#pragma unroll
                for (int ni = 0; ni < 8; ni++) {
                    int col = wn * 64 + ni * 8 + tc;
                    float v0 = (acc[mi][ni][hf * 2 + 0] - m1) * inv * lnsc[col] + lnbi[col];
                    float v1 = (acc[mi][ni][hf * 2 + 1] - m1) * inv * lnsc[col + 1] + lnbi[col + 1];
                    __half hl[2] = {__float2half(v0), __float2half(v1)};
                    *(uint32_t*)&lnout[(long)row * 128 + col] = *(uint32_t*)hl;
                }
            }
    } else if (lnout) {
#pragma unroll
        for (int mi = 0; mi < 2; mi++)
#pragma unroll
            for (int hf = 0; hf < 2; hf++) {
                int row = m0 + wm * 32 + mi * 16 + hf * 8 + tg;
                if (row >= M) continue;
#pragma unroll
                for (int ni = 0; ni < 8; ni++) {
                    int col = n0 + wn * 64 + ni * 8 + tc;
                    __half hl[2] = {__float2half(acc[mi][ni][hf * 2 + 0]),
                                    __float2half(acc[mi][ni][hf * 2 + 1])};
                    *(uint32_t*)&lnout[(long)row * 128 + col] = *(uint32_t*)hl;
                }
            }
    }
}

// ---------------- MMA local windowed attention --------------------------------
// block = (window w, batch*head); 8 warps = 4 m16-tiles x 2 key-halves (96 each)
__global__ void __launch_bounds__(256, 2)
attn_k(const __half* __restrict__ qkv, __half* __restrict__ o) {
    __shared__ __half q_s[64 * 24];     // pitch 24 halves (48B)
    __shared__ __half k_s[192 * 24];
    __shared__ __half v_s[192 * 24];
    __shared__ float ms_s[2][4][16];
    __shared__ float ls_s[2][4][16];
    __shared__ float osum[2][4][16][16];
    int w = blockIdx.x, bh = blockIdx.y;
    int b = bh >> 3, h = bh & 7;
    int tid = threadIdx.x, warp = tid >> 5, lane = tid & 31;
    int wm = warp & 3, wn = warp >> 2;
    int jstart = (w > 0) ? 0 : S1;
    int jend = (w < S1 - 1) ? 3 * S1 : 2 * S1;
    int cnt = jend - jstart;
    long rb = (long)b * SEQ;
    const uint4* qg = (const uint4*)qkv;

    // stage q/k/v (rows of 16 halves = 2 uint4, pitch 24 halves)
    int total = S1 + 2 * cnt;
    for (int idx = tid; idx < total; idx += 256) {
        if (idx < S1) {
            long grow = (rb + (long)w * S1 + idx) * 48 + h * 2;
            uint4 a = qg[grow], c = qg[grow + 1];
            *(uint4*)&q_s[idx * 24] = a;
            *(uint4*)&q_s[idx * 24 + 8] = c;
        } else {
            int r = idx - S1;
            int which = (r >= cnt);
            int jl = which ? r - cnt : r;
            long grow = (rb + (long)(w - 1) * S1 + jstart + jl) * 48 + h * 2 + (which ? 32 : 16);
            uint4 a = qg[grow], c = qg[grow + 1];
            __half* dst = (which ? v_s : k_s) + jl * 24;
            *(uint4*)dst = a;
            *(uint4*)&dst[8] = c;
        }
    }
    if (tid < 9) *(uint4*)&q_s[61 * 24 + tid * 8] = make_uint4(0, 0, 0, 0);
    // CRITICAL: zero K/V rows [cnt,192) — garbage V would give 0*NaN=NaN in PV MMA
    for (int r = cnt + tid; r < 192; r += 256) {
        uint4 z = make_uint4(0, 0, 0, 0);
        *(uint4*)&k_s[r * 24] = z;
        *(uint4*)&k_s[r * 24 + 8] = z;
        *(uint4*)&v_s[r * 24] = z;
        *(uint4*)&v_s[r * 24 + 8] = z;
    }
    __syncthreads();

    uint32_t qb = smem_u32(q_s), kbb = smem_u32(k_s), vbb = smem_u32(v_s);

    // A fragment (Q rows wm*16..+16, k=dh16)
    uint32_t a[4];
    ldsm4(a, qb + (uint32_t)(wm * 16 + ((lane >> 3) & 1) * 8 + (lane & 7)) * 48 + (lane >> 4) * 16);

    // S = Q K^T : 12 n8-tiles per warp (keys wn*96 .. +96)
    float s[12][4];
#pragma unroll
    for (int ti = 0; ti < 12; ti++)
#pragma unroll
        for (int e = 0; e < 4; e++) s[ti][e] = 0.f;
#pragma unroll
    for (int g = 0; g < 6; g++) {
        uint32_t r[4];
        ldsm4(r, kbb + (uint32_t)(wn * 96 + g * 16 + (lane >> 4) * 8 + (lane & 7)) * 48 +
                   ((lane >> 3) & 1) * 16);
        mma16816(s[g * 2],     a, r[0], r[1]);
        mma16816(s[g * 2 + 1], a, r[2], r[3]);
    }

    // scale + mask + row max
    float mloc[2] = {-1e30f, -1e30f};
#pragma unroll
    for (int ti = 0; ti < 12; ti++) {
        int cbase = wn * 96 + ti * 8 + (lane & 3) * 2;
#pragma unroll
        for (int e = 0; e < 4; e++) {
            int col = cbase + (e & 1);
            float v = (col < cnt) ? s[ti][e] * 0.25f : -1e30f;
            s[ti][e] = v;
            mloc[e >> 1] = fmaxf(mloc[e >> 1], v);
        }
    }
#pragma unroll
    for (int i = 0; i < 2; i++) {
        mloc[i] = fmaxf(mloc[i], __shfl_xor_sync(~0u, mloc[i], 1));
        mloc[i] = fmaxf(mloc[i], __shfl_xor_sync(~0u, mloc[i], 2));
    }
    if ((lane & 3) == 0) {
        ms_s[wn][wm][lane >> 2] = mloc[0];
        ms_s[wn][wm][(lane >> 2) + 8] = mloc[1];
    }
    __syncthreads();
    float m0 = fmaxf(ms_s[0][wm][lane >> 2], ms_s[1][wm][lane >> 2]);
    float m1 = fmaxf(ms_s[0][wm][(lane >> 2) + 8], ms_s[1][wm][(lane >> 2) + 8]);

    // exp + row sum + pack P to fp16 A-fragments
    float lloc[2] = {0.f, 0.f};
    uint32_t ph[12][2];
#pragma unroll
    for (int ti = 0; ti < 12; ti++) {
        float p0 = __expf(s[ti][0] - m0);
        float p1 = __expf(s[ti][1] - m0);
        float p2 = __expf(s[ti][2] - m1);
        float p3 = __expf(s[ti][3] - m1);
        lloc[0] += p0 + p1;
        lloc[1] += p2 + p3;
        __half2 h01 = __floats2half2_rn(p0, p1);
        __half2 h23 = __floats2half2_rn(p2, p3);
        ph[ti][0] = *(uint32_t*)&h01;
        ph[ti][1] = *(uint32_t*)&h23;
    }
#pragma unroll
    for (int i = 0; i < 2; i++) {
        lloc[i] += __shfl_xor_sync(~0u, lloc[i], 1);
        lloc[i] += __shfl_xor_sync(~0u, lloc[i], 2);
    }
    if ((lane & 3) == 0) {
        ls_s[wn][wm][lane >> 2] = lloc[0];
        ls_s[wn][wm][(lane >> 2) + 8] = lloc[1];
    }

    // O_partial = P V (contraction over this warp's 96 keys)
    float oa[2][4] = {{0.f, 0.f, 0.f, 0.f}, {0.f, 0.f, 0.f, 0.f}};
#pragma unroll
    for (int g = 0; g < 6; g++) {
        uint32_t r[4];
        ldsm4t(r, vbb + (uint32_t)(wn * 96 + g * 16 + ((lane >> 3) & 1) * 8 + (lane & 7)) * 48 +
                    (lane >> 4) * 16);
        uint32_t pa[4] = {ph[g * 2][0], ph[g * 2][1], ph[g * 2 + 1][0], ph[g * 2 + 1][1]};
        mma16816(oa[0], pa, r[0], r[1]);
        mma16816(oa[1], pa, r[2], r[3]);
    }
    // store partials
    {
        int rl = lane >> 2, cc = (lane & 3) * 2;
        *(float2*)&osum[wn][wm][rl][cc]         = make_float2(oa[0][0], oa[0][1]);
        *(float2*)&osum[wn][wm][rl + 8][cc]     = make_float2(oa[0][2], oa[0][3]);
        *(float2*)&osum[wn][wm][rl][cc + 8]     = make_float2(oa[1][0], oa[1][1]);
        *(float2*)&osum[wn][wm][rl + 8][cc + 8] = make_float2(oa[1][2], oa[1][3]);
    }
    __syncthreads();

    // combine halves, normalize, write output
    for (int idx = tid; idx < S1 * 16; idx += 256) {
        int i = idx >> 4, d = idx & 15;
        int wmq = i >> 4, rl = i & 15;
        float val = osum[0][wmq][rl][d] + osum[1][wmq][rl][d];
        float l = ls_s[0][wmq][rl] + ls_s[1][wmq][rl];
        o[(rb + (long)w * S1 + i) * 128 + h * 16 + d] = __float2half(val / l);
    }
}

// ---------------- launch ------------------------------------------------------
extern "C" void kernel_launch(void* const* d_in, const int* in_sizes, int n_in,
                              void* d_out, int out_size) {
    const float* x      = (const float*)d_in[0];
    const float* conv_w = (const float*)d_in[1];
    const float* conv_b = (const float*)d_in[2];
    const float* lt_w   = (const float*)d_in[3];
    const float* lt_b   = (const float*)d_in[4];
    const float* pos    = (const float*)d_in[5];
    const float* ln1_s  = (const float*)d_in[6];
    const float* ln1_b  = (const float*)d_in[7];
    const float* wq     = (const float*)d_in[8];
    const float* wk     = (const float*)d_in[9];
    const float* wv     = (const float*)d_in[10];
    const float* wo     = (const float*)d_in[11];
    const float* wo_b   = (const float*)d_in[12];
    const float* ln2_s  = (const float*)d_in[13];
    const float* ln2_b  = (const float*)d_in[14];
    const float* ff_w1  = (const float*)d_in[15];
    const float* ff_b1  = (const float*)d_in[16];
    const float* ff_w2  = (const float*)d_in[17];
    const float* ff_b2  = (const float*)d_in[18];
    const float* pre_w1 = (const float*)d_in[19];
    const float* pre_b1 = (const float*)d_in[20];
    const float* pre_w2 = (const float*)d_in[21];
    const float* pre_b2 = (const float*)d_in[22];
    float* out = (float*)d_out;

    static bool attr_done = false;
    if (!attr_done) {
        cudaFuncSetAttribute(tgemmA<0,2>, cudaFuncAttributeMaxDynamicSharedMemorySize, 98304);
        cudaFuncSetAttribute(tgemmA<2,1>, cudaFuncAttributeMaxDynamicSharedMemorySize, 49152);
        cudaFuncSetAttribute(tgemmA<3,2>, cudaFuncAttributeMaxDynamicSharedMemorySize, 98304);
        cudaFuncSetAttribute(tgemmA<4,2>, cudaFuncAttributeMaxDynamicSharedMemorySize, 98304);
        cudaFuncSetAttribute(tgemmA<5,2>, cudaFuncAttributeMaxDynamicSharedMemorySize, 98304);
        cudaFuncSetAttribute(tgemmC, cudaFuncAttributeMaxDynamicSharedMemorySize, 98304);
        attr_done = true;
    }

    __half *p, *lnb, *att, *ff, *hh, *wlt, *wqkv, *woh, *wf1, *wf2, *wp1, *qkvh;
    float *h;
    cudaGetSymbolAddress((void**)&p, g_p);       cudaGetSymbolAddress((void**)&h, g_h);
    cudaGetSymbolAddress((void**)&lnb, g_ln);    cudaGetSymbolAddress((void**)&qkvh, g_qkv);
    cudaGetSymbolAddress((void**)&att, g_att);   cudaGetSymbolAddress((void**)&ff, g_ff);
    cudaGetSymbolAddress((void**)&hh, g_hh);     cudaGetSymbolAddress((void**)&wlt, g_wlt);
    cudaGetSymbolAddress((void**)&wqkv, g_wqkv); cudaGetSymbolAddress((void**)&woh, g_wo);
    cudaGetSymbolAddress((void**)&wf1, g_wf1);   cudaGetSymbolAddress((void**)&wf2, g_wf2);
    cudaGetSymbolAddress((void**)&wp1, g_wp1);

    const int M = MROWS;
    dim3 gA(1, MTILES);

    prep_all<<<(PREP_TOTAL + 255) / 256, 256>>>(lt_w, wq, wk, wv, wo, ff_w1, ff_w2, pre_w1,
                                                wlt, wqkv, woh, wf1, wf2, wp1);
    conv_k<<<(MROWS * 64 + 255) / 256, 256>>>(x, conv_w, conv_b, p);
    tgemmA<2,1><<<gA, 256, 49152>>>(p, wlt, lt_b, nullptr, pos, nullptr,
                                    h, nullptr, ln1_s, ln1_b, lnb, M, 128, 1);

    for (int i = 0; i < NLAYER; i++) {
        tgemmA<0,2><<<gA, 256, 98304>>>(lnb, wqkv + (long)i * 49152,
            nullptr, nullptr, nullptr, nullptr, nullptr, qkvh,
            nullptr, nullptr, nullptr, M, 384, 3);
        attn_k<<<dim3(S1, BATCH * HEADS), 256>>>(qkvh, att);
        tgemmA<3,2><<<gA, 256, 98304>>>(att, woh + (long)i * 16384,
            wo_b + i * 128, h, nullptr, nullptr, h, nullptr,
            ln2_s + i * 128, ln2_b + i * 128, lnb, M, 128, 1);
        tgemmA<4,2><<<gA, 256, 98304>>>(lnb, wf1 + (long)i * 65536,
            ff_b1 + i * 512, nullptr, nullptr, nullptr, nullptr, ff,
            nullptr, nullptr, nullptr, M, 512, 4);
        bool last = (i == NLAYER - 1);
        tgemmC<<<dim3(1, MTILES), 256, 98304>>>(ff, wf2 + (long)i * 65536,
            ff_b2 + i * 128, h, h,
            last ? nullptr : ln1_s + (i + 1) * 128,
            last ? nullptr : ln1_b + (i + 1) * 128,
            last ? hh : lnb, M, 128, 512);
    }

    tgemmA<5,2><<<gA, 256, 98304>>>(hh, wp1, pre_b1, nullptr, pre_b2, pre_w2,
                                    out, nullptr, nullptr, nullptr, nullptr, M, 128, 1);
}

// round 11
// speedup vs baseline: 2.9876x; 1.0398x over previous
#include <cuda_runtime.h>
#include <cuda_fp16.h>
#include <cstdint>
#include <math.h>

#define BATCH 16
#define S1 61
#define SEQ 3721
#define DMODEL 128
#define HEADS 8
#define DH 16
#define NLAYER 4
#define FFDIM 512
#define PCH 49
#define MROWS (BATCH * SEQ) // 59536
#define MTILES ((MROWS + 127) / 128) // 466

// ---------------------------------------------------------------- scratch
__device__ __half g_p[MROWS * 64];
__device__ float  g_h[MROWS * 128];
__device__ __half g_ln[MROWS * 128];
__device__ __half g_qkv[(size_t)MROWS * 384];
__device__ __half g_att[MROWS * 128];
__device__ __half g_ff[(size_t)MROWS * 512];
__device__ __half g_hh[MROWS * 128];
__device__ __half g_wlt[128 * 64];
__device__ __half g_wqkv[NLAYER * 384 * 128];
__device__ __half g_wo[NLAYER * 128 * 128];
__device__ __half g_wf1[NLAYER * 512 * 128];
__device__ __half g_wf2[NLAYER * 128 * 512];
__device__ __half g_wp1[128 * 128];

// ---------------------------------------------------------------- helpers
__device__ __forceinline__ uint32_t smem_u32(const void* p) {
    uint32_t a;
    asm("{ .reg .u64 t; cvta.to.shared.u64 t, %1; cvt.u32.u64 %0, t; }" : "=r"(a) : "l"(p));
    return a;
}
__device__ __forceinline__ void ldsm4(uint32_t* r, uint32_t addr) {
    asm volatile("ldmatrix.sync.aligned.m8n8.x4.shared.b16 {%0,%1,%2,%3}, [%4];"
                 : "=r"(r[0]), "=r"(r[1]), "=r"(r[2]), "=r"(r[3]) : "r"(addr));
}
__device__ __forceinline__ void ldsm4t(uint32_t* r, uint32_t addr) {
    asm volatile("ldmatrix.sync.aligned.m8n8.x4.trans.shared.b16 {%0,%1,%2,%3}, [%4];"
                 : "=r"(r[0]), "=r"(r[1]), "=r"(r[2]), "=r"(r[3]) : "r"(addr));
}
__device__ __forceinline__ void mma16816(float* c, const uint32_t* a, uint32_t b0, uint32_t b1) {
    asm volatile("mma.sync.aligned.m16n8k16.row.col.f32.f16.f16.f32 "
                 "{%0,%1,%2,%3}, {%4,%5,%6,%7}, {%8,%9}, {%0,%1,%2,%3};"
                 : "+f"(c[0]), "+f"(c[1]), "+f"(c[2]), "+f"(c[3])
                 : "r"(a[0]), "r"(a[1]), "r"(a[2]), "r"(a[3]), "r"(b0), "r"(b1));
}
__device__ __forceinline__ void cpasync16(uint32_t saddr, const void* g, uint32_t ssz) {
    asm volatile("cp.async.cg.shared.global [%0], [%1], 16, %2;"
                 :: "r"(saddr), "l"(g), "r"(ssz));
}
#define CP_COMMIT() asm volatile("cp.async.commit_group;" ::: "memory")
#define CP_WAIT(n)  asm volatile("cp.async.wait_group %0;" :: "n"(n) : "memory")

// ------------------------------------------- single fused weight prep --------
__global__ void prep_all(const float* __restrict__ lt_w, const float* __restrict__ wq,
                         const float* __restrict__ wk, const float* __restrict__ wv,
                         const float* __restrict__ wo, const float* __restrict__ ff_w1,
                         const float* __restrict__ ff_w2, const float* __restrict__ pre_w1,
                         __half* __restrict__ wlt, __half* __restrict__ wqkv,
                         __half* __restrict__ woh, __half* __restrict__ wf1,
                         __half* __restrict__ wf2, __half* __restrict__ wp1) {
    long t = (long)blockIdx.x * blockDim.x + threadIdx.x;
    if (t < 8192) {
        int n = (int)(t >> 6), kk = (int)(t & 63);
        wlt[t] = __float2half(kk < 49 ? lt_w[kk * 128 + n] : 0.f);
        return;
    }
    t -= 8192;
    if (t < 196608) {
        int l = (int)(t / 49152), r = (int)(t % 49152);
        int n = r >> 7, kk = r & 127;
        int s = n >> 7, nn = n & 127;
        const float* W = (s == 0 ? wq : s == 1 ? wk : wv) + (long)l * 16384;
        wqkv[t] = __float2half(W[kk * 128 + nn]);
        return;
    }
    t -= 196608;
    if (t < 65536) {
        int l = (int)(t / 16384), r = (int)(t % 16384);
        int n = r >> 7, kk = r & 127;
        woh[t] = __float2half(wo[(long)l * 16384 + kk * 128 + n]);
        return;
    }
    t -= 65536;
    if (t < 262144) {
        int l = (int)(t / 65536), r = (int)(t % 65536);
        int n = r >> 7, kk = r & 127;
        wf1[t] = __float2half(ff_w1[(long)l * 65536 + (long)kk * 512 + n]);
        return;
    }
    t -= 262144;
    if (t < 262144) {
        int l = (int)(t / 65536), r = (int)(t % 65536);
        int n = r / 512, kk = r % 512;
        wf2[t] = __float2half(ff_w2[(long)l * 65536 + (long)kk * 128 + n]);
        return;
    }
    t -= 262144;
    if (t < 16384) {
        int n = (int)(t >> 7), kk = (int)(t & 127);
        wp1[t] = __float2half(pre_w1[kk * 128 + n]);
    }
}
#define PREP_TOTAL (8192 + 196608 + 65536 + 262144 + 262144 + 16384)

// ---------------- conv 7x7 'same' + relu -> fp16 [M,64] ----------------------
__global__ void conv_k(const float* __restrict__ x, const float* __restrict__ cw,
                       const float* __restrict__ cb, __half* __restrict__ p) {
    int t = blockIdx.x * blockDim.x + threadIdx.x;
    if (t >= MROWS * 64) return;
    int o = t & 63;
    float sum = 0.f;
    if (o < PCH) {
        int s = (t >> 6) % SEQ;
        int b = (t >> 6) / SEQ;
        int y = s / S1, xx = s % S1;
        const float* xb = x + (long)b * SEQ;
        const float* wo = cw + o * 49;
        sum = cb[o];
#pragma unroll
        for (int dy = 0; dy < 7; dy++) {
            int iy = y + dy - 3;
            if (iy < 0 || iy >= S1) continue;
#pragma unroll
            for (int dx = 0; dx < 7; dx++) {
                int ix = xx + dx - 3;
                if (ix < 0 || ix >= S1) continue;
                sum += xb[iy * S1 + ix] * wo[dy * 7 + dx];
            }
        }
        sum = fmaxf(sum, 0.f);
    }
    p[t] = __float2half(sum);
}

// =============== A-resident fp16 GEMM (K<=128), n-tile = blockIdx.x ==========
// EPI: 0 -> fp16 Ch; 2 +bias+pos -> fp32 C (+LN->lnout);
//      3 +bias+res -> fp32 C (+LN->lnout); 4 gelu(+bias)->fp16 Ch; 5 head
template <int EPI, int NK>
__global__ void __launch_bounds__(256, 2)
tgemmA(const __half* __restrict__ A, const __half* __restrict__ B,
       const float* __restrict__ bias, const float* __restrict__ res,
       const float* __restrict__ pos, const float* __restrict__ w2,
       float* __restrict__ C, __half* __restrict__ Ch,
       const float* __restrict__ lnsc, const float* __restrict__ lnbi,
       __half* __restrict__ lnout, int M, int Nfull) {
    extern __shared__ char sm[];
    __shared__ float red[2][128];
    __shared__ float lnred[2][128][2];
    uint32_t sb = smem_u32(sm);
    const int K = NK * 64;
    const uint32_t ABYTES = (uint32_t)NK * 16384u;
    int tid = threadIdx.x;
    int w = tid >> 5, lane = tid & 31;
    int wm = w & 3, wn = w >> 2;
    int m0 = blockIdx.y * 128;
    int nt = blockIdx.x;

    int rA[2], rB[4];
#pragma unroll
    for (int mi = 0; mi < 2; mi++) rA[mi] = wm * 32 + mi * 16 + (lane & 15);
#pragma unroll
    for (int ng = 0; ng < 4; ng++)
        rB[ng] = wn * 64 + ng * 16 + ((lane >> 4) << 3) + (lane & 7);
    int cA = lane >> 4;
    int cB = (lane >> 3) & 1;

    // load A once
#pragma unroll
    for (int t = 0; t < NK * 4; t++) {
        int slot = t * 256 + tid;
        int tile = slot >> 10;
        int idx = slot & 1023;
        int row = idx >> 3, c16 = idx & 7;
        long grow = m0 + row;
        bool ok = grow < M;
        if (!ok) grow = 0;
        cpasync16(sb + (uint32_t)tile * 16384u + row * 128 + (((uint32_t)c16 ^ (row & 7)) << 4),
                  A + grow * K + tile * 64 + c16 * 8, ok ? 16u : 0u);
    }
    // load B tile for this block's n-slice
#pragma unroll
    for (int t = 0; t < NK * 4; t++) {
        int slot = t * 256 + tid;
        int tile = slot >> 10;
        int idx = slot & 1023;
        int row = idx >> 3, c16 = idx & 7;
        long grow = (long)(nt * 128 + row);
        cpasync16(sb + ABYTES + (uint32_t)tile * 16384u + row * 128 +
                      (((uint32_t)c16 ^ (row & 7)) << 4),
                  B + grow * K + tile * 64 + c16 * 8, 16u);
    }
    CP_COMMIT();
    CP_WAIT(0);
    __syncthreads();

    float acc[2][8][4];
#pragma unroll
    for (int i = 0; i < 2; i++)
#pragma unroll
        for (int j = 0; j < 8; j++)
#pragma unroll
            for (int q = 0; q < 4; q++) acc[i][j][q] = 0.f;

#pragma unroll
    for (int i = 0; i < NK * 4; i++) {
        int chunk = i >> 2, ks = i & 3, kc = ks * 2;
        uint32_t Ab = sb + (uint32_t)chunk * 16384u;
        uint32_t Bb = sb + ABYTES + (uint32_t)chunk * 16384u;
        uint32_t fa[2][4], fb[4][4];
#pragma unroll
        for (int mi = 0; mi < 2; mi++) {
            int row = rA[mi];
            ldsm4(fa[mi], Ab + row * 128 + ((((uint32_t)(kc + cA)) ^ (row & 7)) << 4));
        }
#pragma unroll
        for (int ng = 0; ng < 4; ng++) {
            int row = rB[ng];
            ldsm4(fb[ng], Bb + row * 128 + ((((uint32_t)(kc + cB)) ^ (row & 7)) << 4));
        }
#pragma unroll
        for (int ng = 0; ng < 4; ng++)
#pragma unroll
            for (int mi = 0; mi < 2; mi++) {
                mma16816(acc[mi][ng * 2],     fa[mi], fb[ng][0], fb[ng][1]);
                mma16816(acc[mi][ng * 2 + 1], fa[mi], fb[ng][2], fb[ng][3]);
            }
    }
    __syncthreads();

    int n0 = nt * 128;
    int tg = lane >> 2;
    int tc = (lane & 3) * 2;

    if (EPI == 5) {
        float p[2][2] = {};
#pragma unroll
        for (int mi = 0; mi < 2; mi++)
#pragma unroll
            for (int ni = 0; ni < 8; ni++) {
                int col = wn * 64 + ni * 8 + tc;
                float b0 = bias[col], b1 = bias[col + 1];
                float w20 = w2[col], w21 = w2[col + 1];
                p[mi][0] += fmaxf(acc[mi][ni][0] + b0, 0.f) * w20 +
                            fmaxf(acc[mi][ni][1] + b1, 0.f) * w21;
                p[mi][1] += fmaxf(acc[mi][ni][2] + b0, 0.f) * w20 +
                            fmaxf(acc[mi][ni][3] + b1, 0.f) * w21;
            }
#pragma unroll
        for (int mi = 0; mi < 2; mi++)
#pragma unroll
            for (int hf = 0; hf < 2; hf++) {
                float v = p[mi][hf];
                v += __shfl_xor_sync(~0u, v, 1);
                v += __shfl_xor_sync(~0u, v, 2);
                if ((lane & 3) == 0) red[wn][wm * 32 + mi * 16 + hf * 8 + tg] = v;
            }
        __syncthreads();
        if (tid < 128) {
            int row = m0 + tid;
            if (row < M) C[row] = red[0][tid] + red[1][tid] + pos[0];
        }
        return;
    }

    if (EPI == 0 || EPI == 4) {
#pragma unroll
        for (int mi = 0; mi < 2; mi++)
#pragma unroll
            for (int hf = 0; hf < 2; hf++) {
                int row = m0 + wm * 32 + mi * 16 + hf * 8 + tg;
                if (row >= M) continue;
#pragma unroll
                for (int ni = 0; ni < 8; ni++) {
                    int col = n0 + wn * 64 + ni * 8 + tc;
                    float v0 = acc[mi][ni][hf * 2 + 0];
                    float v1 = acc[mi][ni][hf * 2 + 1];
                    if (EPI == 4) {
                        v0 += bias[col];
                        v1 += bias[col + 1];
                        v0 = 0.5f * v0 * (1.f + erff(v0 * 0.70710678118654752f));
                        v1 = 0.5f * v1 * (1.f + erff(v1 * 0.70710678118654752f));
                    }
                    __half hl[2] = {__float2half(v0), __float2half(v1)};
                    *(uint32_t*)&Ch[(long)row * Nfull + col] = *(uint32_t*)hl;
                }
            }
        return;
    }

    // EPI 2/3: finalize, fp32 C, LN stats + normalized fp16 out
    float s1[2][2] = {}, s2[2][2] = {};
#pragma unroll
    for (int mi = 0; mi < 2; mi++)
#pragma unroll
        for (int hf = 0; hf < 2; hf++) {
            int row = m0 + wm * 32 + mi * 16 + hf * 8 + tg;
            bool rok = row < M;
            long pr = (EPI == 2 && rok) ? (long)(row % SEQ) * 128 : 0;
#pragma unroll
            for (int ni = 0; ni < 8; ni++) {
                int col = n0 + wn * 64 + ni * 8 + tc;
                float v0 = acc[mi][ni][hf * 2 + 0] + bias[col];
                float v1 = acc[mi][ni][hf * 2 + 1] + bias[col + 1];
                if (rok) {
                    if (EPI == 2) {
                        v0 += pos[pr + col];
                        v1 += pos[pr + col + 1];
                    } else {
                        v0 += res[(long)row * Nfull + col];
                        v1 += res[(long)row * Nfull + col + 1];
                    }
                    *(float2*)&C[(long)row * Nfull + col] = make_float2(v0, v1);
                }
                acc[mi][ni][hf * 2 + 0] = v0;
                acc[mi][ni][hf * 2 + 1] = v1;
                s1[mi][hf] += v0 + v1;
                s2[mi][hf] += v0 * v0 + v1 * v1;
            }
        }
    if (lnout) {
#pragma unroll
        for (int mi = 0; mi < 2; mi++)
#pragma unroll
            for (int hf = 0; hf < 2; hf++) {
                float a = s1[mi][hf], b = s2[mi][hf];
                a += __shfl_xor_sync(~0u, a, 1);
                a += __shfl_xor_sync(~0u, a, 2);
                b += __shfl_xor_sync(~0u, b, 1);
                b += __shfl_xor_sync(~0u, b, 2);
                if ((lane & 3) == 0) {
                    int ri = wm * 32 + mi * 16 + hf * 8 + tg;
                    lnred[wn][ri][0] = a;
                    lnred[wn][ri][1] = b;
                }
            }
        __syncthreads();
#pragma unroll
        for (int mi = 0; mi < 2; mi++)
#pragma unroll
            for (int hf = 0; hf < 2; hf++) {
                int ri = wm * 32 + mi * 16 + hf * 8 + tg;
                int row = m0 + ri;
                if (row >= M) continue;
                float m1 = (lnred[0][ri][0] + lnred[1][ri][0]) * (1.f / 128.f);
                float m2 = (lnred[0][ri][1] + lnred[1][ri][1]) * (1.f / 128.f);
                float inv = rsqrtf(m2 - m1 * m1 + 1e-5f);
#pragma unroll
                for (int ni = 0; ni < 8; ni++) {
                    int col = wn * 64 + ni * 8 + tc;
                    float v0 = (acc[mi][ni][hf * 2 + 0] - m1) * inv * lnsc[col] + lnbi[col];
                    float v1 = (acc[mi][ni][hf * 2 + 1] - m1) * inv * lnsc[col + 1] + lnbi[col + 1];
                    __half hl[2] = {__float2half(v0), __float2half(v1)};
                    *(uint32_t*)&lnout[(long)row * 128 + col] = *(uint32_t*)hl;
                }
            }
    }
}

// =============== chunked fp16 GEMM for K=512 (ff2) + fused LN/out ============
#define CSTAGE_B 32768u

__global__ void __launch_bounds__(256, 2)
tgemmC(const __half* __restrict__ A, const __half* __restrict__ B,
       const float* __restrict__ bias, const float* __restrict__ res,
       float* __restrict__ C, const float* __restrict__ lnsc,
       const float* __restrict__ lnbi, __half* __restrict__ lnout,
       int M, int N, int K) {
    extern __shared__ char sm[];
    __shared__ float lnred[2][128][2];
    uint32_t sb = smem_u32(sm);
    int tid = threadIdx.x;
    int w = tid >> 5, lane = tid & 31;
    int wm = w & 3, wn = w >> 2;
    int m0 = blockIdx.y * 128, n0 = blockIdx.x * 128;
    int nk = K >> 6;

    float acc[2][8][4];
#pragma unroll
    for (int i = 0; i < 2; i++)
#pragma unroll
        for (int j = 0; j < 8; j++)
#pragma unroll
            for (int q = 0; q < 4; q++) acc[i][j][q] = 0.f;

    int rA[2], rB[4];
#pragma unroll
    for (int mi = 0; mi < 2; mi++) rA[mi] = wm * 32 + mi * 16 + (lane & 15);
#pragma unroll
    for (int ng = 0; ng < 4; ng++)
        rB[ng] = wn * 64 + ng * 16 + ((lane >> 4) << 3) + (lane & 7);
    int cA = lane >> 4;
    int cB = (lane >> 3) & 1;

    auto load_stage = [&](int c, int buf) {
#pragma unroll
        for (int it = 0; it < 8; it++) {
            int slot = it * 256 + tid;
            int t = it >> 2;
            int row = (slot >> 3) & 127;
            int chunk = slot & 7;
            const __half* src = t ? B : A;
            long grow = t ? (long)(n0 + row) : (long)(m0 + row);
            bool ok = t ? true : (m0 + row < M);
            if (!ok) grow = 0;
            const void* g = (const void*)(src + grow * K + ((long)c << 6) + chunk * 8);
            uint32_t saddr = sb + buf * CSTAGE_B + (uint32_t)t * 16384u + row * 128 +
                             ((chunk ^ (row & 7)) << 4);
            cpasync16(saddr, g, ok ? 16u : 0u);
        }
        CP_COMMIT();
    };

#pragma unroll
    for (int p = 0; p < 2; p++) load_stage(p, p);

    for (int c = 0; c < nk; c++) {
        int nxt = c + 2;
        if (nxt < nk) load_stage(nxt, nxt % 3);
        int allow = (nxt < nk ? nxt : nk - 1) - c;
        if (allow >= 2) CP_WAIT(2);
        else if (allow == 1) CP_WAIT(1);
        else CP_WAIT(0);
        __syncthreads();

        uint32_t st = sb + (c % 3) * CSTAGE_B;
#pragma unroll
        for (int ks = 0; ks < 4; ks++) {
            int kc = ks * 2;
            uint32_t fa[2][4], fb[4][4];
#pragma unroll
            for (int mi = 0; mi < 2; mi++) {
                int row = rA[mi];
                ldsm4(fa[mi], st + row * 128 + ((((uint32_t)(kc + cA)) ^ (row & 7)) << 4));
            }
#pragma unroll
            for (int ng = 0; ng < 4; ng++) {
                int row = rB[ng];
                ldsm4(fb[ng], st + 16384u + row * 128 + ((((uint32_t)(kc + cB)) ^ (row & 7)) << 4));
            }
#pragma unroll
            for (int ng = 0; ng < 4; ng++)
#pragma unroll
                for (int mi = 0; mi < 2; mi++) {
                    mma16816(acc[mi][ng * 2],     fa[mi], fb[ng][0], fb[ng][1]);
                    mma16816(acc[mi][ng * 2 + 1], fa[mi], fb[ng][2], fb[ng][3]);
                }
        }
        __syncthreads();
    }

    int tg = lane >> 2;
    int tc = (lane & 3) * 2;
    float s1[2][2] = {}, s2[2][2] = {};
#pragma unroll
    for (int mi = 0; mi < 2; mi++)
#pragma unroll
        for (int hf = 0; hf < 2; hf++) {
            int row = m0 + wm * 32 + mi * 16 + hf * 8 + tg;
            bool rok = row < M;
#pragma unroll
            for (int ni = 0; ni < 8; ni++) {
                int col = n0 + wn * 64 + ni * 8 + tc;
                float v0 = acc[mi][ni][hf * 2 + 0] + bias[col];
                float v1 = acc[mi][ni][hf * 2 + 1] + bias[col + 1];
                if (rok) {
                    v0 += res[(long)row * N + col];
                    v1 += res[(long)row * N + col + 1];
                    *(float2*)&C[(long)row * N + col] = make_float2(v0, v1);
                }
                acc[mi][ni][hf * 2 + 0] = v0;
                acc[mi][ni][hf * 2 + 1] = v1;
                s1[mi][hf] += v0 + v1;
                s2[mi][hf] += v0 * v0 + v1 * v1;
            }
        }
    if (lnout && lnsc) {
#pragma unroll
        for (int mi = 0; mi < 2; mi++)
#pragma unroll
            for (int hf = 0; hf < 2; hf++) {
                float a = s1[mi][hf], b = s2[mi][hf];
                a += __shfl_xor_sync(~0u, a, 1);
                a += __shfl_xor_sync(~0u, a, 2);
                b += __shfl_xor_sync(~0u, b, 1);
                b += __shfl_xor_sync(~0u, b, 2);
                if ((lane & 3) == 0) {
                    int ri = wm * 32 + mi * 16 + hf * 8 + tg;
                    lnred[wn][ri][0] = a;
                    lnred[wn][ri][1] = b;
                }
            }
        __syncthreads();
#pragma unroll
        for (int mi = 0; mi < 2; mi++)
#pragma unroll
            for (int hf = 0; hf < 2; hf++) {
                int ri = wm * 32 + mi * 16 + hf * 8 + tg;
                int row = m0 + ri;
                if (row >= M) continue;
                float m1 = (lnred[0][ri][0] + lnred[1][ri][0]) * (1.f / 128.f);
                float m2 = (lnred[0][ri][1] + lnred[1][ri][1]) * (1.f / 128.f);
                float inv = rsqrtf(m2 - m1 * m1 + 1e-5f);
#pragma unroll
                for (int ni = 0; ni < 8; ni++) {
                    int col = wn * 64 + ni * 8 + tc;
                    float v0 = (acc[mi][ni][hf * 2 + 0] - m1) * inv * lnsc[col] + lnbi[col];
                    float v1 = (acc[mi][ni][hf * 2 + 1] - m1) * inv * lnsc[col + 1] + lnbi[col + 1];
                    __half hl[2] = {__float2half(v0), __float2half(v1)};
                    *(uint32_t*)&lnout[(long)row * 128 + col] = *(uint32_t*)hl;
                }
            }
    } else if (lnout) {
#pragma unroll
        for (int mi = 0; mi < 2; mi++)
#pragma unroll
            for (int hf = 0; hf < 2; hf++) {
                int row = m0 + wm * 32 + mi * 16 + hf * 8 + tg;
                if (row >= M) continue;
#pragma unroll
                for (int ni = 0; ni < 8; ni++) {
                    int col = n0 + wn * 64 + ni * 8 + tc;
                    __half hl[2] = {__float2half(acc[mi][ni][hf * 2 + 0]),
                                    __float2half(acc[mi][ni][hf * 2 + 1])};
                    *(uint32_t*)&lnout[(long)row * 128 + col] = *(uint32_t*)hl;
                }
            }
    }
}

// ---------------- MMA local windowed attention --------------------------------
__global__ void __launch_bounds__(256, 2)
attn_k(const __half* __restrict__ qkv, __half* __restrict__ o) {
    __shared__ __half q_s[64 * 24];
    __shared__ __half k_s[192 * 24];
    __shared__ __half v_s[192 * 24];
    __shared__ float ms_s[2][4][16];
    __shared__ float ls_s[2][4][16];
    __shared__ float osum[2][4][16][16];
    int w = blockIdx.x, bh = blockIdx.y;
    int b = bh >> 3, h = bh & 7;
    int tid = threadIdx.x, warp = tid >> 5, lane = tid & 31;
    int wm = warp & 3, wn = warp >> 2;
    int jstart = (w > 0) ? 0 : S1;
    int jend = (w < S1 - 1) ? 3 * S1 : 2 * S1;
    int cnt = jend - jstart;
    long rb = (long)b * SEQ;
    const uint4* qg = (const uint4*)qkv;

    int total = S1 + 2 * cnt;
    for (int idx = tid; idx < total; idx += 256) {
        if (idx < S1) {
            long grow = (rb + (long)w * S1 + idx) * 48 + h * 2;
            uint4 a = qg[grow], c = qg[grow + 1];
            *(uint4*)&q_s[idx * 24] = a;
            *(uint4*)&q_s[idx * 24 + 8] = c;
        } else {
            int r = idx - S1;
            int which = (r >= cnt);
            int jl = which ? r - cnt : r;
            long grow = (rb + (long)(w - 1) * S1 + jstart + jl) * 48 + h * 2 + (which ? 32 : 16);
            uint4 a = qg[grow], c = qg[grow + 1];
            __half* dst = (which ? v_s : k_s) + jl * 24;
            *(uint4*)dst = a;
            *(uint4*)&dst[8] = c;
        }
    }
    if (tid < 9) *(uint4*)&q_s[61 * 24 + tid * 8] = make_uint4(0, 0, 0, 0);
    for (int r = cnt + tid; r < 192; r += 256) {
        uint4 z = make_uint4(0, 0, 0, 0);
        *(uint4*)&k_s[r * 24] = z;
        *(uint4*)&k_s[r * 24 + 8] = z;
        *(uint4*)&v_s[r * 24] = z;
        *(uint4*)&v_s[r * 24 + 8] = z;
    }
    __syncthreads();

    uint32_t qb = smem_u32(q_s), kbb = smem_u32(k_s), vbb = smem_u32(v_s);

    uint32_t a[4];
    ldsm4(a, qb + (uint32_t)(wm * 16 + ((lane >> 3) & 1) * 8 + (lane & 7)) * 48 + (lane >> 4) * 16);

    float s[12][4];
#pragma unroll
    for (int ti = 0; ti < 12; ti++)
#pragma unroll
        for (int e = 0; e < 4; e++) s[ti][e] = 0.f;
#pragma unroll
    for (int g = 0; g < 6; g++) {
        uint32_t r[4];
        ldsm4(r, kbb + (uint32_t)(wn * 96 + g * 16 + (lane >> 4) * 8 + (lane & 7)) * 48 +
                   ((lane >> 3) & 1) * 16);
        mma16816(s[g * 2],     a, r[0], r[1]);
        mma16816(s[g * 2 + 1], a, r[2], r[3]);
    }

    float mloc[2] = {-1e30f, -1e30f};
#pragma unroll
    for (int ti = 0; ti < 12; ti++) {
        int cbase = wn * 96 + ti * 8 + (lane & 3) * 2;
#pragma unroll
        for (int e = 0; e < 4; e++) {
            int col = cbase + (e & 1);
            float v = (col < cnt) ? s[ti][e] * 0.25f : -1e30f;
            s[ti][e] = v;
            mloc[e >> 1] = fmaxf(mloc[e >> 1], v);
        }
    }
#pragma unroll
    for (int i = 0; i < 2; i++) {
        mloc[i] = fmaxf(mloc[i], __shfl_xor_sync(~0u, mloc[i], 1));
        mloc[i] = fmaxf(mloc[i], __shfl_xor_sync(~0u, mloc[i], 2));
    }
    if ((lane & 3) == 0) {
        ms_s[wn][wm][lane >> 2] = mloc[0];
        ms_s[wn][wm][(lane >> 2) + 8] = mloc[1];
    }
    __syncthreads();
    float m0 = fmaxf(ms_s[0][wm][lane >> 2], ms_s[1][wm][lane >> 2]);
    float m1 = fmaxf(ms_s[0][wm][(lane >> 2) + 8], ms_s[1][wm][(lane >> 2) + 8]);

    float lloc[2] = {0.f, 0.f};
    uint32_t ph[12][2];
#pragma unroll
    for (int ti = 0; ti < 12; ti++) {
        float p0 = __expf(s[ti][0] - m0);
        float p1 = __expf(s[ti][1] - m0);
        float p2 = __expf(s[ti][2] - m1);
        float p3 = __expf(s[ti][3] - m1);
        lloc[0] += p0 + p1;
        lloc[1] += p2 + p3;
        __half2 h01 = __floats2half2_rn(p0, p1);
        __half2 h23 = __floats2half2_rn(p2, p3);
        ph[ti][0] = *(uint32_t*)&h01;
        ph[ti][1] = *(uint32_t*)&h23;
    }
#pragma unroll
    for (int i = 0; i < 2; i++) {
        lloc[i] += __shfl_xor_sync(~0u, lloc[i], 1);
        lloc[i] += __shfl_xor_sync(~0u, lloc[i], 2);
    }
    if ((lane & 3) == 0) {
        ls_s[wn][wm][lane >> 2] = lloc[0];
        ls_s[wn][wm][(lane >> 2) + 8] = lloc[1];
    }

    float oa[2][4] = {{0.f, 0.f, 0.f, 0.f}, {0.f, 0.f, 0.f, 0.f}};
#pragma unroll
    for (int g = 0; g < 6; g++) {
        uint32_t r[4];
        ldsm4t(r, vbb + (uint32_t)(wn * 96 + g * 16 + ((lane >> 3) & 1) * 8 + (lane & 7)) * 48 +
                    (lane >> 4) * 16);
        uint32_t pa[4] = {ph[g * 2][0], ph[g * 2][1], ph[g * 2 + 1][0], ph[g * 2 + 1][1]};
        mma16816(oa[0], pa, r[0], r[1]);
        mma16816(oa[1], pa, r[2], r[3]);
    }
    {
        int rl = lane >> 2, cc = (lane & 3) * 2;
        *(float2*)&osum[wn][wm][rl][cc]         = make_float2(oa[0][0], oa[0][1]);
        *(float2*)&osum[wn][wm][rl + 8][cc]     = make_float2(oa[0][2], oa[0][3]);
        *(float2*)&osum[wn][wm][rl][cc + 8]     = make_float2(oa[1][0], oa[1][1]);
        *(float2*)&osum[wn][wm][rl + 8][cc + 8] = make_float2(oa[1][2], oa[1][3]);
    }
    __syncthreads();

    for (int idx = tid; idx < S1 * 16; idx += 256) {
        int i = idx >> 4, d = idx & 15;
        int wmq = i >> 4, rl = i & 15;
        float val = osum[0][wmq][rl][d] + osum[1][wmq][rl][d];
        float l = ls_s[0][wmq][rl] + ls_s[1][wmq][rl];
        o[(rb + (long)w * S1 + i) * 128 + h * 16 + d] = __float2half(val / l);
    }
}

// ---------------- launch ------------------------------------------------------
extern "C" void kernel_launch(void* const* d_in, const int* in_sizes, int n_in,
                              void* d_out, int out_size) {
    const float* x      = (const float*)d_in[0];
    const float* conv_w = (const float*)d_in[1];
    const float* conv_b = (const float*)d_in[2];
    const float* lt_w   = (const float*)d_in[3];
    const float* lt_b   = (const float*)d_in[4];
    const float* pos    = (const float*)d_in[5];
    const float* ln1_s  = (const float*)d_in[6];
    const float* ln1_b  = (const float*)d_in[7];
    const float* wq     = (const float*)d_in[8];
    const float* wk     = (const float*)d_in[9];
    const float* wv     = (const float*)d_in[10];
    const float* wo     = (const float*)d_in[11];
    const float* wo_b   = (const float*)d_in[12];
    const float* ln2_s  = (const float*)d_in[13];
    const float* ln2_b  = (const float*)d_in[14];
    const float* ff_w1  = (const float*)d_in[15];
    const float* ff_b1  = (const float*)d_in[16];
    const float* ff_w2  = (const float*)d_in[17];
    const float* ff_b2  = (const float*)d_in[18];
    const float* pre_w1 = (const float*)d_in[19];
    const float* pre_b1 = (const float*)d_in[20];
    const float* pre_w2 = (const float*)d_in[21];
    const float* pre_b2 = (const float*)d_in[22];
    float* out = (float*)d_out;

    static bool attr_done = false;
    if (!attr_done) {
        cudaFuncSetAttribute(tgemmA<0,2>, cudaFuncAttributeMaxDynamicSharedMemorySize, 65536);
        cudaFuncSetAttribute(tgemmA<2,1>, cudaFuncAttributeMaxDynamicSharedMemorySize, 32768);
        cudaFuncSetAttribute(tgemmA<3,2>, cudaFuncAttributeMaxDynamicSharedMemorySize, 65536);
        cudaFuncSetAttribute(tgemmA<4,2>, cudaFuncAttributeMaxDynamicSharedMemorySize, 65536);
        cudaFuncSetAttribute(tgemmA<5,2>, cudaFuncAttributeMaxDynamicSharedMemorySize, 65536);
        cudaFuncSetAttribute(tgemmC, cudaFuncAttributeMaxDynamicSharedMemorySize, 98304);
        attr_done = true;
    }

    __half *p, *lnb, *att, *ff, *hh, *wlt, *wqkv, *woh, *wf1, *wf2, *wp1, *qkvh;
    float *h;
    cudaGetSymbolAddress((void**)&p, g_p);       cudaGetSymbolAddress((void**)&h, g_h);
    cudaGetSymbolAddress((void**)&lnb, g_ln);    cudaGetSymbolAddress((void**)&qkvh, g_qkv);
    cudaGetSymbolAddress((void**)&att, g_att);   cudaGetSymbolAddress((void**)&ff, g_ff);
    cudaGetSymbolAddress((void**)&hh, g_hh);     cudaGetSymbolAddress((void**)&wlt, g_wlt);
    cudaGetSymbolAddress((void**)&wqkv, g_wqkv); cudaGetSymbolAddress((void**)&woh, g_wo);
    cudaGetSymbolAddress((void**)&wf1, g_wf1);   cudaGetSymbolAddress((void**)&wf2, g_wf2);
    cudaGetSymbolAddress((void**)&wp1, g_wp1);

    const int M = MROWS;

    prep_all<<<(PREP_TOTAL + 255) / 256, 256>>>(lt_w, wq, wk, wv, wo, ff_w1, ff_w2, pre_w1,
                                                wlt, wqkv, woh, wf1, wf2, wp1);
    conv_k<<<(MROWS * 64 + 255) / 256, 256>>>(x, conv_w, conv_b, p);
    tgemmA<2,1><<<dim3(1, MTILES), 256, 32768>>>(p, wlt, lt_b, nullptr, pos, nullptr,
                                                 h, nullptr, ln1_s, ln1_b, lnb, M, 128);

    for (int i = 0; i < NLAYER; i++) {
        tgemmA<0,2><<<dim3(3, MTILES), 256, 65536>>>(lnb, wqkv + (long)i * 49152,
            nullptr, nullptr, nullptr, nullptr, nullptr, qkvh,
            nullptr, nullptr, nullptr, M, 384);
        attn_k<<<dim3(S1, BATCH * HEADS), 256>>>(qkvh, att);
        tgemmA<3,2><<<dim3(1, MTILES), 256, 65536>>>(att, woh + (long)i * 16384,
            wo_b + i * 128, h, nullptr, nullptr, h, nullptr,
            ln2_s + i * 128, ln2_b + i * 128, lnb, M, 128);
        tgemmA<4,2><<<dim3(4, MTILES), 256, 65536>>>(lnb, wf1 + (long)i * 65536,
            ff_b1 + i * 512, nullptr, nullptr, nullptr, nullptr, ff,
            nullptr, nullptr, nullptr, M, 512);
        bool last = (i == NLAYER - 1);
        tgemmC<<<dim3(1, MTILES), 256, 98304>>>(ff, wf2 + (long)i * 65536,
            ff_b2 + i * 128, h, h,
            last ? nullptr : ln1_s + (i + 1) * 128,
            last ? nullptr : ln1_b + (i + 1) * 128,
            last ? hh : lnb, M, 128, 512);
    }

    tgemmA<5,2><<<dim3(1, MTILES), 256, 65536>>>(hh, wp1, pre_b1, nullptr, pre_b2, pre_w2,
                                                 out, nullptr, nullptr, nullptr, nullptr, M, 128);
}

// round 12
// speedup vs baseline: 3.0469x; 1.0198x over previous
#include <cuda_runtime.h>
#include <cuda_fp16.h>
#include <cstdint>
#include <math.h>

#define BATCH 16
#define S1 61
#define SEQ 3721
#define DMODEL 128
#define HEADS 8
#define DH 16
#define NLAYER 4
#define FFDIM 512
#define PCH 49
#define MROWS (BATCH * SEQ) // 59536
#define MTILES ((MROWS + 127) / 128) // 466

// ---------------------------------------------------------------- scratch
__device__ __half g_p[MROWS * 64];
__device__ float  g_h[MROWS * 128];
__device__ __half g_ln[MROWS * 128];
__device__ __half g_qkv[(size_t)MROWS * 384];
__device__ __half g_att[MROWS * 128];
__device__ __half g_ff[(size_t)MROWS * 512];
__device__ __half g_hh[MROWS * 128];
__device__ __half g_wlt[128 * 64];
__device__ __half g_wqkv[NLAYER * 384 * 128];
__device__ __half g_wo[NLAYER * 128 * 128];
__device__ __half g_wf1[NLAYER * 512 * 128];
__device__ __half g_wf2[NLAYER * 128 * 512];
__device__ __half g_wp1[128 * 128];

// ---------------------------------------------------------------- helpers
__device__ __forceinline__ uint32_t smem_u32(const void* p) {
    uint32_t a;
    asm("{ .reg .u64 t; cvta.to.shared.u64 t, %1; cvt.u32.u64 %0, t; }" : "=r"(a) : "l"(p));
    return a;
}
__device__ __forceinline__ void ldsm4(uint32_t* r, uint32_t addr) {
    asm volatile("ldmatrix.sync.aligned.m8n8.x4.shared.b16 {%0,%1,%2,%3}, [%4];"
                 : "=r"(r[0]), "=r"(r[1]), "=r"(r[2]), "=r"(r[3]) : "r"(addr));
}
__device__ __forceinline__ void ldsm4t(uint32_t* r, uint32_t addr) {
    asm volatile("ldmatrix.sync.aligned.m8n8.x4.trans.shared.b16 {%0,%1,%2,%3}, [%4];"
                 : "=r"(r[0]), "=r"(r[1]), "=r"(r[2]), "=r"(r[3]) : "r"(addr));
}
__device__ __forceinline__ void mma16816(float* c, const uint32_t* a, uint32_t b0, uint32_t b1) {
    asm volatile("mma.sync.aligned.m16n8k16.row.col.f32.f16.f16.f32 "
                 "{%0,%1,%2,%3}, {%4,%5,%6,%7}, {%8,%9}, {%0,%1,%2,%3};"
                 : "+f"(c[0]), "+f"(c[1]), "+f"(c[2]), "+f"(c[3])
                 : "r"(a[0]), "r"(a[1]), "r"(a[2]), "r"(a[3]), "r"(b0), "r"(b1));
}
__device__ __forceinline__ void cpasync16(uint32_t saddr, const void* g, uint32_t ssz) {
    asm volatile("cp.async.cg.shared.global [%0], [%1], 16, %2;"
                 :: "r"(saddr), "l"(g), "r"(ssz));
}
#define CP_COMMIT() asm volatile("cp.async.commit_group;" ::: "memory")
#define CP_WAIT(n)  asm volatile("cp.async.wait_group %0;" :: "n"(n) : "memory")

// ------------------------------------------- single fused weight prep --------
__global__ void prep_all(const float* __restrict__ lt_w, const float* __restrict__ wq,
                         const float* __restrict__ wk, const float* __restrict__ wv,
                         const float* __restrict__ wo, const float* __restrict__ ff_w1,
                         const float* __restrict__ ff_w2, const float* __restrict__ pre_w1,
                         __half* __restrict__ wlt, __half* __restrict__ wqkv,
                         __half* __restrict__ woh, __half* __restrict__ wf1,
                         __half* __restrict__ wf2, __half* __restrict__ wp1) {
    long t = (long)blockIdx.x * blockDim.x + threadIdx.x;
    if (t < 8192) {
        int n = (int)(t >> 6), kk = (int)(t & 63);
        wlt[t] = __float2half(kk < 49 ? lt_w[kk * 128 + n] : 0.f);
        return;
    }
    t -= 8192;
    if (t < 196608) {
        int l = (int)(t / 49152), r = (int)(t % 49152);
        int n = r >> 7, kk = r & 127;
        int s = n >> 7, nn = n & 127;
        const float* W = (s == 0 ? wq : s == 1 ? wk : wv) + (long)l * 16384;
        wqkv[t] = __float2half(W[kk * 128 + nn]);
        return;
    }
    t -= 196608;
    if (t < 65536) {
        int l = (int)(t / 16384), r = (int)(t % 16384);
        int n = r >> 7, kk = r & 127;
        woh[t] = __float2half(wo[(long)l * 16384 + kk * 128 + n]);
        return;
    }
    t -= 65536;
    if (t < 262144) {
        int l = (int)(t / 65536), r = (int)(t % 65536);
        int n = r >> 7, kk = r & 127;
        wf1[t] = __float2half(ff_w1[(long)l * 65536 + (long)kk * 512 + n]);
        return;
    }
    t -= 262144;
    if (t < 262144) {
        int l = (int)(t / 65536), r = (int)(t % 65536);
        int n = r / 512, kk = r % 512;
        wf2[t] = __float2half(ff_w2[(long)l * 65536 + (long)kk * 128 + n]);
        return;
    }
    t -= 262144;
    if (t < 16384) {
        int n = (int)(t >> 7), kk = (int)(t & 127);
        wp1[t] = __float2half(pre_w1[kk * 128 + n]);
    }
}
#define PREP_TOTAL (8192 + 196608 + 65536 + 262144 + 262144 + 16384)

// ---------------- conv 7x7 'same' + relu -> fp16 [M,64] ----------------------
__global__ void conv_k(const float* __restrict__ x, const float* __restrict__ cw,
                       const float* __restrict__ cb, __half* __restrict__ p) {
    int t = blockIdx.x * blockDim.x + threadIdx.x;
    if (t >= MROWS * 64) return;
    int o = t & 63;
    float sum = 0.f;
    if (o < PCH) {
        int s = (t >> 6) % SEQ;
        int b = (t >> 6) / SEQ;
        int y = s / S1, xx = s % S1;
        const float* xb = x + (long)b * SEQ;
        const float* wo = cw + o * 49;
        sum = cb[o];
#pragma unroll
        for (int dy = 0; dy < 7; dy++) {
            int iy = y + dy - 3;
            if (iy < 0 || iy >= S1) continue;
#pragma unroll
            for (int dx = 0; dx < 7; dx++) {
                int ix = xx + dx - 3;
                if (ix < 0 || ix >= S1) continue;
                sum += xb[iy * S1 + ix] * wo[dy * 7 + dx];
            }
        }
        sum = fmaxf(sum, 0.f);
    }
    p[t] = __float2half(sum);
}

// =============== A-resident fp16 GEMM (K<=128), n-tile = blockIdx.x ==========
// Chunk-pipelined: per-64-col chunk cp.async groups; compute chunk c while
// chunk c+1 is in flight.
template <int EPI, int NK>
__global__ void __launch_bounds__(256, 2)
tgemmA(const __half* __restrict__ A, const __half* __restrict__ B,
       const float* __restrict__ bias, const float* __restrict__ res,
       const float* __restrict__ pos, const float* __restrict__ w2,
       float* __restrict__ C, __half* __restrict__ Ch,
       const float* __restrict__ lnsc, const float* __restrict__ lnbi,
       __half* __restrict__ lnout, int M, int Nfull) {
    extern __shared__ char sm[];
    __shared__ float red[2][128];
    __shared__ float lnred[2][128][2];
    uint32_t sb = smem_u32(sm);
    const int K = NK * 64;
    const uint32_t ABYTES = (uint32_t)NK * 16384u;
    int tid = threadIdx.x;
    int w = tid >> 5, lane = tid & 31;
    int wm = w & 3, wn = w >> 2;
    int m0 = blockIdx.y * 128;
    int nt = blockIdx.x;

    int rA[2], rB[4];
#pragma unroll
    for (int mi = 0; mi < 2; mi++) rA[mi] = wm * 32 + mi * 16 + (lane & 15);
#pragma unroll
    for (int ng = 0; ng < 4; ng++)
        rB[ng] = wn * 64 + ng * 16 + ((lane >> 4) << 3) + (lane & 7);
    int cA = lane >> 4;
    int cB = (lane >> 3) & 1;

    // issue loads per chunk: group c = A-chunk c + B-chunk c
#pragma unroll
    for (int chunk = 0; chunk < NK; chunk++) {
#pragma unroll
        for (int t = 0; t < 4; t++) {
            int idx = t * 256 + tid;
            int row = idx >> 3, c16 = idx & 7;
            uint32_t soff = row * 128 + (((uint32_t)c16 ^ (row & 7)) << 4);
            long ga = m0 + row;
            bool ok = ga < M;
            if (!ok) ga = 0;
            cpasync16(sb + (uint32_t)chunk * 16384u + soff,
                      A + ga * K + chunk * 64 + c16 * 8, ok ? 16u : 0u);
            long gb = (long)(nt * 128 + row);
            cpasync16(sb + ABYTES + (uint32_t)chunk * 16384u + soff,
                      B + gb * K + chunk * 64 + c16 * 8, 16u);
        }
        CP_COMMIT();
    }

    float acc[2][8][4];
#pragma unroll
    for (int i = 0; i < 2; i++)
#pragma unroll
        for (int j = 0; j < 8; j++)
#pragma unroll
            for (int q = 0; q < 4; q++) acc[i][j][q] = 0.f;

#pragma unroll
    for (int chunk = 0; chunk < NK; chunk++) {
        if (NK == 2 && chunk == 0) CP_WAIT(1);
        else CP_WAIT(0);
        __syncthreads();
        uint32_t Ab = sb + (uint32_t)chunk * 16384u;
        uint32_t Bb = sb + ABYTES + (uint32_t)chunk * 16384u;
#pragma unroll
        for (int ks = 0; ks < 4; ks++) {
            int kc = ks * 2;
            uint32_t fa[2][4], fb[4][4];
#pragma unroll
            for (int mi = 0; mi < 2; mi++) {
                int row = rA[mi];
                ldsm4(fa[mi], Ab + row * 128 + ((((uint32_t)(kc + cA)) ^ (row & 7)) << 4));
            }
#pragma unroll
            for (int ng = 0; ng < 4; ng++) {
                int row = rB[ng];
                ldsm4(fb[ng], Bb + row * 128 + ((((uint32_t)(kc + cB)) ^ (row & 7)) << 4));
            }
#pragma unroll
            for (int ng = 0; ng < 4; ng++)
#pragma unroll
                for (int mi = 0; mi < 2; mi++) {
                    mma16816(acc[mi][ng * 2],     fa[mi], fb[ng][0], fb[ng][1]);
                    mma16816(acc[mi][ng * 2 + 1], fa[mi], fb[ng][2], fb[ng][3]);
                }
        }
    }
    __syncthreads();

    int n0 = nt * 128;
    int tg = lane >> 2;
    int tc = (lane & 3) * 2;

    if (EPI == 5) {
        float p[2][2] = {};
#pragma unroll
        for (int mi = 0; mi < 2; mi++)
#pragma unroll
            for (int ni = 0; ni < 8; ni++) {
                int col = wn * 64 + ni * 8 + tc;
                float b0 = bias[col], b1 = bias[col + 1];
                float w20 = w2[col], w21 = w2[col + 1];
                p[mi][0] += fmaxf(acc[mi][ni][0] + b0, 0.f) * w20 +
                            fmaxf(acc[mi][ni][1] + b1, 0.f) * w21;
                p[mi][1] += fmaxf(acc[mi][ni][2] + b0, 0.f) * w20 +
                            fmaxf(acc[mi][ni][3] + b1, 0.f) * w21;
            }
#pragma unroll
        for (int mi = 0; mi < 2; mi++)
#pragma unroll
            for (int hf = 0; hf < 2; hf++) {
                float v = p[mi][hf];
                v += __shfl_xor_sync(~0u, v, 1);
                v += __shfl_xor_sync(~0u, v, 2);
                if ((lane & 3) == 0) red[wn][wm * 32 + mi * 16 + hf * 8 + tg] = v;
            }
        __syncthreads();
        if (tid < 128) {
            int row = m0 + tid;
            if (row < M) C[row] = red[0][tid] + red[1][tid] + pos[0];
        }
        return;
    }

    if (EPI == 0 || EPI == 4) {
#pragma unroll
        for (int mi = 0; mi < 2; mi++)
#pragma unroll
            for (int hf = 0; hf < 2; hf++) {
                int row = m0 + wm * 32 + mi * 16 + hf * 8 + tg;
                if (row >= M) continue;
#pragma unroll
                for (int ni = 0; ni < 8; ni++) {
                    int col = n0 + wn * 64 + ni * 8 + tc;
                    float v0 = acc[mi][ni][hf * 2 + 0];
                    float v1 = acc[mi][ni][hf * 2 + 1];
                    if (EPI == 4) {
                        v0 += bias[col];
                        v1 += bias[col + 1];
                        v0 = 0.5f * v0 * (1.f + erff(v0 * 0.70710678118654752f));
                        v1 = 0.5f * v1 * (1.f + erff(v1 * 0.70710678118654752f));
                    }
                    __half hl[2] = {__float2half(v0), __float2half(v1)};
                    *(uint32_t*)&Ch[(long)row * Nfull + col] = *(uint32_t*)hl;
                }
            }
        return;
    }

    // EPI 2/3
    float s1[2][2] = {}, s2[2][2] = {};
#pragma unroll
    for (int mi = 0; mi < 2; mi++)
#pragma unroll
        for (int hf = 0; hf < 2; hf++) {
            int row = m0 + wm * 32 + mi * 16 + hf * 8 + tg;
            bool rok = row < M;
            long pr = (EPI == 2 && rok) ? (long)(row % SEQ) * 128 : 0;
#pragma unroll
            for (int ni = 0; ni < 8; ni++) {
                int col = n0 + wn * 64 + ni * 8 + tc;
                float v0 = acc[mi][ni][hf * 2 + 0] + bias[col];
                float v1 = acc[mi][ni][hf * 2 + 1] + bias[col + 1];
                if (rok) {
                    if (EPI == 2) {
                        v0 += pos[pr + col];
                        v1 += pos[pr + col + 1];
                    } else {
                        v0 += res[(long)row * Nfull + col];
                        v1 += res[(long)row * Nfull + col + 1];
                    }
                    *(float2*)&C[(long)row * Nfull + col] = make_float2(v0, v1);
                }
                acc[mi][ni][hf * 2 + 0] = v0;
                acc[mi][ni][hf * 2 + 1] = v1;
                s1[mi][hf] += v0 + v1;
                s2[mi][hf] += v0 * v0 + v1 * v1;
            }
        }
    if (lnout) {
#pragma unroll
        for (int mi = 0; mi < 2; mi++)
#pragma unroll
            for (int hf = 0; hf < 2; hf++) {
                float a = s1[mi][hf], b = s2[mi][hf];
                a += __shfl_xor_sync(~0u, a, 1);
                a += __shfl_xor_sync(~0u, a, 2);
                b += __shfl_xor_sync(~0u, b, 1);
                b += __shfl_xor_sync(~0u, b, 2);
                if ((lane & 3) == 0) {
                    int ri = wm * 32 + mi * 16 + hf * 8 + tg;
                    lnred[wn][ri][0] = a;
                    lnred[wn][ri][1] = b;
                }
            }
        __syncthreads();
#pragma unroll
        for (int mi = 0; mi < 2; mi++)
#pragma unroll
            for (int hf = 0; hf < 2; hf++) {
                int ri = wm * 32 + mi * 16 + hf * 8 + tg;
                int row = m0 + ri;
                if (row >= M) continue;
                float m1 = (lnred[0][ri][0] + lnred[1][ri][0]) * (1.f / 128.f);
                float m2 = (lnred[0][ri][1] + lnred[1][ri][1]) * (1.f / 128.f);
                float inv = rsqrtf(m2 - m1 * m1 + 1e-5f);
#pragma unroll
                for (int ni = 0; ni < 8; ni++) {
                    int col = wn * 64 + ni * 8 + tc;
                    float v0 = (acc[mi][ni][hf * 2 + 0] - m1) * inv * lnsc[col] + lnbi[col];
                    float v1 = (acc[mi][ni][hf * 2 + 1] - m1) * inv * lnsc[col + 1] + lnbi[col + 1];
                    __half hl[2] = {__float2half(v0), __float2half(v1)};
                    *(uint32_t*)&lnout[(long)row * 128 + col] = *(uint32_t*)hl;
                }
            }
    }
}

// =============== chunked fp16 GEMM for K=512 (ff2) + fused LN/out ============
#define CSTAGE_B 32768u

__global__ void __launch_bounds__(256, 2)
tgemmC(const __half* __restrict__ A, const __half* __restrict__ B,
       const float* __restrict__ bias, const float* __restrict__ res,
       float* __restrict__ C, const float* __restrict__ lnsc,
       const float* __restrict__ lnbi, __half* __restrict__ lnout,
       int M, int N, int K) {
    extern __shared__ char sm[];
    __shared__ float lnred[2][128][2];
    uint32_t sb = smem_u32(sm);
    int tid = threadIdx.x;
    int w = tid >> 5, lane = tid & 31;
    int wm = w & 3, wn = w >> 2;
    int m0 = blockIdx.y * 128, n0 = blockIdx.x * 128;
    int nk = K >> 6;

    float acc[2][8][4];
#pragma unroll
    for (int i = 0; i < 2; i++)
#pragma unroll
        for (int j = 0; j < 8; j++)
#pragma unroll
            for (int q = 0; q < 4; q++) acc[i][j][q] = 0.f;

    int rA[2], rB[4];
#pragma unroll
    for (int mi = 0; mi < 2; mi++) rA[mi] = wm * 32 + mi * 16 + (lane & 15);
#pragma unroll
    for (int ng = 0; ng < 4; ng++)
        rB[ng] = wn * 64 + ng * 16 + ((lane >> 4) << 3) + (lane & 7);
    int cA = lane >> 4;
    int cB = (lane >> 3) & 1;

    auto load_stage = [&](int c, int buf) {
#pragma unroll
        for (int it = 0; it < 8; it++) {
            int slot = it * 256 + tid;
            int t = it >> 2;
            int row = (slot >> 3) & 127;
            int chunk = slot & 7;
            const __half* src = t ? B : A;
            long grow = t ? (long)(n0 + row) : (long)(m0 + row);
            bool ok = t ? true : (m0 + row < M);
            if (!ok) grow = 0;
            const void* g = (const void*)(src + grow * K + ((long)c << 6) + chunk * 8);
            uint32_t saddr = sb + buf * CSTAGE_B + (uint32_t)t * 16384u + row * 128 +
                             ((chunk ^ (row & 7)) << 4);
            cpasync16(saddr, g, ok ? 16u : 0u);
        }
        CP_COMMIT();
    };

#pragma unroll
    for (int p = 0; p < 2; p++) load_stage(p, p);

    for (int c = 0; c < nk; c++) {
        int nxt = c + 2;
        if (nxt < nk) load_stage(nxt, nxt % 3);
        int allow = (nxt < nk ? nxt : nk - 1) - c;
        if (allow >= 2) CP_WAIT(2);
        else if (allow == 1) CP_WAIT(1);
        else CP_WAIT(0);
        __syncthreads();

        uint32_t st = sb + (c % 3) * CSTAGE_B;
#pragma unroll
        for (int ks = 0; ks < 4; ks++) {
            int kc = ks * 2;
            uint32_t fa[2][4], fb[4][4];
#pragma unroll
            for (int mi = 0; mi < 2; mi++) {
                int row = rA[mi];
                ldsm4(fa[mi], st + row * 128 + ((((uint32_t)(kc + cA)) ^ (row & 7)) << 4));
            }
#pragma unroll
            for (int ng = 0; ng < 4; ng++) {
                int row = rB[ng];
                ldsm4(fb[ng], st + 16384u + row * 128 + ((((uint32_t)(kc + cB)) ^ (row & 7)) << 4));
            }
#pragma unroll
            for (int ng = 0; ng < 4; ng++)
#pragma unroll
                for (int mi = 0; mi < 2; mi++) {
                    mma16816(acc[mi][ng * 2],     fa[mi], fb[ng][0], fb[ng][1]);
                    mma16816(acc[mi][ng * 2 + 1], fa[mi], fb[ng][2], fb[ng][3]);
                }
        }
        __syncthreads();
    }

    int tg = lane >> 2;
    int tc = (lane & 3) * 2;
    float s1[2][2] = {}, s2[2][2] = {};
#pragma unroll
    for (int mi = 0; mi < 2; mi++)
#pragma unroll
        for (int hf = 0; hf < 2; hf++) {
            int row = m0 + wm * 32 + mi * 16 + hf * 8 + tg;
            bool rok = row < M;
#pragma unroll
            for (int ni = 0; ni < 8; ni++) {
                int col = n0 + wn * 64 + ni * 8 + tc;
                float v0 = acc[mi][ni][hf * 2 + 0] + bias[col];
                float v1 = acc[mi][ni][hf * 2 + 1] + bias[col + 1];
                if (rok) {
                    v0 += res[(long)row * N + col];
                    v1 += res[(long)row * N + col + 1];
                    *(float2*)&C[(long)row * N + col] = make_float2(v0, v1);
                }
                acc[mi][ni][hf * 2 + 0] = v0;
                acc[mi][ni][hf * 2 + 1] = v1;
                s1[mi][hf] += v0 + v1;
                s2[mi][hf] += v0 * v0 + v1 * v1;
            }
        }
    if (lnout && lnsc) {
#pragma unroll
        for (int mi = 0; mi < 2; mi++)
#pragma unroll
            for (int hf = 0; hf < 2; hf++) {
                float a = s1[mi][hf], b = s2[mi][hf];
                a += __shfl_xor_sync(~0u, a, 1);
                a += __shfl_xor_sync(~0u, a, 2);
                b += __shfl_xor_sync(~0u, b, 1);
                b += __shfl_xor_sync(~0u, b, 2);
                if ((lane & 3) == 0) {
                    int ri = wm * 32 + mi * 16 + hf * 8 + tg;
                    lnred[wn][ri][0] = a;
                    lnred[wn][ri][1] = b;
                }
            }
        __syncthreads();
#pragma unroll
        for (int mi = 0; mi < 2; mi++)
#pragma unroll
            for (int hf = 0; hf < 2; hf++) {
                int ri = wm * 32 + mi * 16 + hf * 8 + tg;
                int row = m0 + ri;
                if (row >= M) continue;
                float m1 = (lnred[0][ri][0] + lnred[1][ri][0]) * (1.f / 128.f);
                float m2 = (lnred[0][ri][1] + lnred[1][ri][1]) * (1.f / 128.f);
                float inv = rsqrtf(m2 - m1 * m1 + 1e-5f);
#pragma unroll
                for (int ni = 0; ni < 8; ni++) {
                    int col = wn * 64 + ni * 8 + tc;
                    float v0 = (acc[mi][ni][hf * 2 + 0] - m1) * inv * lnsc[col] + lnbi[col];
                    float v1 = (acc[mi][ni][hf * 2 + 1] - m1) * inv * lnsc[col + 1] + lnbi[col + 1];
                    __half hl[2] = {__float2half(v0), __float2half(v1)};
                    *(uint32_t*)&lnout[(long)row * 128 + col] = *(uint32_t*)hl;
                }
            }
    } else if (lnout) {
#pragma unroll
        for (int mi = 0; mi < 2; mi++)
#pragma unroll
            for (int hf = 0; hf < 2; hf++) {
                int row = m0 + wm * 32 + mi * 16 + hf * 8 + tg;
                if (row >= M) continue;
#pragma unroll
                for (int ni = 0; ni < 8; ni++) {
                    int col = n0 + wn * 64 + ni * 8 + tc;
                    __half hl[2] = {__float2half(acc[mi][ni][hf * 2 + 0]),
                                    __float2half(acc[mi][ni][hf * 2 + 1])};
                    *(uint32_t*)&lnout[(long)row * 128 + col] = *(uint32_t*)hl;
                }
            }
    }
}

// ---------------- MMA local windowed attention --------------------------------
__global__ void __launch_bounds__(256, 2)
attn_k(const __half* __restrict__ qkv, __half* __restrict__ o) {
    __shared__ __half q_s[64 * 24];
    __shared__ __half k_s[192 * 24];
    __shared__ __half v_s[192 * 24];
    __shared__ float ms_s[2][4][16];
    __shared__ float ls_s[2][4][16];
    __shared__ float osum[2][4][16][16];
    int w = blockIdx.x, bh = blockIdx.y;
    int b = bh >> 3, h = bh & 7;
    int tid = threadIdx.x, warp = tid >> 5, lane = tid & 31;
    int wm = warp & 3, wn = warp >> 2;
    int jstart = (w > 0) ? 0 : S1;
    int jend = (w < S1 - 1) ? 3 * S1 : 2 * S1;
    int cnt = jend - jstart;
    long rb = (long)b * SEQ;
    const uint4* qg = (const uint4*)qkv;

    int total = S1 + 2 * cnt;
    for (int idx = tid; idx < total; idx += 256) {
        if (idx < S1) {
            long grow = (rb + (long)w * S1 + idx) * 48 + h * 2;
            uint4 a = qg[grow], c = qg[grow + 1];
            *(uint4*)&q_s[idx * 24] = a;
            *(uint4*)&q_s[idx * 24 + 8] = c;
        } else {
            int r = idx - S1;
            int which = (r >= cnt);
            int jl = which ? r - cnt : r;
            long grow = (rb + (long)(w - 1) * S1 + jstart + jl) * 48 + h * 2 + (which ? 32 : 16);
            uint4 a = qg[grow], c = qg[grow + 1];
            __half* dst = (which ? v_s : k_s) + jl * 24;
            *(uint4*)dst = a;
            *(uint4*)&dst[8] = c;
        }
    }
    if (tid < 9) *(uint4*)&q_s[61 * 24 + tid * 8] = make_uint4(0, 0, 0, 0);
    for (int r = cnt + tid; r < 192; r += 256) {
        uint4 z = make_uint4(0, 0, 0, 0);
        *(uint4*)&k_s[r * 24] = z;
        *(uint4*)&k_s[r * 24 + 8] = z;
        *(uint4*)&v_s[r * 24] = z;
        *(uint4*)&v_s[r * 24 + 8] = z;
    }
    __syncthreads();

    uint32_t qb = smem_u32(q_s), kbb = smem_u32(k_s), vbb = smem_u32(v_s);

    uint32_t a[4];
    ldsm4(a, qb + (uint32_t)(wm * 16 + ((lane >> 3) & 1) * 8 + (lane & 7)) * 48 + (lane >> 4) * 16);

    float s[12][4];
#pragma unroll
    for (int ti = 0; ti < 12; ti++)
#pragma unroll
        for (int e = 0; e < 4; e++) s[ti][e] = 0.f;
#pragma unroll
    for (int g = 0; g < 6; g++) {
        uint32_t r[4];
        ldsm4(r, kbb + (uint32_t)(wn * 96 + g * 16 + (lane >> 4) * 8 + (lane & 7)) * 48 +
                   ((lane >> 3) & 1) * 16);
        mma16816(s[g * 2],     a, r[0], r[1]);
        mma16816(s[g * 2 + 1], a, r[2], r[3]);
    }

    float mloc[2] = {-1e30f, -1e30f};
#pragma unroll
    for (int ti = 0; ti < 12; ti++) {
        int cbase = wn * 96 + ti * 8 + (lane & 3) * 2;
#pragma unroll
        for (int e = 0; e < 4; e++) {
            int col = cbase + (e & 1);
            float v = (col < cnt) ? s[ti][e] * 0.25f : -1e30f;
            s[ti][e] = v;
            mloc[e >> 1] = fmaxf(mloc[e >> 1], v);
        }
    }
#pragma unroll
    for (int i = 0; i < 2; i++) {
        mloc[i] = fmaxf(mloc[i], __shfl_xor_sync(~0u, mloc[i], 1));
        mloc[i] = fmaxf(mloc[i], __shfl_xor_sync(~0u, mloc[i], 2));
    }
    if ((lane & 3) == 0) {
        ms_s[wn][wm][lane >> 2] = mloc[0];
        ms_s[wn][wm][(lane >> 2) + 8] = mloc[1];
    }
    __syncthreads();
    float m0 = fmaxf(ms_s[0][wm][lane >> 2], ms_s[1][wm][lane >> 2]);
    float m1 = fmaxf(ms_s[0][wm][(lane >> 2) + 8], ms_s[1][wm][(lane >> 2) + 8]);

    float lloc[2] = {0.f, 0.f};
    uint32_t ph[12][2];
#pragma unroll
    for (int ti = 0; ti < 12; ti++) {
        float p0 = __expf(s[ti][0] - m0);
        float p1 = __expf(s[ti][1] - m0);
        float p2 = __expf(s[ti][2] - m1);
        float p3 = __expf(s[ti][3] - m1);
        lloc[0] += p0 + p1;
        lloc[1] += p2 + p3;
        __half2 h01 = __floats2half2_rn(p0, p1);
        __half2 h23 = __floats2half2_rn(p2, p3);
        ph[ti][0] = *(uint32_t*)&h01;
        ph[ti][1] = *(uint32_t*)&h23;
    }
#pragma unroll
    for (int i = 0; i < 2; i++) {
        lloc[i] += __shfl_xor_sync(~0u, lloc[i], 1);
        lloc[i] += __shfl_xor_sync(~0u, lloc[i], 2);
    }
    if ((lane & 3) == 0) {
        ls_s[wn][wm][lane >> 2] = lloc[0];
        ls_s[wn][wm][(lane >> 2) + 8] = lloc[1];
    }

    float oa[2][4] = {{0.f, 0.f, 0.f, 0.f}, {0.f, 0.f, 0.f, 0.f}};
#pragma unroll
    for (int g = 0; g < 6; g++) {
        uint32_t r[4];
        ldsm4t(r, vbb + (uint32_t)(wn * 96 + g * 16 + ((lane >> 3) & 1) * 8 + (lane & 7)) * 48 +
                    (lane >> 4) * 16);
        uint32_t pa[4] = {ph[g * 2][0], ph[g * 2][1], ph[g * 2 + 1][0], ph[g * 2 + 1][1]};
        mma16816(oa[0], pa, r[0], r[1]);
        mma16816(oa[1], pa, r[2], r[3]);
    }
    {
        int rl = lane >> 2, cc = (lane & 3) * 2;
        *(float2*)&osum[wn][wm][rl][cc]         = make_float2(oa[0][0], oa[0][1]);
        *(float2*)&osum[wn][wm][rl + 8][cc]     = make_float2(oa[0][2], oa[0][3]);
        *(float2*)&osum[wn][wm][rl][cc + 8]     = make_float2(oa[1][0], oa[1][1]);
        *(float2*)&osum[wn][wm][rl + 8][cc + 8] = make_float2(oa[1][2], oa[1][3]);
    }
    __syncthreads();

    for (int idx = tid; idx < S1 * 16; idx += 256) {
        int i = idx >> 4, d = idx & 15;
        int wmq = i >> 4, rl = i & 15;
        float val = osum[0][wmq][rl][d] + osum[1][wmq][rl][d];
        float l = ls_s[0][wmq][rl] + ls_s[1][wmq][rl];
        o[(rb + (long)w * S1 + i) * 128 + h * 16 + d] = __float2half(val / l);
    }
}

// ---------------- launch ------------------------------------------------------
extern "C" void kernel_launch(void* const* d_in, const int* in_sizes, int n_in,
                              void* d_out, int out_size) {
    const float* x      = (const float*)d_in[0];
    const float* conv_w = (const float*)d_in[1];
    const float* conv_b = (const float*)d_in[2];
    const float* lt_w   = (const float*)d_in[3];
    const float* lt_b   = (const float*)d_in[4];
    const float* pos    = (const float*)d_in[5];
    const float* ln1_s  = (const float*)d_in[6];
    const float* ln1_b  = (const float*)d_in[7];
    const float* wq     = (const float*)d_in[8];
    const float* wk     = (const float*)d_in[9];
    const float* wv     = (const float*)d_in[10];
    const float* wo     = (const float*)d_in[11];
    const float* wo_b   = (const float*)d_in[12];
    const float* ln2_s  = (const float*)d_in[13];
    const float* ln2_b  = (const float*)d_in[14];
    const float* ff_w1  = (const float*)d_in[15];
    const float* ff_b1  = (const float*)d_in[16];
    const float* ff_w2  = (const float*)d_in[17];
    const float* ff_b2  = (const float*)d_in[18];
    const float* pre_w1 = (const float*)d_in[19];
    const float* pre_b1 = (const float*)d_in[20];
    const float* pre_w2 = (const float*)d_in[21];
    const float* pre_b2 = (const float*)d_in[22];
    float* out = (float*)d_out;

    static bool attr_done = false;
    if (!attr_done) {
        cudaFuncSetAttribute(tgemmA<0,2>, cudaFuncAttributeMaxDynamicSharedMemorySize, 65536);
        cudaFuncSetAttribute(tgemmA<2,1>, cudaFuncAttributeMaxDynamicSharedMemorySize, 32768);
        cudaFuncSetAttribute(tgemmA<3,2>, cudaFuncAttributeMaxDynamicSharedMemorySize, 65536);
        cudaFuncSetAttribute(tgemmA<4,2>, cudaFuncAttributeMaxDynamicSharedMemorySize, 65536);
        cudaFuncSetAttribute(tgemmA<5,2>, cudaFuncAttributeMaxDynamicSharedMemorySize, 65536);
        cudaFuncSetAttribute(tgemmC, cudaFuncAttributeMaxDynamicSharedMemorySize, 98304);
        attr_done = true;
    }

    __half *p, *lnb, *att, *ff, *hh, *wlt, *wqkv, *woh, *wf1, *wf2, *wp1, *qkvh;
    float *h;
    cudaGetSymbolAddress((void**)&p, g_p);       cudaGetSymbolAddress((void**)&h, g_h);
    cudaGetSymbolAddress((void**)&lnb, g_ln);    cudaGetSymbolAddress((void**)&qkvh, g_qkv);
    cudaGetSymbolAddress((void**)&att, g_att);   cudaGetSymbolAddress((void**)&ff, g_ff);
    cudaGetSymbolAddress((void**)&hh, g_hh);     cudaGetSymbolAddress((void**)&wlt, g_wlt);
    cudaGetSymbolAddress((void**)&wqkv, g_wqkv); cudaGetSymbolAddress((void**)&woh, g_wo);
    cudaGetSymbolAddress((void**)&wf1, g_wf1);   cudaGetSymbolAddress((void**)&wf2, g_wf2);
    cudaGetSymbolAddress((void**)&wp1, g_wp1);

    const int M = MROWS;

    prep_all<<<(PREP_TOTAL + 255) / 256, 256>>>(lt_w, wq, wk, wv, wo, ff_w1, ff_w2, pre_w1,
                                                wlt, wqkv, woh, wf1, wf2, wp1);
    conv_k<<<(MROWS * 64 + 255) / 256, 256>>>(x, conv_w, conv_b, p);
    tgemmA<2,1><<<dim3(1, MTILES), 256, 32768>>>(p, wlt, lt_b, nullptr, pos, nullptr,
                                                 h, nullptr, ln1_s, ln1_b, lnb, M, 128);

    for (int i = 0; i < NLAYER; i++) {
        tgemmA<0,2><<<dim3(3, MTILES), 256, 65536>>>(lnb, wqkv + (long)i * 49152,
            nullptr, nullptr, nullptr, nullptr, nullptr, qkvh,
            nullptr, nullptr, nullptr, M, 384);
        attn_k<<<dim3(S1, BATCH * HEADS), 256>>>(qkvh, att);
        tgemmA<3,2><<<dim3(1, MTILES), 256, 65536>>>(att, woh + (long)i * 16384,
            wo_b + i * 128, h, nullptr, nullptr, h, nullptr,
            ln2_s + i * 128, ln2_b + i * 128, lnb, M, 128);
        tgemmA<4,2><<<dim3(4, MTILES), 256, 65536>>>(lnb, wf1 + (long)i * 65536,
            ff_b1 + i * 512, nullptr, nullptr, nullptr, nullptr, ff,
            nullptr, nullptr, nullptr, M, 512);
        bool last = (i == NLAYER - 1);
        tgemmC<<<dim3(1, MTILES), 256, 98304>>>(ff, wf2 + (long)i * 65536,
            ff_b2 + i * 128, h, h,
            last ? nullptr : ln1_s + (i + 1) * 128,
            last ? nullptr : ln1_b + (i + 1) * 128,
            last ? hh : lnb, M, 128, 512);
    }

    tgemmA<5,2><<<dim3(1, MTILES), 256, 65536>>>(hh, wp1, pre_b1, nullptr, pre_b2, pre_w2,
                                                 out, nullptr, nullptr, nullptr, nullptr, M, 128);
}

// round 13
// speedup vs baseline: 3.1137x; 1.0219x over previous
#include <cuda_runtime.h>
#include <cuda_fp16.h>
#include <cstdint>
#include <math.h>

#define BATCH 16
#define S1 61
#define SEQ 3721
#define DMODEL 128
#define HEADS 8
#define DH 16
#define NLAYER 4
#define FFDIM 512
#define PCH 49
#define MROWS (BATCH * SEQ) // 59536
#define MTILES ((MROWS + 127) / 128) // 466

// ---------------------------------------------------------------- scratch
__device__ __half g_p[MROWS * 64];
__device__ float  g_h[MROWS * 128];
__device__ __half g_ln[MROWS * 128];
__device__ __half g_qkv[(size_t)MROWS * 384];
__device__ __half g_att[MROWS * 128];
__device__ __half g_ff[(size_t)MROWS * 512];
__device__ __half g_hh[MROWS * 128];
__device__ __half g_wlt[128 * 64];
__device__ __half g_wqkv[NLAYER * 384 * 128];
__device__ __half g_wo[NLAYER * 128 * 128];
__device__ __half g_wf1[NLAYER * 512 * 128];
__device__ __half g_wf2[NLAYER * 128 * 512];
__device__ __half g_wp1[128 * 128];

// ---------------------------------------------------------------- helpers
__device__ __forceinline__ uint32_t smem_u32(const void* p) {
    uint32_t a;
    asm("{ .reg .u64 t; cvta.to.shared.u64 t, %1; cvt.u32.u64 %0, t; }" : "=r"(a) : "l"(p));
    return a;
}
__device__ __forceinline__ void ldsm4(uint32_t* r, uint32_t addr) {
    asm volatile("ldmatrix.sync.aligned.m8n8.x4.shared.b16 {%0,%1,%2,%3}, [%4];"
                 : "=r"(r[0]), "=r"(r[1]), "=r"(r[2]), "=r"(r[3]) : "r"(addr));
}
__device__ __forceinline__ void ldsm4t(uint32_t* r, uint32_t addr) {
    asm volatile("ldmatrix.sync.aligned.m8n8.x4.trans.shared.b16 {%0,%1,%2,%3}, [%4];"
                 : "=r"(r[0]), "=r"(r[1]), "=r"(r[2]), "=r"(r[3]) : "r"(addr));
}
__device__ __forceinline__ void mma16816(float* c, const uint32_t* a, uint32_t b0, uint32_t b1) {
    asm volatile("mma.sync.aligned.m16n8k16.row.col.f32.f16.f16.f32 "
                 "{%0,%1,%2,%3}, {%4,%5,%6,%7}, {%8,%9}, {%0,%1,%2,%3};"
                 : "+f"(c[0]), "+f"(c[1]), "+f"(c[2]), "+f"(c[3])
                 : "r"(a[0]), "r"(a[1]), "r"(a[2]), "r"(a[3]), "r"(b0), "r"(b1));
}
__device__ __forceinline__ void cpasync16(uint32_t saddr, const void* g, uint32_t ssz) {
    asm volatile("cp.async.cg.shared.global [%0], [%1], 16, %2;"
                 :: "r"(saddr), "l"(g), "r"(ssz));
}
#define CP_COMMIT() asm volatile("cp.async.commit_group;" ::: "memory")
#define CP_WAIT(n)  asm volatile("cp.async.wait_group %0;" :: "n"(n) : "memory")

// ------------- fused conv (7x7 same + relu -> fp16) AND weight prep ----------
#define CONV_TOTAL (MROWS * 64)
#define PREP_TOTAL (8192 + 196608 + 65536 + 262144 + 262144 + 16384)
__global__ void conv_prep(const float* __restrict__ x, const float* __restrict__ cw,
                          const float* __restrict__ cb, __half* __restrict__ p,
                          const float* __restrict__ lt_w, const float* __restrict__ wq,
                          const float* __restrict__ wk, const float* __restrict__ wv,
                          const float* __restrict__ wo, const float* __restrict__ ff_w1,
                          const float* __restrict__ ff_w2, const float* __restrict__ pre_w1,
                          __half* __restrict__ wlt, __half* __restrict__ wqkv,
                          __half* __restrict__ woh, __half* __restrict__ wf1,
                          __half* __restrict__ wf2, __half* __restrict__ wp1) {
    long t = (long)blockIdx.x * blockDim.x + threadIdx.x;
    if (t < CONV_TOTAL) {
        int o = (int)(t & 63);
        float sum = 0.f;
        if (o < PCH) {
            int s = (int)(t >> 6) % SEQ;
            int b = (int)(t >> 6) / SEQ;
            int y = s / S1, xx = s % S1;
            const float* xb = x + (long)b * SEQ;
            const float* wrow = cw + o * 49;
            sum = cb[o];
#pragma unroll
            for (int dy = 0; dy < 7; dy++) {
                int iy = y + dy - 3;
                if (iy < 0 || iy >= S1) continue;
#pragma unroll
                for (int dx = 0; dx < 7; dx++) {
                    int ix = xx + dx - 3;
                    if (ix < 0 || ix >= S1) continue;
                    sum += xb[iy * S1 + ix] * wrow[dy * 7 + dx];
                }
            }
            sum = fmaxf(sum, 0.f);
        }
        p[t] = __float2half(sum);
        return;
    }
    t -= CONV_TOTAL;
    if (t >= PREP_TOTAL) return;
    if (t < 8192) {
        int n = (int)(t >> 6), kk = (int)(t & 63);
        wlt[t] = __float2half(kk < 49 ? lt_w[kk * 128 + n] : 0.f);
        return;
    }
    t -= 8192;
    if (t < 196608) {
        int l = (int)(t / 49152), r = (int)(t % 49152);
        int n = r >> 7, kk = r & 127;
        int s = n >> 7, nn = n & 127;
        const float* W = (s == 0 ? wq : s == 1 ? wk : wv) + (long)l * 16384;
        wqkv[t] = __float2half(W[kk * 128 + nn]);
        return;
    }
    t -= 196608;
    if (t < 65536) {
        int l = (int)(t / 16384), r = (int)(t % 16384);
        int n = r >> 7, kk = r & 127;
        woh[t] = __float2half(wo[(long)l * 16384 + kk * 128 + n]);
        return;
    }
    t -= 65536;
    if (t < 262144) {
        int l = (int)(t / 65536), r = (int)(t % 65536);
        int n = r >> 7, kk = r & 127;
        wf1[t] = __float2half(ff_w1[(long)l * 65536 + (long)kk * 512 + n]);
        return;
    }
    t -= 262144;
    if (t < 262144) {
        int l = (int)(t / 65536), r = (int)(t % 65536);
        int n = r / 512, kk = r % 512;
        wf2[t] = __float2half(ff_w2[(long)l * 65536 + (long)kk * 128 + n]);
        return;
    }
    t -= 262144;
    if (t < 16384) {
        int n = (int)(t >> 7), kk = (int)(t & 127);
        wp1[t] = __float2half(pre_w1[kk * 128 + n]);
    }
}

// =============== A-resident fp16 GEMM (K<=128), n-tile = blockIdx.x ==========
template <int EPI, int NK>
__global__ void __launch_bounds__(256, 2)
tgemmA(const __half* __restrict__ A, const __half* __restrict__ B,
       const float* __restrict__ bias, const float* __restrict__ res,
       const float* __restrict__ pos, const float* __restrict__ w2,
       float* __restrict__ C, __half* __restrict__ Ch,
       const float* __restrict__ lnsc, const float* __restrict__ lnbi,
       __half* __restrict__ lnout, int M, int Nfull) {
    extern __shared__ char sm[];
    __shared__ float red[2][128];
    __shared__ float lnred[2][128][2];
    uint32_t sb = smem_u32(sm);
    const int K = NK * 64;
    const uint32_t ABYTES = (uint32_t)NK * 16384u;
    int tid = threadIdx.x;
    int w = tid >> 5, lane = tid & 31;
    int wm = w & 3, wn = w >> 2;
    int m0 = blockIdx.y * 128;
    int nt = blockIdx.x;

    int rA[2], rB[4];
#pragma unroll
    for (int mi = 0; mi < 2; mi++) rA[mi] = wm * 32 + mi * 16 + (lane & 15);
#pragma unroll
    for (int ng = 0; ng < 4; ng++)
        rB[ng] = wn * 64 + ng * 16 + ((lane >> 4) << 3) + (lane & 7);
    int cA = lane >> 4;
    int cB = (lane >> 3) & 1;

#pragma unroll
    for (int chunk = 0; chunk < NK; chunk++) {
#pragma unroll
        for (int t = 0; t < 4; t++) {
            int idx = t * 256 + tid;
            int row = idx >> 3, c16 = idx & 7;
            uint32_t soff = row * 128 + (((uint32_t)c16 ^ (row & 7)) << 4);
            long ga = m0 + row;
            bool ok = ga < M;
            if (!ok) ga = 0;
            cpasync16(sb + (uint32_t)chunk * 16384u + soff,
                      A + ga * K + chunk * 64 + c16 * 8, ok ? 16u : 0u);
            long gb = (long)(nt * 128 + row);
            cpasync16(sb + ABYTES + (uint32_t)chunk * 16384u + soff,
                      B + gb * K + chunk * 64 + c16 * 8, 16u);
        }
        CP_COMMIT();
    }

    float acc[2][8][4];
#pragma unroll
    for (int i = 0; i < 2; i++)
#pragma unroll
        for (int j = 0; j < 8; j++)
#pragma unroll
            for (int q = 0; q < 4; q++) acc[i][j][q] = 0.f;

#pragma unroll
    for (int chunk = 0; chunk < NK; chunk++) {
        if (NK == 2 && chunk == 0) CP_WAIT(1);
        else CP_WAIT(0);
        __syncthreads();
        uint32_t Ab = sb + (uint32_t)chunk * 16384u;
        uint32_t Bb = sb + ABYTES + (uint32_t)chunk * 16384u;
#pragma unroll
        for (int ks = 0; ks < 4; ks++) {
            int kc = ks * 2;
            uint32_t fa[2][4], fb[4][4];
#pragma unroll
            for (int mi = 0; mi < 2; mi++) {
                int row = rA[mi];
                ldsm4(fa[mi], Ab + row * 128 + ((((uint32_t)(kc + cA)) ^ (row & 7)) << 4));
            }
#pragma unroll
            for (int ng = 0; ng < 4; ng++) {
                int row = rB[ng];
                ldsm4(fb[ng], Bb + row * 128 + ((((uint32_t)(kc + cB)) ^ (row & 7)) << 4));
            }
#pragma unroll
            for (int ng = 0; ng < 4; ng++)
#pragma unroll
                for (int mi = 0; mi < 2; mi++) {
                    mma16816(acc[mi][ng * 2],     fa[mi], fb[ng][0], fb[ng][1]);
                    mma16816(acc[mi][ng * 2 + 1], fa[mi], fb[ng][2], fb[ng][3]);
                }
        }
    }
    __syncthreads();

    int n0 = nt * 128;
    int tg = lane >> 2;
    int tc = (lane & 3) * 2;

    if (EPI == 5) {
        float p[2][2] = {};
#pragma unroll
        for (int mi = 0; mi < 2; mi++)
#pragma unroll
            for (int ni = 0; ni < 8; ni++) {
                int col = wn * 64 + ni * 8 + tc;
                float b0 = bias[col], b1 = bias[col + 1];
                float w20 = w2[col], w21 = w2[col + 1];
                p[mi][0] += fmaxf(acc[mi][ni][0] + b0, 0.f) * w20 +
                            fmaxf(acc[mi][ni][1] + b1, 0.f) * w21;
                p[mi][1] += fmaxf(acc[mi][ni][2] + b0, 0.f) * w20 +
                            fmaxf(acc[mi][ni][3] + b1, 0.f) * w21;
            }
#pragma unroll
        for (int mi = 0; mi < 2; mi++)
#pragma unroll
            for (int hf = 0; hf < 2; hf++) {
                float v = p[mi][hf];
                v += __shfl_xor_sync(~0u, v, 1);
                v += __shfl_xor_sync(~0u, v, 2);
                if ((lane & 3) == 0) red[wn][wm * 32 + mi * 16 + hf * 8 + tg] = v;
            }
        __syncthreads();
        if (tid < 128) {
            int row = m0 + tid;
            if (row < M) C[row] = red[0][tid] + red[1][tid] + pos[0];
        }
        return;
    }

    if (EPI == 0 || EPI == 4) {
#pragma unroll
        for (int mi = 0; mi < 2; mi++)
#pragma unroll
            for (int hf = 0; hf < 2; hf++) {
                int row = m0 + wm * 32 + mi * 16 + hf * 8 + tg;
                if (row >= M) continue;
#pragma unroll
                for (int ni = 0; ni < 8; ni++) {
                    int col = n0 + wn * 64 + ni * 8 + tc;
                    float v0 = acc[mi][ni][hf * 2 + 0];
                    float v1 = acc[mi][ni][hf * 2 + 1];
                    if (EPI == 4) {
                        v0 += bias[col];
                        v1 += bias[col + 1];
                        v0 = 0.5f * v0 * (1.f + erff(v0 * 0.70710678118654752f));
                        v1 = 0.5f * v1 * (1.f + erff(v1 * 0.70710678118654752f));
                    }
                    __half hl[2] = {__float2half(v0), __float2half(v1)};
                    *(uint32_t*)&Ch[(long)row * Nfull + col] = *(uint32_t*)hl;
                }
            }
        return;
    }

    // EPI 2/3
    float s1[2][2] = {}, s2[2][2] = {};
#pragma unroll
    for (int mi = 0; mi < 2; mi++)
#pragma unroll
        for (int hf = 0; hf < 2; hf++) {
            int row = m0 + wm * 32 + mi * 16 + hf * 8 + tg;
            bool rok = row < M;
            long pr = (EPI == 2 && rok) ? (long)(row % SEQ) * 128 : 0;
#pragma unroll
            for (int ni = 0; ni < 8; ni++) {
                int col = n0 + wn * 64 + ni * 8 + tc;
                float v0 = acc[mi][ni][hf * 2 + 0] + bias[col];
                float v1 = acc[mi][ni][hf * 2 + 1] + bias[col + 1];
                if (rok) {
                    if (EPI == 2) {
                        v0 += pos[pr + col];
                        v1 += pos[pr + col + 1];
                    } else {
                        v0 += res[(long)row * Nfull + col];
                        v1 += res[(long)row * Nfull + col + 1];
                    }
                    *(float2*)&C[(long)row * Nfull + col] = make_float2(v0, v1);
                }
                acc[mi][ni][hf * 2 + 0] = v0;
                acc[mi][ni][hf * 2 + 1] = v1;
                s1[mi][hf] += v0 + v1;
                s2[mi][hf] += v0 * v0 + v1 * v1;
            }
        }
    if (lnout) {
#pragma unroll
        for (int mi = 0; mi < 2; mi++)
#pragma unroll
            for (int hf = 0; hf < 2; hf++) {
                float a = s1[mi][hf], b = s2[mi][hf];
                a += __shfl_xor_sync(~0u, a, 1);
                a += __shfl_xor_sync(~0u, a, 2);
                b += __shfl_xor_sync(~0u, b, 1);
                b += __shfl_xor_sync(~0u, b, 2);
                if ((lane & 3) == 0) {
                    int ri = wm * 32 + mi * 16 + hf * 8 + tg;
                    lnred[wn][ri][0] = a;
                    lnred[wn][ri][1] = b;
                }
            }
        __syncthreads();
#pragma unroll
        for (int mi = 0; mi < 2; mi++)
#pragma unroll
            for (int hf = 0; hf < 2; hf++) {
                int ri = wm * 32 + mi * 16 + hf * 8 + tg;
                int row = m0 + ri;
                if (row >= M) continue;
                float m1 = (lnred[0][ri][0] + lnred[1][ri][0]) * (1.f / 128.f);
                float m2 = (lnred[0][ri][1] + lnred[1][ri][1]) * (1.f / 128.f);
                float inv = rsqrtf(m2 - m1 * m1 + 1e-5f);
#pragma unroll
                for (int ni = 0; ni < 8; ni++) {
                    int col = wn * 64 + ni * 8 + tc;
                    float v0 = (acc[mi][ni][hf * 2 + 0] - m1) * inv * lnsc[col] + lnbi[col];
                    float v1 = (acc[mi][ni][hf * 2 + 1] - m1) * inv * lnsc[col + 1] + lnbi[col + 1];
                    __half hl[2] = {__float2half(v0), __float2half(v1)};
                    *(uint32_t*)&lnout[(long)row * 128 + col] = *(uint32_t*)hl;
                }
            }
    }
}

// =============== 2-stage chunked fp16 GEMM for K=512 (ff2), 2 CTAs/SM ========
#define CSTAGE_B 32768u

__global__ void __launch_bounds__(256, 2)
tgemmC(const __half* __restrict__ A, const __half* __restrict__ B,
       const float* __restrict__ bias, const float* __restrict__ res,
       float* __restrict__ C, const float* __restrict__ lnsc,
       const float* __restrict__ lnbi, __half* __restrict__ lnout,
       int M, int N, int K) {
    extern __shared__ char sm[];
    __shared__ float lnred[2][128][2];
    uint32_t sb = smem_u32(sm);
    int tid = threadIdx.x;
    int w = tid >> 5, lane = tid & 31;
    int wm = w & 3, wn = w >> 2;
    int m0 = blockIdx.y * 128, n0 = blockIdx.x * 128;
    int nk = K >> 6;

    float acc[2][8][4];
#pragma unroll
    for (int i = 0; i < 2; i++)
#pragma unroll
        for (int j = 0; j < 8; j++)
#pragma unroll
            for (int q = 0; q < 4; q++) acc[i][j][q] = 0.f;

    int rA[2], rB[4];
#pragma unroll
    for (int mi = 0; mi < 2; mi++) rA[mi] = wm * 32 + mi * 16 + (lane & 15);
#pragma unroll
    for (int ng = 0; ng < 4; ng++)
        rB[ng] = wn * 64 + ng * 16 + ((lane >> 4) << 3) + (lane & 7);
    int cA = lane >> 4;
    int cB = (lane >> 3) & 1;

    auto load_stage = [&](int c, int buf) {
#pragma unroll
        for (int it = 0; it < 8; it++) {
            int slot = it * 256 + tid;
            int t = it >> 2;
            int row = (slot >> 3) & 127;
            int chunk = slot & 7;
            const __half* src = t ? B : A;
            long grow = t ? (long)(n0 + row) : (long)(m0 + row);
            bool ok = t ? true : (m0 + row < M);
            if (!ok) grow = 0;
            const void* g = (const void*)(src + grow * K + ((long)c << 6) + chunk * 8);
            uint32_t saddr = sb + buf * CSTAGE_B + (uint32_t)t * 16384u + row * 128 +
                             ((chunk ^ (row & 7)) << 4);
            cpasync16(saddr, g, ok ? 16u : 0u);
        }
        CP_COMMIT();
    };

    load_stage(0, 0);

    for (int c = 0; c < nk; c++) {
        if (c + 1 < nk) {
            load_stage(c + 1, (c + 1) & 1);
            CP_WAIT(1);
        } else {
            CP_WAIT(0);
        }
        __syncthreads();

        uint32_t st = sb + (c & 1) * CSTAGE_B;
#pragma unroll
        for (int ks = 0; ks < 4; ks++) {
            int kc = ks * 2;
            uint32_t fa[2][4], fb[4][4];
#pragma unroll
            for (int mi = 0; mi < 2; mi++) {
                int row = rA[mi];
                ldsm4(fa[mi], st + row * 128 + ((((uint32_t)(kc + cA)) ^ (row & 7)) << 4));
            }
#pragma unroll
            for (int ng = 0; ng < 4; ng++) {
                int row = rB[ng];
                ldsm4(fb[ng], st + 16384u + row * 128 + ((((uint32_t)(kc + cB)) ^ (row & 7)) << 4));
            }
#pragma unroll
            for (int ng = 0; ng < 4; ng++)
#pragma unroll
                for (int mi = 0; mi < 2; mi++) {
                    mma16816(acc[mi][ng * 2],     fa[mi], fb[ng][0], fb[ng][1]);
                    mma16816(acc[mi][ng * 2 + 1], fa[mi], fb[ng][2], fb[ng][3]);
                }
        }
        __syncthreads();   // buffer (c&1) free before load c+2 overwrites it
    }

    int tg = lane >> 2;
    int tc = (lane & 3) * 2;
    float s1[2][2] = {}, s2[2][2] = {};
#pragma unroll
    for (int mi = 0; mi < 2; mi++)
#pragma unroll
        for (int hf = 0; hf < 2; hf++) {
            int row = m0 + wm * 32 + mi * 16 + hf * 8 + tg;
            bool rok = row < M;
#pragma unroll
            for (int ni = 0; ni < 8; ni++) {
                int col = n0 + wn * 64 + ni * 8 + tc;
                float v0 = acc[mi][ni][hf * 2 + 0] + bias[col];
                float v1 = acc[mi][ni][hf * 2 + 1] + bias[col + 1];
                if (rok) {
                    v0 += res[(long)row * N + col];
                    v1 += res[(long)row * N + col + 1];
                    *(float2*)&C[(long)row * N + col] = make_float2(v0, v1);
                }
                acc[mi][ni][hf * 2 + 0] = v0;
                acc[mi][ni][hf * 2 + 1] = v1;
                s1[mi][hf] += v0 + v1;
                s2[mi][hf] += v0 * v0 + v1 * v1;
            }
        }
    if (lnout && lnsc) {
#pragma unroll
        for (int mi = 0; mi < 2; mi++)
#pragma unroll
            for (int hf = 0; hf < 2; hf++) {
                float a = s1[mi][hf], b = s2[mi][hf];
                a += __shfl_xor_sync(~0u, a, 1);
                a += __shfl_xor_sync(~0u, a, 2);
                b += __shfl_xor_sync(~0u, b, 1);
                b += __shfl_xor_sync(~0u, b, 2);
                if ((lane & 3) == 0) {
                    int ri = wm * 32 + mi * 16 + hf * 8 + tg;
                    lnred[wn][ri][0] = a;
                    lnred[wn][ri][1] = b;
                }
            }
        __syncthreads();
#pragma unroll
        for (int mi = 0; mi < 2; mi++)
#pragma unroll
            for (int hf = 0; hf < 2; hf++) {
                int ri = wm * 32 + mi * 16 + hf * 8 + tg;
                int row = m0 + ri;
                if (row >= M) continue;
                float m1 = (lnred[0][ri][0] + lnred[1][ri][0]) * (1.f / 128.f);
                float m2 = (lnred[0][ri][1] + lnred[1][ri][1]) * (1.f / 128.f);
                float inv = rsqrtf(m2 - m1 * m1 + 1e-5f);
#pragma unroll
                for (int ni = 0; ni < 8; ni++) {
                    int col = wn * 64 + ni * 8 + tc;
                    float v0 = (acc[mi][ni][hf * 2 + 0] - m1) * inv * lnsc[col] + lnbi[col];
                    float v1 = (acc[mi][ni][hf * 2 + 1] - m1) * inv * lnsc[col + 1] + lnbi[col + 1];
                    __half hl[2] = {__float2half(v0), __float2half(v1)};
                    *(uint32_t*)&lnout[(long)row * 128 + col] = *(uint32_t*)hl;
                }
            }
    } else if (lnout) {
#pragma unroll
        for (int mi = 0; mi < 2; mi++)
#pragma unroll
            for (int hf = 0; hf < 2; hf++) {
                int row = m0 + wm * 32 + mi * 16 + hf * 8 + tg;
                if (row >= M) continue;
#pragma unroll
                for (int ni = 0; ni < 8; ni++) {
                    int col = n0 + wn * 64 + ni * 8 + tc;
                    __half hl[2] = {__float2half(acc[mi][ni][hf * 2 + 0]),
                                    __float2half(acc[mi][ni][hf * 2 + 1])};
                    *(uint32_t*)&lnout[(long)row * 128 + col] = *(uint32_t*)hl;
                }
            }
    }
}

// ---------------- MMA local windowed attention --------------------------------
__global__ void __launch_bounds__(256, 2)
attn_k(const __half* __restrict__ qkv, __half* __restrict__ o) {
    __shared__ __half q_s[64 * 24];
    __shared__ __half k_s[192 * 24];
    __shared__ __half v_s[192 * 24];
    __shared__ float ms_s[2][4][16];
    __shared__ float ls_s[2][4][16];
    __shared__ float osum[2][4][16][16];
    int w = blockIdx.x, bh = blockIdx.y;
    int b = bh >> 3, h = bh & 7;
    int tid = threadIdx.x, warp = tid >> 5, lane = tid & 31;
    int wm = warp & 3, wn = warp >> 2;
    int jstart = (w > 0) ? 0 : S1;
    int jend = (w < S1 - 1) ? 3 * S1 : 2 * S1;
    int cnt = jend - jstart;
    long rb = (long)b * SEQ;
    const uint4* qg = (const uint4*)qkv;

    int total = S1 + 2 * cnt;
    for (int idx = tid; idx < total; idx += 256) {
        if (idx < S1) {
            long grow = (rb + (long)w * S1 + idx) * 48 + h * 2;
            uint4 a = qg[grow], c = qg[grow + 1];
            *(uint4*)&q_s[idx * 24] = a;
            *(uint4*)&q_s[idx * 24 + 8] = c;
        } else {
            int r = idx - S1;
            int which = (r >= cnt);
            int jl = which ? r - cnt : r;
            long grow = (rb + (long)(w - 1) * S1 + jstart + jl) * 48 + h * 2 + (which ? 32 : 16);
            uint4 a = qg[grow], c = qg[grow + 1];
            __half* dst = (which ? v_s : k_s) + jl * 24;
            *(uint4*)dst = a;
            *(uint4*)&dst[8] = c;
        }
    }
    if (tid < 9) *(uint4*)&q_s[61 * 24 + tid * 8] = make_uint4(0, 0, 0, 0);
    for (int r = cnt + tid; r < 192; r += 256) {
        uint4 z = make_uint4(0, 0, 0, 0);
        *(uint4*)&k_s[r * 24] = z;
        *(uint4*)&k_s[r * 24 + 8] = z;
        *(uint4*)&v_s[r * 24] = z;
        *(uint4*)&v_s[r * 24 + 8] = z;
    }
    __syncthreads();

    uint32_t qb = smem_u32(q_s), kbb = smem_u32(k_s), vbb = smem_u32(v_s);

    uint32_t a[4];
    ldsm4(a, qb + (uint32_t)(wm * 16 + ((lane >> 3) & 1) * 8 + (lane & 7)) * 48 + (lane >> 4) * 16);

    float s[12][4];
#pragma unroll
    for (int ti = 0; ti < 12; ti++)
#pragma unroll
        for (int e = 0; e < 4; e++) s[ti][e] = 0.f;
#pragma unroll
    for (int g = 0; g < 6; g++) {
        uint32_t r[4];
        ldsm4(r, kbb + (uint32_t)(wn * 96 + g * 16 + (lane >> 4) * 8 + (lane & 7)) * 48 +
                   ((lane >> 3) & 1) * 16);
        mma16816(s[g * 2],     a, r[0], r[1]);
        mma16816(s[g * 2 + 1], a, r[2], r[3]);
    }

    float mloc[2] = {-1e30f, -1e30f};
#pragma unroll
    for (int ti = 0; ti < 12; ti++) {
        int cbase = wn * 96 + ti * 8 + (lane & 3) * 2;
#pragma unroll
        for (int e = 0; e < 4; e++) {
            int col = cbase + (e & 1);
            float v = (col < cnt) ? s[ti][e] * 0.25f : -1e30f;
            s[ti][e] = v;
            mloc[e >> 1] = fmaxf(mloc[e >> 1], v);
        }
    }
#pragma unroll
    for (int i = 0; i < 2; i++) {
        mloc[i] = fmaxf(mloc[i], __shfl_xor_sync(~0u, mloc[i], 1));
        mloc[i] = fmaxf(mloc[i], __shfl_xor_sync(~0u, mloc[i], 2));
    }
    if ((lane & 3) == 0) {
        ms_s[wn][wm][lane >> 2] = mloc[0];
        ms_s[wn][wm][(lane >> 2) + 8] = mloc[1];
    }
    __syncthreads();
    float m0 = fmaxf(ms_s[0][wm][lane >> 2], ms_s[1][wm][lane >> 2]);
    float m1 = fmaxf(ms_s[0][wm][(lane >> 2) + 8], ms_s[1][wm][(lane >> 2) + 8]);

    float lloc[2] = {0.f, 0.f};
    uint32_t ph[12][2];
#pragma unroll
    for (int ti = 0; ti < 12; ti++) {
        float p0 = __expf(s[ti][0] - m0);
        float p1 = __expf(s[ti][1] - m0);
        float p2 = __expf(s[ti][2] - m1);
        float p3 = __expf(s[ti][3] - m1);
        lloc[0] += p0 + p1;
        lloc[1] += p2 + p3;
        __half2 h01 = __floats2half2_rn(p0, p1);
        __half2 h23 = __floats2half2_rn(p2, p3);
        ph[ti][0] = *(uint32_t*)&h01;
        ph[ti][1] = *(uint32_t*)&h23;
    }
#pragma unroll
    for (int i = 0; i < 2; i++) {
        lloc[i] += __shfl_xor_sync(~0u, lloc[i], 1);
        lloc[i] += __shfl_xor_sync(~0u, lloc[i], 2);
    }
    if ((lane & 3) == 0) {
        ls_s[wn][wm][lane >> 2] = lloc[0];
        ls_s[wn][wm][(lane >> 2) + 8] = lloc[1];
    }

    float oa[2][4] = {{0.f, 0.f, 0.f, 0.f}, {0.f, 0.f, 0.f, 0.f}};
#pragma unroll
    for (int g = 0; g < 6; g++) {
        uint32_t r[4];
        ldsm4t(r, vbb + (uint32_t)(wn * 96 + g * 16 + ((lane >> 3) & 1) * 8 + (lane & 7)) * 48 +
                    (lane >> 4) * 16);
        uint32_t pa[4] = {ph[g * 2][0], ph[g * 2][1], ph[g * 2 + 1][0], ph[g * 2 + 1][1]};
        mma16816(oa[0], pa, r[0], r[1]);
        mma16816(oa[1], pa, r[2], r[3]);
    }
    {
        int rl = lane >> 2, cc = (lane & 3) * 2;
        *(float2*)&osum[wn][wm][rl][cc]         = make_float2(oa[0][0], oa[0][1]);
        *(float2*)&osum[wn][wm][rl + 8][cc]     = make_float2(oa[0][2], oa[0][3]);
        *(float2*)&osum[wn][wm][rl][cc + 8]     = make_float2(oa[1][0], oa[1][1]);
        *(float2*)&osum[wn][wm][rl + 8][cc + 8] = make_float2(oa[1][2], oa[1][3]);
    }
    __syncthreads();

    for (int idx = tid; idx < S1 * 16; idx += 256) {
        int i = idx >> 4, d = idx & 15;
        int wmq = i >> 4, rl = i & 15;
        float val = osum[0][wmq][rl][d] + osum[1][wmq][rl][d];
        float l = ls_s[0][wmq][rl] + ls_s[1][wmq][rl];
        o[(rb + (long)w * S1 + i) * 128 + h * 16 + d] = __float2half(val / l);
    }
}

// ---------------- launch ------------------------------------------------------
extern "C" void kernel_launch(void* const* d_in, const int* in_sizes, int n_in,
                              void* d_out, int out_size) {
    const float* x      = (const float*)d_in[0];
    const float* conv_w = (const float*)d_in[1];
    const float* conv_b = (const float*)d_in[2];
    const float* lt_w   = (const float*)d_in[3];
    const float* lt_b   = (const float*)d_in[4];
    const float* pos    = (const float*)d_in[5];
    const float* ln1_s  = (const float*)d_in[6];
    const float* ln1_b  = (const float*)d_in[7];
    const float* wq     = (const float*)d_in[8];
    const float* wk     = (const float*)d_in[9];
    const float* wv     = (const float*)d_in[10];
    const float* wo     = (const float*)d_in[11];
    const float* wo_b   = (const float*)d_in[12];
    const float* ln2_s  = (const float*)d_in[13];
    const float* ln2_b  = (const float*)d_in[14];
    const float* ff_w1  = (const float*)d_in[15];
    const float* ff_b1  = (const float*)d_in[16];
    const float* ff_w2  = (const float*)d_in[17];
    const float* ff_b2  = (const float*)d_in[18];
    const float* pre_w1 = (const float*)d_in[19];
    const float* pre_b1 = (const float*)d_in[20];
    const float* pre_w2 = (const float*)d_in[21];
    const float* pre_b2 = (const float*)d_in[22];
    float* out = (float*)d_out;

    static bool attr_done = false;
    if (!attr_done) {
        cudaFuncSetAttribute(tgemmA<0,2>, cudaFuncAttributeMaxDynamicSharedMemorySize, 65536);
        cudaFuncSetAttribute(tgemmA<2,1>, cudaFuncAttributeMaxDynamicSharedMemorySize, 32768);
        cudaFuncSetAttribute(tgemmA<3,2>, cudaFuncAttributeMaxDynamicSharedMemorySize, 65536);
        cudaFuncSetAttribute(tgemmA<4,2>, cudaFuncAttributeMaxDynamicSharedMemorySize, 65536);
        cudaFuncSetAttribute(tgemmA<5,2>, cudaFuncAttributeMaxDynamicSharedMemorySize, 65536);
        cudaFuncSetAttribute(tgemmC, cudaFuncAttributeMaxDynamicSharedMemorySize, 65536);
        attr_done = true;
    }

    __half *p, *lnb, *att, *ff, *hh, *wlt, *wqkv, *woh, *wf1, *wf2, *wp1, *qkvh;
    float *h;
    cudaGetSymbolAddress((void**)&p, g_p);       cudaGetSymbolAddress((void**)&h, g_h);
    cudaGetSymbolAddress((void**)&lnb, g_ln);    cudaGetSymbolAddress((void**)&qkvh, g_qkv);
    cudaGetSymbolAddress((void**)&att, g_att);   cudaGetSymbolAddress((void**)&ff, g_ff);
    cudaGetSymbolAddress((void**)&hh, g_hh);     cudaGetSymbolAddress((void**)&wlt, g_wlt);
    cudaGetSymbolAddress((void**)&wqkv, g_wqkv); cudaGetSymbolAddress((void**)&woh, g_wo);
    cudaGetSymbolAddress((void**)&wf1, g_wf1);   cudaGetSymbolAddress((void**)&wf2, g_wf2);
    cudaGetSymbolAddress((void**)&wp1, g_wp1);

    const int M = MROWS;

    conv_prep<<<(CONV_TOTAL + PREP_TOTAL + 255) / 256, 256>>>(
        x, conv_w, conv_b, p, lt_w, wq, wk, wv, wo, ff_w1, ff_w2, pre_w1,
        wlt, wqkv, woh, wf1, wf2, wp1);
    tgemmA<2,1><<<dim3(1, MTILES), 256, 32768>>>(p, wlt, lt_b, nullptr, pos, nullptr,
                                                 h, nullptr, ln1_s, ln1_b, lnb, M, 128);

    for (int i = 0; i < NLAYER; i++) {
        tgemmA<0,2><<<dim3(3, MTILES), 256, 65536>>>(lnb, wqkv + (long)i * 49152,
            nullptr, nullptr, nullptr, nullptr, nullptr, qkvh,
            nullptr, nullptr, nullptr, M, 384);
        attn_k<<<dim3(S1, BATCH * HEADS), 256>>>(qkvh, att);
        tgemmA<3,2><<<dim3(1, MTILES), 256, 65536>>>(att, woh + (long)i * 16384,
            wo_b + i * 128, h, nullptr, nullptr, h, nullptr,
            ln2_s + i * 128, ln2_b + i * 128, lnb, M, 128);
        tgemmA<4,2><<<dim3(4, MTILES), 256, 65536>>>(lnb, wf1 + (long)i * 65536,
            ff_b1 + i * 512, nullptr, nullptr, nullptr, nullptr, ff,
            nullptr, nullptr, nullptr, M, 512);
        bool last = (i == NLAYER - 1);
        tgemmC<<<dim3(1, MTILES), 256, 65536>>>(ff, wf2 + (long)i * 65536,
            ff_b2 + i * 128, h, h,
            last ? nullptr : ln1_s + (i + 1) * 128,
            last ? nullptr : ln1_b + (i + 1) * 128,
            last ? hh : lnb, M, 128, 512);
    }

    tgemmA<5,2><<<dim3(1, MTILES), 256, 65536>>>(hh, wp1, pre_b1, nullptr, pre_b2, pre_w2,
                                                 out, nullptr, nullptr, nullptr, nullptr, M, 128);
}

// round 14
// speedup vs baseline: 3.1770x; 1.0203x over previous
#include <cuda_runtime.h>
#include <cuda_fp16.h>
#include <cstdint>
#include <math.h>

#define BATCH 16
#define S1 61
#define SEQ 3721
#define DMODEL 128
#define HEADS 8
#define DH 16
#define NLAYER 4
#define FFDIM 512
#define PCH 49
#define MROWS (BATCH * SEQ) // 59536
#define MTILES ((MROWS + 127) / 128) // 466

// ---------------------------------------------------------------- scratch
__device__ __half g_p[MROWS * 64];
__device__ float  g_h[MROWS * 128];
__device__ __half g_ln[MROWS * 128];
__device__ __half g_qkv[(size_t)MROWS * 384];
__device__ __half g_att[MROWS * 128];
__device__ __half g_ff[(size_t)MROWS * 512];
__device__ __half g_hh[MROWS * 128];
__device__ __half g_wlt[128 * 64];
__device__ __half g_wqkv[NLAYER * 384 * 128];
__device__ __half g_wo[NLAYER * 128 * 128];
__device__ __half g_wf1[NLAYER * 512 * 128];
__device__ __half g_wf2[NLAYER * 128 * 512];
__device__ __half g_wp1[128 * 128];

// ---------------------------------------------------------------- helpers
__device__ __forceinline__ uint32_t smem_u32(const void* p) {
    uint32_t a;
    asm("{ .reg .u64 t; cvta.to.shared.u64 t, %1; cvt.u32.u64 %0, t; }" : "=r"(a) : "l"(p));
    return a;
}
__device__ __forceinline__ void ldsm4(uint32_t* r, uint32_t addr) {
    asm volatile("ldmatrix.sync.aligned.m8n8.x4.shared.b16 {%0,%1,%2,%3}, [%4];"
                 : "=r"(r[0]), "=r"(r[1]), "=r"(r[2]), "=r"(r[3]) : "r"(addr));
}
__device__ __forceinline__ void ldsm4t(uint32_t* r, uint32_t addr) {
    asm volatile("ldmatrix.sync.aligned.m8n8.x4.trans.shared.b16 {%0,%1,%2,%3}, [%4];"
                 : "=r"(r[0]), "=r"(r[1]), "=r"(r[2]), "=r"(r[3]) : "r"(addr));
}
__device__ __forceinline__ void mma16816(float* c, const uint32_t* a, uint32_t b0, uint32_t b1) {
    asm volatile("mma.sync.aligned.m16n8k16.row.col.f32.f16.f16.f32 "
                 "{%0,%1,%2,%3}, {%4,%5,%6,%7}, {%8,%9}, {%0,%1,%2,%3};"
                 : "+f"(c[0]), "+f"(c[1]), "+f"(c[2]), "+f"(c[3])
                 : "r"(a[0]), "r"(a[1]), "r"(a[2]), "r"(a[3]), "r"(b0), "r"(b1));
}
__device__ __forceinline__ void cpasync16(uint32_t saddr, const void* g, uint32_t ssz) {
    asm volatile("cp.async.cg.shared.global [%0], [%1], 16, %2;"
                 :: "r"(saddr), "l"(g), "r"(ssz));
}
#define CP_COMMIT() asm volatile("cp.async.commit_group;" ::: "memory")
#define CP_WAIT(n)  asm volatile("cp.async.wait_group %0;" :: "n"(n) : "memory")

// ------------- fused conv (7x7 same + relu -> fp16) AND weight prep ----------
#define CONV_TOTAL (MROWS * 64)
#define PREP_TOTAL (8192 + 196608 + 65536 + 262144 + 262144 + 16384)
__global__ void conv_prep(const float* __restrict__ x, const float* __restrict__ cw,
                          const float* __restrict__ cb, __half* __restrict__ p,
                          const float* __restrict__ lt_w, const float* __restrict__ wq,
                          const float* __restrict__ wk, const float* __restrict__ wv,
                          const float* __restrict__ wo, const float* __restrict__ ff_w1,
                          const float* __restrict__ ff_w2, const float* __restrict__ pre_w1,
                          __half* __restrict__ wlt, __half* __restrict__ wqkv,
                          __half* __restrict__ woh, __half* __restrict__ wf1,
                          __half* __restrict__ wf2, __half* __restrict__ wp1) {
    long t = (long)blockIdx.x * blockDim.x + threadIdx.x;
    if (t < CONV_TOTAL) {
        int o = (int)(t & 63);
        float sum = 0.f;
        if (o < PCH) {
            int s = (int)(t >> 6) % SEQ;
            int b = (int)(t >> 6) / SEQ;
            int y = s / S1, xx = s % S1;
            const float* xb = x + (long)b * SEQ;
            const float* wrow = cw + o * 49;
            sum = cb[o];
#pragma unroll
            for (int dy = 0; dy < 7; dy++) {
                int iy = y + dy - 3;
                if (iy < 0 || iy >= S1) continue;
#pragma unroll
                for (int dx = 0; dx < 7; dx++) {
                    int ix = xx + dx - 3;
                    if (ix < 0 || ix >= S1) continue;
                    sum += xb[iy * S1 + ix] * wrow[dy * 7 + dx];
                }
            }
            sum = fmaxf(sum, 0.f);
        }
        p[t] = __float2half(sum);
        return;
    }
    t -= CONV_TOTAL;
    if (t >= PREP_TOTAL) return;
    if (t < 8192) {
        int n = (int)(t >> 6), kk = (int)(t & 63);
        wlt[t] = __float2half(kk < 49 ? lt_w[kk * 128 + n] : 0.f);
        return;
    }
    t -= 8192;
    if (t < 196608) {
        int l = (int)(t / 49152), r = (int)(t % 49152);
        int n = r >> 7, kk = r & 127;
        int s = n >> 7, nn = n & 127;
        const float* W = (s == 0 ? wq : s == 1 ? wk : wv) + (long)l * 16384;
        wqkv[t] = __float2half(W[kk * 128 + nn]);
        return;
    }
    t -= 196608;
    if (t < 65536) {
        int l = (int)(t / 16384), r = (int)(t % 16384);
        int n = r >> 7, kk = r & 127;
        woh[t] = __float2half(wo[(long)l * 16384 + kk * 128 + n]);
        return;
    }
    t -= 65536;
    if (t < 262144) {
        int l = (int)(t / 65536), r = (int)(t % 65536);
        int n = r >> 7, kk = r & 127;
        wf1[t] = __float2half(ff_w1[(long)l * 65536 + (long)kk * 512 + n]);
        return;
    }
    t -= 262144;
    if (t < 262144) {
        int l = (int)(t / 65536), r = (int)(t % 65536);
        int n = r / 512, kk = r % 512;
        wf2[t] = __float2half(ff_w2[(long)l * 65536 + (long)kk * 128 + n]);
        return;
    }
    t -= 262144;
    if (t < 16384) {
        int n = (int)(t >> 7), kk = (int)(t & 127);
        wp1[t] = __float2half(pre_w1[kk * 128 + n]);
    }
}

// =============== A-resident fp16 GEMM (K<=128), n-tile = blockIdx.x ==========
template <int EPI, int NK>
__global__ void __launch_bounds__(256, 2)
tgemmA(const __half* __restrict__ A, const __half* __restrict__ B,
       const float* __restrict__ bias, const float* __restrict__ res,
       const float* __restrict__ pos, const float* __restrict__ w2,
       float* __restrict__ C, __half* __restrict__ Ch,
       const float* __restrict__ lnsc, const float* __restrict__ lnbi,
       __half* __restrict__ lnout, int M, int Nfull) {
    extern __shared__ char sm[];
    __shared__ float red[2][128];
    __shared__ float lnred[2][128][2];
    uint32_t sb = smem_u32(sm);
    const int K = NK * 64;
    const uint32_t ABYTES = (uint32_t)NK * 16384u;
    int tid = threadIdx.x;
    int w = tid >> 5, lane = tid & 31;
    int wm = w & 3, wn = w >> 2;
    int m0 = blockIdx.y * 128;
    int nt = blockIdx.x;

    int rA[2], rB[4];
#pragma unroll
    for (int mi = 0; mi < 2; mi++) rA[mi] = wm * 32 + mi * 16 + (lane & 15);
#pragma unroll
    for (int ng = 0; ng < 4; ng++)
        rB[ng] = wn * 64 + ng * 16 + ((lane >> 4) << 3) + (lane & 7);
    int cA = lane >> 4;
    int cB = (lane >> 3) & 1;

#pragma unroll
    for (int chunk = 0; chunk < NK; chunk++) {
#pragma unroll
        for (int t = 0; t < 4; t++) {
            int idx = t * 256 + tid;
            int row = idx >> 3, c16 = idx & 7;
            uint32_t soff = row * 128 + (((uint32_t)c16 ^ (row & 7)) << 4);
            long ga = m0 + row;
            bool ok = ga < M;
            if (!ok) ga = 0;
            cpasync16(sb + (uint32_t)chunk * 16384u + soff,
                      A + ga * K + chunk * 64 + c16 * 8, ok ? 16u : 0u);
            long gb = (long)(nt * 128 + row);
            cpasync16(sb + ABYTES + (uint32_t)chunk * 16384u + soff,
                      B + gb * K + chunk * 64 + c16 * 8, 16u);
        }
        CP_COMMIT();
    }

    float acc[2][8][4];
#pragma unroll
    for (int i = 0; i < 2; i++)
#pragma unroll
        for (int j = 0; j < 8; j++)
#pragma unroll
            for (int q = 0; q < 4; q++) acc[i][j][q] = 0.f;

#pragma unroll
    for (int chunk = 0; chunk < NK; chunk++) {
        if (NK == 2 && chunk == 0) CP_WAIT(1);
        else CP_WAIT(0);
        __syncthreads();
        uint32_t Ab = sb + (uint32_t)chunk * 16384u;
        uint32_t Bb = sb + ABYTES + (uint32_t)chunk * 16384u;
#pragma unroll
        for (int ks = 0; ks < 4; ks++) {
            int kc = ks * 2;
            uint32_t fa[2][4], fb[4][4];
#pragma unroll
            for (int mi = 0; mi < 2; mi++) {
                int row = rA[mi];
                ldsm4(fa[mi], Ab + row * 128 + ((((uint32_t)(kc + cA)) ^ (row & 7)) << 4));
            }
#pragma unroll
            for (int ng = 0; ng < 4; ng++) {
                int row = rB[ng];
                ldsm4(fb[ng], Bb + row * 128 + ((((uint32_t)(kc + cB)) ^ (row & 7)) << 4));
            }
#pragma unroll
            for (int ng = 0; ng < 4; ng++)
#pragma unroll
                for (int mi = 0; mi < 2; mi++) {
                    mma16816(acc[mi][ng * 2],     fa[mi], fb[ng][0], fb[ng][1]);
                    mma16816(acc[mi][ng * 2 + 1], fa[mi], fb[ng][2], fb[ng][3]);
                }
        }
    }
    __syncthreads();

    int n0 = nt * 128;
    int tg = lane >> 2;
    int tc = (lane & 3) * 2;

    if (EPI == 5) {
        float p[2][2] = {};
#pragma unroll
        for (int mi = 0; mi < 2; mi++)
#pragma unroll
            for (int ni = 0; ni < 8; ni++) {
                int col = wn * 64 + ni * 8 + tc;
                float b0 = bias[col], b1 = bias[col + 1];
                float w20 = w2[col], w21 = w2[col + 1];
                p[mi][0] += fmaxf(acc[mi][ni][0] + b0, 0.f) * w20 +
                            fmaxf(acc[mi][ni][1] + b1, 0.f) * w21;
                p[mi][1] += fmaxf(acc[mi][ni][2] + b0, 0.f) * w20 +
                            fmaxf(acc[mi][ni][3] + b1, 0.f) * w21;
            }
#pragma unroll
        for (int mi = 0; mi < 2; mi++)
#pragma unroll
            for (int hf = 0; hf < 2; hf++) {
                float v = p[mi][hf];
                v += __shfl_xor_sync(~0u, v, 1);
                v += __shfl_xor_sync(~0u, v, 2);
                if ((lane & 3) == 0) red[wn][wm * 32 + mi * 16 + hf * 8 + tg] = v;
            }
        __syncthreads();
        if (tid < 128) {
            int row = m0 + tid;
            if (row < M) C[row] = red[0][tid] + red[1][tid] + pos[0];
        }
        return;
    }

    if (EPI == 0 || EPI == 4) {
#pragma unroll
        for (int mi = 0; mi < 2; mi++)
#pragma unroll
            for (int hf = 0; hf < 2; hf++) {
                int row = m0 + wm * 32 + mi * 16 + hf * 8 + tg;
                if (row >= M) continue;
#pragma unroll
                for (int ni = 0; ni < 8; ni++) {
                    int col = n0 + wn * 64 + ni * 8 + tc;
                    float v0 = acc[mi][ni][hf * 2 + 0];
                    float v1 = acc[mi][ni][hf * 2 + 1];
                    if (EPI == 4) {
                        v0 += bias[col];
                        v1 += bias[col + 1];
                        v0 = 0.5f * v0 * (1.f + erff(v0 * 0.70710678118654752f));
                        v1 = 0.5f * v1 * (1.f + erff(v1 * 0.70710678118654752f));
                    }
                    __half hl[2] = {__float2half(v0), __float2half(v1)};
                    *(uint32_t*)&Ch[(long)row * Nfull + col] = *(uint32_t*)hl;
                }
            }
        return;
    }

    // EPI 2/3
    float s1[2][2] = {}, s2[2][2] = {};
#pragma unroll
    for (int mi = 0; mi < 2; mi++)
#pragma unroll
        for (int hf = 0; hf < 2; hf++) {
            int row = m0 + wm * 32 + mi * 16 + hf * 8 + tg;
            bool rok = row < M;
            long pr = (EPI == 2 && rok) ? (long)(row % SEQ) * 128 : 0;
#pragma unroll
            for (int ni = 0; ni < 8; ni++) {
                int col = n0 + wn * 64 + ni * 8 + tc;
                float v0 = acc[mi][ni][hf * 2 + 0] + bias[col];
                float v1 = acc[mi][ni][hf * 2 + 1] + bias[col + 1];
                if (rok) {
                    if (EPI == 2) {
                        v0 += pos[pr + col];
                        v1 += pos[pr + col + 1];
                    } else {
                        v0 += res[(long)row * Nfull + col];
                        v1 += res[(long)row * Nfull + col + 1];
                    }
                    *(float2*)&C[(long)row * Nfull + col] = make_float2(v0, v1);
                }
                acc[mi][ni][hf * 2 + 0] = v0;
                acc[mi][ni][hf * 2 + 1] = v1;
                s1[mi][hf] += v0 + v1;
                s2[mi][hf] += v0 * v0 + v1 * v1;
            }
        }
    if (lnout) {
#pragma unroll
        for (int mi = 0; mi < 2; mi++)
#pragma unroll
            for (int hf = 0; hf < 2; hf++) {
                float a = s1[mi][hf], b = s2[mi][hf];
                a += __shfl_xor_sync(~0u, a, 1);
                a += __shfl_xor_sync(~0u, a, 2);
                b += __shfl_xor_sync(~0u, b, 1);
                b += __shfl_xor_sync(~0u, b, 2);
                if ((lane & 3) == 0) {
                    int ri = wm * 32 + mi * 16 + hf * 8 + tg;
                    lnred[wn][ri][0] = a;
                    lnred[wn][ri][1] = b;
                }
            }
        __syncthreads();
#pragma unroll
        for (int mi = 0; mi < 2; mi++)
#pragma unroll
            for (int hf = 0; hf < 2; hf++) {
                int ri = wm * 32 + mi * 16 + hf * 8 + tg;
                int row = m0 + ri;
                if (row >= M) continue;
                float m1 = (lnred[0][ri][0] + lnred[1][ri][0]) * (1.f / 128.f);
                float m2 = (lnred[0][ri][1] + lnred[1][ri][1]) * (1.f / 128.f);
                float inv = rsqrtf(m2 - m1 * m1 + 1e-5f);
#pragma unroll
                for (int ni = 0; ni < 8; ni++) {
                    int col = wn * 64 + ni * 8 + tc;
                    float v0 = (acc[mi][ni][hf * 2 + 0] - m1) * inv * lnsc[col] + lnbi[col];
                    float v1 = (acc[mi][ni][hf * 2 + 1] - m1) * inv * lnsc[col + 1] + lnbi[col + 1];
                    __half hl[2] = {__float2half(v0), __float2half(v1)};
                    *(uint32_t*)&lnout[(long)row * 128 + col] = *(uint32_t*)hl;
                }
            }
    }
}

// =============== 2-stage chunked fp16 GEMM for K=512 (ff2), 2 CTAs/SM ========
#define CSTAGE_B 32768u

__global__ void __launch_bounds__(256, 2)
tgemmC(const __half* __restrict__ A, const __half* __restrict__ B,
       const float* __restrict__ bias, const float* __restrict__ res,
       float* __restrict__ C, const float* __restrict__ lnsc,
       const float* __restrict__ lnbi, __half* __restrict__ lnout,
       int M, int N, int K) {
    extern __shared__ char sm[];
    __shared__ float lnred[2][128][2];
    uint32_t sb = smem_u32(sm);
    int tid = threadIdx.x;
    int w = tid >> 5, lane = tid & 31;
    int wm = w & 3, wn = w >> 2;
    int m0 = blockIdx.y * 128, n0 = blockIdx.x * 128;
    int nk = K >> 6;

    float acc[2][8][4];
#pragma unroll
    for (int i = 0; i < 2; i++)
#pragma unroll
        for (int j = 0; j < 8; j++)
#pragma unroll
            for (int q = 0; q < 4; q++) acc[i][j][q] = 0.f;

    int rA[2], rB[4];
#pragma unroll
    for (int mi = 0; mi < 2; mi++) rA[mi] = wm * 32 + mi * 16 + (lane & 15);
#pragma unroll
    for (int ng = 0; ng < 4; ng++)
        rB[ng] = wn * 64 + ng * 16 + ((lane >> 4) << 3) + (lane & 7);
    int cA = lane >> 4;
    int cB = (lane >> 3) & 1;

    auto load_stage = [&](int c, int buf) {
#pragma unroll
        for (int it = 0; it < 8; it++) {
            int slot = it * 256 + tid;
            int t = it >> 2;
            int row = (slot >> 3) & 127;
            int chunk = slot & 7;
            const __half* src = t ? B : A;
            long grow = t ? (long)(n0 + row) : (long)(m0 + row);
            bool ok = t ? true : (m0 + row < M);
            if (!ok) grow = 0;
            const void* g = (const void*)(src + grow * K + ((long)c << 6) + chunk * 8);
            uint32_t saddr = sb + buf * CSTAGE_B + (uint32_t)t * 16384u + row * 128 +
                             ((chunk ^ (row & 7)) << 4);
            cpasync16(saddr, g, ok ? 16u : 0u);
        }
        CP_COMMIT();
    };

    load_stage(0, 0);

    for (int c = 0; c < nk; c++) {
        if (c + 1 < nk) {
            load_stage(c + 1, (c + 1) & 1);
            CP_WAIT(1);
        } else {
            CP_WAIT(0);
        }
        __syncthreads();

        uint32_t st = sb + (c & 1) * CSTAGE_B;
#pragma unroll
        for (int ks = 0; ks < 4; ks++) {
            int kc = ks * 2;
            uint32_t fa[2][4], fb[4][4];
#pragma unroll
            for (int mi = 0; mi < 2; mi++) {
                int row = rA[mi];
                ldsm4(fa[mi], st + row * 128 + ((((uint32_t)(kc + cA)) ^ (row & 7)) << 4));
            }
#pragma unroll
            for (int ng = 0; ng < 4; ng++) {
                int row = rB[ng];
                ldsm4(fb[ng], st + 16384u + row * 128 + ((((uint32_t)(kc + cB)) ^ (row & 7)) << 4));
            }
#pragma unroll
            for (int ng = 0; ng < 4; ng++)
#pragma unroll
                for (int mi = 0; mi < 2; mi++) {
                    mma16816(acc[mi][ng * 2],     fa[mi], fb[ng][0], fb[ng][1]);
                    mma16816(acc[mi][ng * 2 + 1], fa[mi], fb[ng][2], fb[ng][3]);
                }
        }
        __syncthreads();
    }

    int tg = lane >> 2;
    int tc = (lane & 3) * 2;
    float s1[2][2] = {}, s2[2][2] = {};
#pragma unroll
    for (int mi = 0; mi < 2; mi++)
#pragma unroll
        for (int hf = 0; hf < 2; hf++) {
            int row = m0 + wm * 32 + mi * 16 + hf * 8 + tg;
            bool rok = row < M;
#pragma unroll
            for (int ni = 0; ni < 8; ni++) {
                int col = n0 + wn * 64 + ni * 8 + tc;
                float v0 = acc[mi][ni][hf * 2 + 0] + bias[col];
                float v1 = acc[mi][ni][hf * 2 + 1] + bias[col + 1];
                if (rok) {
                    v0 += res[(long)row * N + col];
                    v1 += res[(long)row * N + col + 1];
                    *(float2*)&C[(long)row * N + col] = make_float2(v0, v1);
                }
                acc[mi][ni][hf * 2 + 0] = v0;
                acc[mi][ni][hf * 2 + 1] = v1;
                s1[mi][hf] += v0 + v1;
                s2[mi][hf] += v0 * v0 + v1 * v1;
            }
        }
    if (lnout && lnsc) {
#pragma unroll
        for (int mi = 0; mi < 2; mi++)
#pragma unroll
            for (int hf = 0; hf < 2; hf++) {
                float a = s1[mi][hf], b = s2[mi][hf];
                a += __shfl_xor_sync(~0u, a, 1);
                a += __shfl_xor_sync(~0u, a, 2);
                b += __shfl_xor_sync(~0u, b, 1);
                b += __shfl_xor_sync(~0u, b, 2);
                if ((lane & 3) == 0) {
                    int ri = wm * 32 + mi * 16 + hf * 8 + tg;
                    lnred[wn][ri][0] = a;
                    lnred[wn][ri][1] = b;
                }
            }
        __syncthreads();
#pragma unroll
        for (int mi = 0; mi < 2; mi++)
#pragma unroll
            for (int hf = 0; hf < 2; hf++) {
                int ri = wm * 32 + mi * 16 + hf * 8 + tg;
                int row = m0 + ri;
                if (row >= M) continue;
                float m1 = (lnred[0][ri][0] + lnred[1][ri][0]) * (1.f / 128.f);
                float m2 = (lnred[0][ri][1] + lnred[1][ri][1]) * (1.f / 128.f);
                float inv = rsqrtf(m2 - m1 * m1 + 1e-5f);
#pragma unroll
                for (int ni = 0; ni < 8; ni++) {
                    int col = wn * 64 + ni * 8 + tc;
                    float v0 = (acc[mi][ni][hf * 2 + 0] - m1) * inv * lnsc[col] + lnbi[col];
                    float v1 = (acc[mi][ni][hf * 2 + 1] - m1) * inv * lnsc[col + 1] + lnbi[col + 1];
                    __half hl[2] = {__float2half(v0), __float2half(v1)};
                    *(uint32_t*)&lnout[(long)row * 128 + col] = *(uint32_t*)hl;
                }
            }
    } else if (lnout) {
#pragma unroll
        for (int mi = 0; mi < 2; mi++)
#pragma unroll
            for (int hf = 0; hf < 2; hf++) {
                int row = m0 + wm * 32 + mi * 16 + hf * 8 + tg;
                if (row >= M) continue;
#pragma unroll
                for (int ni = 0; ni < 8; ni++) {
                    int col = n0 + wn * 64 + ni * 8 + tc;
                    __half hl[2] = {__float2half(acc[mi][ni][hf * 2 + 0]),
                                    __float2half(acc[mi][ni][hf * 2 + 1])};
                    *(uint32_t*)&lnout[(long)row * 128 + col] = *(uint32_t*)hl;
                }
            }
    }
}

// ---------------- MMA local windowed attention (branch-free staging) ---------
__global__ void __launch_bounds__(256, 3)
attn_k(const __half* __restrict__ qkv, __half* __restrict__ o) {
    __shared__ __half q_s[64 * 24];
    __shared__ __half k_s[192 * 24];
    __shared__ __half v_s[192 * 24];
    __shared__ float ms_s[2][4][16];
    __shared__ float ls_s[2][4][16];
    __shared__ float osum[2][4][16][16];
    int w = blockIdx.x, bh = blockIdx.y;
    int b = bh >> 3, h = bh & 7;
    int tid = threadIdx.x, warp = tid >> 5, lane = tid & 31;
    int wm = warp & 3, wn = warp >> 2;
    int jstart = (w > 0) ? 0 : S1;
    int jend = (w < S1 - 1) ? 3 * S1 : 2 * S1;
    int cnt = jend - jstart;
    long rb = (long)b * SEQ;
    const uint4* qg = (const uint4*)qkv;
    const uint4 z4 = make_uint4(0, 0, 0, 0);

    // --- branch-free staging: thread t handles k-row t, v-row t (t<192), q-row t (t<64)
    if (tid < 192) {
        bool ok = tid < cnt;
        long base = (rb + (long)(w - 1) * S1 + jstart + (ok ? tid : 0)) * 48 + h * 2;
        uint4 ka = ok ? qg[base + 16] : z4;
        uint4 kc = ok ? qg[base + 17] : z4;
        uint4 va = ok ? qg[base + 32] : z4;
        uint4 vc = ok ? qg[base + 33] : z4;
        *(uint4*)&k_s[tid * 24] = ka;
        *(uint4*)&k_s[tid * 24 + 8] = kc;
        *(uint4*)&v_s[tid * 24] = va;
        *(uint4*)&v_s[tid * 24 + 8] = vc;
    }
    if (tid < 64) {
        bool ok = tid < S1;
        long base = (rb + (long)w * S1 + (ok ? tid : 0)) * 48 + h * 2;
        uint4 qa = ok ? qg[base] : z4;
        uint4 qc = ok ? qg[base + 1] : z4;
        *(uint4*)&q_s[tid * 24] = qa;
        *(uint4*)&q_s[tid * 24 + 8] = qc;
    }
    __syncthreads();

    uint32_t qb = smem_u32(q_s), kbb = smem_u32(k_s), vbb = smem_u32(v_s);

    uint32_t a[4];
    ldsm4(a, qb + (uint32_t)(wm * 16 + ((lane >> 3) & 1) * 8 + (lane & 7)) * 48 + (lane >> 4) * 16);

    float s[12][4];
#pragma unroll
    for (int ti = 0; ti < 12; ti++)
#pragma unroll
        for (int e = 0; e < 4; e++) s[ti][e] = 0.f;
#pragma unroll
    for (int g = 0; g < 6; g++) {
        uint32_t r[4];
        ldsm4(r, kbb + (uint32_t)(wn * 96 + g * 16 + (lane >> 4) * 8 + (lane & 7)) * 48 +
                   ((lane >> 3) & 1) * 16);
        mma16816(s[g * 2],     a, r[0], r[1]);
        mma16816(s[g * 2 + 1], a, r[2], r[3]);
    }

    float mloc[2] = {-1e30f, -1e30f};
#pragma unroll
    for (int ti = 0; ti < 12; ti++) {
        int cbase = wn * 96 + ti * 8 + (lane & 3) * 2;
#pragma unroll
        for (int e = 0; e < 4; e++) {
            int col = cbase + (e & 1);
            float v = (col < cnt) ? s[ti][e] * 0.25f : -1e30f;
            s[ti][e] = v;
            mloc[e >> 1] = fmaxf(mloc[e >> 1], v);
        }
    }
#pragma unroll
    for (int i = 0; i < 2; i++) {
        mloc[i] = fmaxf(mloc[i], __shfl_xor_sync(~0u, mloc[i], 1));
        mloc[i] = fmaxf(mloc[i], __shfl_xor_sync(~0u, mloc[i], 2));
    }
    if ((lane & 3) == 0) {
        ms_s[wn][wm][lane >> 2] = mloc[0];
        ms_s[wn][wm][(lane >> 2) + 8] = mloc[1];
    }
    __syncthreads();
    float m0 = fmaxf(ms_s[0][wm][lane >> 2], ms_s[1][wm][lane >> 2]);
    float m1 = fmaxf(ms_s[0][wm][(lane >> 2) + 8], ms_s[1][wm][(lane >> 2) + 8]);

    float lloc[2] = {0.f, 0.f};
    uint32_t ph[12][2];
#pragma unroll
    for (int ti = 0; ti < 12; ti++) {
        float p0 = __expf(s[ti][0] - m0);
        float p1 = __expf(s[ti][1] - m0);
        float p2 = __expf(s[ti][2] - m1);
        float p3 = __expf(s[ti][3] - m1);
        lloc[0] += p0 + p1;
        lloc[1] += p2 + p3;
        __half2 h01 = __floats2half2_rn(p0, p1);
        __half2 h23 = __floats2half2_rn(p2, p3);
        ph[ti][0] = *(uint32_t*)&h01;
        ph[ti][1] = *(uint32_t*)&h23;
    }
#pragma unroll
    for (int i = 0; i < 2; i++) {
        lloc[i] += __shfl_xor_sync(~0u, lloc[i], 1);
        lloc[i] += __shfl_xor_sync(~0u, lloc[i], 2);
    }
    if ((lane & 3) == 0) {
        ls_s[wn][wm][lane >> 2] = lloc[0];
        ls_s[wn][wm][(lane >> 2) + 8] = lloc[1];
    }

    float oa[2][4] = {{0.f, 0.f, 0.f, 0.f}, {0.f, 0.f, 0.f, 0.f}};
#pragma unroll
    for (int g = 0; g < 6; g++) {
        uint32_t r[4];
        ldsm4t(r, vbb + (uint32_t)(wn * 96 + g * 16 + ((lane >> 3) & 1) * 8 + (lane & 7)) * 48 +
                    (lane >> 4) * 16);
        uint32_t pa[4] = {ph[g * 2][0], ph[g * 2][1], ph[g * 2 + 1][0], ph[g * 2 + 1][1]};
        mma16816(oa[0], pa, r[0], r[1]);
        mma16816(oa[1], pa, r[2], r[3]);
    }
    {
        int rl = lane >> 2, cc = (lane & 3) * 2;
        *(float2*)&osum[wn][wm][rl][cc]         = make_float2(oa[0][0], oa[0][1]);
        *(float2*)&osum[wn][wm][rl + 8][cc]     = make_float2(oa[0][2], oa[0][3]);
        *(float2*)&osum[wn][wm][rl][cc + 8]     = make_float2(oa[1][0], oa[1][1]);
        *(float2*)&osum[wn][wm][rl + 8][cc + 8] = make_float2(oa[1][2], oa[1][3]);
    }
    __syncthreads();

    for (int idx = tid; idx < S1 * 16; idx += 256) {
        int i = idx >> 4, d = idx & 15;
        int wmq = i >> 4, rl = i & 15;
        float val = osum[0][wmq][rl][d] + osum[1][wmq][rl][d];
        float l = ls_s[0][wmq][rl] + ls_s[1][wmq][rl];
        o[(rb + (long)w * S1 + i) * 128 + h * 16 + d] = __float2half(val / l);
    }
}

// ---------------- launch ------------------------------------------------------
extern "C" void kernel_launch(void* const* d_in, const int* in_sizes, int n_in,
                              void* d_out, int out_size) {
    const float* x      = (const float*)d_in[0];
    const float* conv_w = (const float*)d_in[1];
    const float* conv_b = (const float*)d_in[2];
    const float* lt_w   = (const float*)d_in[3];
    const float* lt_b   = (const float*)d_in[4];
    const float* pos    = (const float*)d_in[5];
    const float* ln1_s  = (const float*)d_in[6];
    const float* ln1_b  = (const float*)d_in[7];
    const float* wq     = (const float*)d_in[8];
    const float* wk     = (const float*)d_in[9];
    const float* wv     = (const float*)d_in[10];
    const float* wo     = (const float*)d_in[11];
    const float* wo_b   = (const float*)d_in[12];
    const float* ln2_s  = (const float*)d_in[13];
    const float* ln2_b  = (const float*)d_in[14];
    const float* ff_w1  = (const float*)d_in[15];
    const float* ff_b1  = (const float*)d_in[16];
    const float* ff_w2  = (const float*)d_in[17];
    const float* ff_b2  = (const float*)d_in[18];
    const float* pre_w1 = (const float*)d_in[19];
    const float* pre_b1 = (const float*)d_in[20];
    const float* pre_w2 = (const float*)d_in[21];
    const float* pre_b2 = (const float*)d_in[22];
    float* out = (float*)d_out;

    static bool attr_done = false;
    if (!attr_done) {
        cudaFuncSetAttribute(tgemmA<0,2>, cudaFuncAttributeMaxDynamicSharedMemorySize, 65536);
        cudaFuncSetAttribute(tgemmA<2,1>, cudaFuncAttributeMaxDynamicSharedMemorySize, 32768);
        cudaFuncSetAttribute(tgemmA<3,2>, cudaFuncAttributeMaxDynamicSharedMemorySize, 65536);
        cudaFuncSetAttribute(tgemmA<4,2>, cudaFuncAttributeMaxDynamicSharedMemorySize, 65536);
        cudaFuncSetAttribute(tgemmA<5,2>, cudaFuncAttributeMaxDynamicSharedMemorySize, 65536);
        cudaFuncSetAttribute(tgemmC, cudaFuncAttributeMaxDynamicSharedMemorySize, 65536);
        attr_done = true;
    }

    __half *p, *lnb, *att, *ff, *hh, *wlt, *wqkv, *woh, *wf1, *wf2, *wp1, *qkvh;
    float *h;
    cudaGetSymbolAddress((void**)&p, g_p);       cudaGetSymbolAddress((void**)&h, g_h);
    cudaGetSymbolAddress((void**)&lnb, g_ln);    cudaGetSymbolAddress((void**)&qkvh, g_qkv);
    cudaGetSymbolAddress((void**)&att, g_att);   cudaGetSymbolAddress((void**)&ff, g_ff);
    cudaGetSymbolAddress((void**)&hh, g_hh);     cudaGetSymbolAddress((void**)&wlt, g_wlt);
    cudaGetSymbolAddress((void**)&wqkv, g_wqkv); cudaGetSymbolAddress((void**)&woh, g_wo);
    cudaGetSymbolAddress((void**)&wf1, g_wf1);   cudaGetSymbolAddress((void**)&wf2, g_wf2);
    cudaGetSymbolAddress((void**)&wp1, g_wp1);

    const int M = MROWS;

    conv_prep<<<(CONV_TOTAL + PREP_TOTAL + 255) / 256, 256>>>(
        x, conv_w, conv_b, p, lt_w, wq, wk, wv, wo, ff_w1, ff_w2, pre_w1,
        wlt, wqkv, woh, wf1, wf2, wp1);
    tgemmA<2,1><<<dim3(1, MTILES), 256, 32768>>>(p, wlt, lt_b, nullptr, pos, nullptr,
                                                 h, nullptr, ln1_s, ln1_b, lnb, M, 128);

    for (int i = 0; i < NLAYER; i++) {
        tgemmA<0,2><<<dim3(3, MTILES), 256, 65536>>>(lnb, wqkv + (long)i * 49152,
            nullptr, nullptr, nullptr, nullptr, nullptr, qkvh,
            nullptr, nullptr, nullptr, M, 384);
        attn_k<<<dim3(S1, BATCH * HEADS), 256>>>(qkvh, att);
        tgemmA<3,2><<<dim3(1, MTILES), 256, 65536>>>(att, woh + (long)i * 16384,
            wo_b + i * 128, h, nullptr, nullptr, h, nullptr,
            ln2_s + i * 128, ln2_b + i * 128, lnb, M, 128);
        tgemmA<4,2><<<dim3(4, MTILES), 256, 65536>>>(lnb, wf1 + (long)i * 65536,
            ff_b1 + i * 512, nullptr, nullptr, nullptr, nullptr, ff,
            nullptr, nullptr, nullptr, M, 512);
        bool last = (i == NLAYER - 1);
        tgemmC<<<dim3(1, MTILES), 256, 65536>>>(ff, wf2 + (long)i * 65536,
            ff_b2 + i * 128, h, h,
            last ? nullptr : ln1_s + (i + 1) * 128,
            last ? nullptr : ln1_b + (i + 1) * 128,
            last ? hh : lnb, M, 128, 512);
    }

    tgemmA<5,2><<<dim3(1, MTILES), 256, 65536>>>(hh, wp1, pre_b1, nullptr, pre_b2, pre_w2,
                                                 out, nullptr, nullptr, nullptr, nullptr, M, 128);
}

// round 15
// speedup vs baseline: 3.4613x; 1.0895x over previous
#include <cuda_runtime.h>
#include <cuda_fp16.h>
#include <cstdint>
#include <math.h>

#define BATCH 16
#define S1 61
#define SEQ 3721
#define DMODEL 128
#define HEADS 8
#define DH 16
#define NLAYER 4
#define FFDIM 512
#define PCH 49
#define MROWS (BATCH * SEQ) // 59536
#define MTILES ((MROWS + 127) / 128) // 466

// ---------------------------------------------------------------- scratch
__device__ __half g_p[MROWS * 64];
__device__ float  g_h[MROWS * 128];
__device__ __half g_ln[MROWS * 128];
__device__ __half g_qkv[(size_t)MROWS * 384];
__device__ __half g_att[MROWS * 128];
__device__ __half g_ff[(size_t)MROWS * 512];
__device__ __half g_hh[MROWS * 128];
__device__ __half g_wlt[128 * 64];
__device__ __half g_wqkv[NLAYER * 384 * 128];
__device__ __half g_wo[NLAYER * 128 * 128];
__device__ __half g_wf1[NLAYER * 512 * 128];
__device__ __half g_wf2[NLAYER * 128 * 512];
__device__ __half g_wp1[128 * 128];

// ---------------------------------------------------------------- helpers
__device__ __forceinline__ uint32_t smem_u32(const void* p) {
    uint32_t a;
    asm("{ .reg .u64 t; cvta.to.shared.u64 t, %1; cvt.u32.u64 %0, t; }" : "=r"(a) : "l"(p));
    return a;
}
__device__ __forceinline__ void ldsm4(uint32_t* r, uint32_t addr) {
    asm volatile("ldmatrix.sync.aligned.m8n8.x4.shared.b16 {%0,%1,%2,%3}, [%4];"
                 : "=r"(r[0]), "=r"(r[1]), "=r"(r[2]), "=r"(r[3]) : "r"(addr));
}
__device__ __forceinline__ void ldsm4t(uint32_t* r, uint32_t addr) {
    asm volatile("ldmatrix.sync.aligned.m8n8.x4.trans.shared.b16 {%0,%1,%2,%3}, [%4];"
                 : "=r"(r[0]), "=r"(r[1]), "=r"(r[2]), "=r"(r[3]) : "r"(addr));
}
__device__ __forceinline__ void mma16816(float* c, const uint32_t* a, uint32_t b0, uint32_t b1) {
    asm volatile("mma.sync.aligned.m16n8k16.row.col.f32.f16.f16.f32 "
                 "{%0,%1,%2,%3}, {%4,%5,%6,%7}, {%8,%9}, {%0,%1,%2,%3};"
                 : "+f"(c[0]), "+f"(c[1]), "+f"(c[2]), "+f"(c[3])
                 : "r"(a[0]), "r"(a[1]), "r"(a[2]), "r"(a[3]), "r"(b0), "r"(b1));
}
__device__ __forceinline__ void cpasync16(uint32_t saddr, const void* g, uint32_t ssz) {
    asm volatile("cp.async.cg.shared.global [%0], [%1], 16, %2;"
                 :: "r"(saddr), "l"(g), "r"(ssz));
}
#define CP_COMMIT() asm volatile("cp.async.commit_group;" ::: "memory")
#define CP_WAIT(n)  asm volatile("cp.async.wait_group %0;" :: "n"(n) : "memory")

// ------------- fused conv (7x7 same + relu -> fp16) AND weight prep ----------
#define CONV_TOTAL (MROWS * 64)
#define PREP_TOTAL (8192 + 196608 + 65536 + 262144 + 262144 + 16384)
__global__ void conv_prep(const float* __restrict__ x, const float* __restrict__ cw,
                          const float* __restrict__ cb, __half* __restrict__ p,
                          const float* __restrict__ lt_w, const float* __restrict__ wq,
                          const float* __restrict__ wk, const float* __restrict__ wv,
                          const float* __restrict__ wo, const float* __restrict__ ff_w1,
                          const float* __restrict__ ff_w2, const float* __restrict__ pre_w1,
                          __half* __restrict__ wlt, __half* __restrict__ wqkv,
                          __half* __restrict__ woh, __half* __restrict__ wf1,
                          __half* __restrict__ wf2, __half* __restrict__ wp1) {
    long t = (long)blockIdx.x * blockDim.x + threadIdx.x;
    if (t < CONV_TOTAL) {
        int o = (int)(t & 63);
        float sum = 0.f;
        if (o < PCH) {
            int s = (int)(t >> 6) % SEQ;
            int b = (int)(t >> 6) / SEQ;
            int y = s / S1, xx = s % S1;
            const float* xb = x + (long)b * SEQ;
            const float* wrow = cw + o * 49;
            sum = cb[o];
#pragma unroll
            for (int dy = 0; dy < 7; dy++) {
                int iy = y + dy - 3;
                if (iy < 0 || iy >= S1) continue;
#pragma unroll
                for (int dx = 0; dx < 7; dx++) {
                    int ix = xx + dx - 3;
                    if (ix < 0 || ix >= S1) continue;
                    sum += xb[iy * S1 + ix] * wrow[dy * 7 + dx];
                }
            }
            sum = fmaxf(sum, 0.f);
        }
        p[t] = __float2half(sum);
        return;
    }
    t -= CONV_TOTAL;
    if (t >= PREP_TOTAL) return;
    if (t < 8192) {
        int n = (int)(t >> 6), kk = (int)(t & 63);
        wlt[t] = __float2half(kk < 49 ? lt_w[kk * 128 + n] : 0.f);
        return;
    }
    t -= 8192;
    if (t < 196608) {
        int l = (int)(t / 49152), r = (int)(t % 49152);
        int n = r >> 7, kk = r & 127;
        int s = n >> 7, nn = n & 127;
        const float* W = (s == 0 ? wq : s == 1 ? wk : wv) + (long)l * 16384;
        wqkv[t] = __float2half(W[kk * 128 + nn]);
        return;
    }
    t -= 196608;
    if (t < 65536) {
        int l = (int)(t / 16384), r = (int)(t % 16384);
        int n = r >> 7, kk = r & 127;
        woh[t] = __float2half(wo[(long)l * 16384 + kk * 128 + n]);
        return;
    }
    t -= 65536;
    if (t < 262144) {
        int l = (int)(t / 65536), r = (int)(t % 65536);
        int n = r >> 7, kk = r & 127;
        wf1[t] = __float2half(ff_w1[(long)l * 65536 + (long)kk * 512 + n]);
        return;
    }
    t -= 262144;
    if (t < 262144) {
        int l = (int)(t / 65536), r = (int)(t % 65536);
        int n = r / 512, kk = r % 512;
        wf2[t] = __float2half(ff_w2[(long)l * 65536 + (long)kk * 128 + n]);
        return;
    }
    t -= 262144;
    if (t < 16384) {
        int n = (int)(t >> 7), kk = (int)(t & 127);
        wp1[t] = __float2half(pre_w1[kk * 128 + n]);
    }
}

// =============== A-resident fp16 GEMM (K<=128), n-tile = blockIdx.x ==========
// EPI 0: fp16 out; qkv variant scales block nt==0 (Q columns) by 0.25.
template <int EPI, int NK>
__global__ void __launch_bounds__(256, 2)
tgemmA(const __half* __restrict__ A, const __half* __restrict__ B,
       const float* __restrict__ bias, const float* __restrict__ res,
       const float* __restrict__ pos, const float* __restrict__ w2,
       float* __restrict__ C, __half* __restrict__ Ch,
       const float* __restrict__ lnsc, const float* __restrict__ lnbi,
       __half* __restrict__ lnout, int M, int Nfull) {
    extern __shared__ char sm[];
    __shared__ float red[2][128];
    __shared__ float lnred[2][128][2];
    uint32_t sb = smem_u32(sm);
    const int K = NK * 64;
    const uint32_t ABYTES = (uint32_t)NK * 16384u;
    int tid = threadIdx.x;
    int w = tid >> 5, lane = tid & 31;
    int wm = w & 3, wn = w >> 2;
    int m0 = blockIdx.y * 128;
    int nt = blockIdx.x;

    int rA[2], rB[4];
#pragma unroll
    for (int mi = 0; mi < 2; mi++) rA[mi] = wm * 32 + mi * 16 + (lane & 15);
#pragma unroll
    for (int ng = 0; ng < 4; ng++)
        rB[ng] = wn * 64 + ng * 16 + ((lane >> 4) << 3) + (lane & 7);
    int cA = lane >> 4;
    int cB = (lane >> 3) & 1;

#pragma unroll
    for (int chunk = 0; chunk < NK; chunk++) {
#pragma unroll
        for (int t = 0; t < 4; t++) {
            int idx = t * 256 + tid;
            int row = idx >> 3, c16 = idx & 7;
            uint32_t soff = row * 128 + (((uint32_t)c16 ^ (row & 7)) << 4);
            long ga = m0 + row;
            bool ok = ga < M;
            if (!ok) ga = 0;
            cpasync16(sb + (uint32_t)chunk * 16384u + soff,
                      A + ga * K + chunk * 64 + c16 * 8, ok ? 16u : 0u);
            long gb = (long)(nt * 128 + row);
            cpasync16(sb + ABYTES + (uint32_t)chunk * 16384u + soff,
                      B + gb * K + chunk * 64 + c16 * 8, 16u);
        }
        CP_COMMIT();
    }

    float acc[2][8][4];
#pragma unroll
    for (int i = 0; i < 2; i++)
#pragma unroll
        for (int j = 0; j < 8; j++)
#pragma unroll
            for (int q = 0; q < 4; q++) acc[i][j][q] = 0.f;

#pragma unroll
    for (int chunk = 0; chunk < NK; chunk++) {
        if (NK == 2 && chunk == 0) CP_WAIT(1);
        else CP_WAIT(0);
        __syncthreads();
        uint32_t Ab = sb + (uint32_t)chunk * 16384u;
        uint32_t Bb = sb + ABYTES + (uint32_t)chunk * 16384u;
#pragma unroll
        for (int ks = 0; ks < 4; ks++) {
            int kc = ks * 2;
            uint32_t fa[2][4], fb[4][4];
#pragma unroll
            for (int mi = 0; mi < 2; mi++) {
                int row = rA[mi];
                ldsm4(fa[mi], Ab + row * 128 + ((((uint32_t)(kc + cA)) ^ (row & 7)) << 4));
            }
#pragma unroll
            for (int ng = 0; ng < 4; ng++) {
                int row = rB[ng];
                ldsm4(fb[ng], Bb + row * 128 + ((((uint32_t)(kc + cB)) ^ (row & 7)) << 4));
            }
#pragma unroll
            for (int ng = 0; ng < 4; ng++)
#pragma unroll
                for (int mi = 0; mi < 2; mi++) {
                    mma16816(acc[mi][ng * 2],     fa[mi], fb[ng][0], fb[ng][1]);
                    mma16816(acc[mi][ng * 2 + 1], fa[mi], fb[ng][2], fb[ng][3]);
                }
        }
    }
    __syncthreads();

    int n0 = nt * 128;
    int tg = lane >> 2;
    int tc = (lane & 3) * 2;

    if (EPI == 5) {
        float p[2][2] = {};
#pragma unroll
        for (int mi = 0; mi < 2; mi++)
#pragma unroll
            for (int ni = 0; ni < 8; ni++) {
                int col = wn * 64 + ni * 8 + tc;
                float b0 = bias[col], b1 = bias[col + 1];
                float w20 = w2[col], w21 = w2[col + 1];
                p[mi][0] += fmaxf(acc[mi][ni][0] + b0, 0.f) * w20 +
                            fmaxf(acc[mi][ni][1] + b1, 0.f) * w21;
                p[mi][1] += fmaxf(acc[mi][ni][2] + b0, 0.f) * w20 +
                            fmaxf(acc[mi][ni][3] + b1, 0.f) * w21;
            }
#pragma unroll
        for (int mi = 0; mi < 2; mi++)
#pragma unroll
            for (int hf = 0; hf < 2; hf++) {
                float v = p[mi][hf];
                v += __shfl_xor_sync(~0u, v, 1);
                v += __shfl_xor_sync(~0u, v, 2);
                if ((lane & 3) == 0) red[wn][wm * 32 + mi * 16 + hf * 8 + tg] = v;
            }
        __syncthreads();
        if (tid < 128) {
            int row = m0 + tid;
            if (row < M) C[row] = red[0][tid] + red[1][tid] + pos[0];
        }
        return;
    }

    if (EPI == 0 || EPI == 4) {
        float scale = (EPI == 0 && nt == 0) ? 0.25f : 1.f;   // fold q-scale into Q
#pragma unroll
        for (int mi = 0; mi < 2; mi++)
#pragma unroll
            for (int hf = 0; hf < 2; hf++) {
                int row = m0 + wm * 32 + mi * 16 + hf * 8 + tg;
                if (row >= M) continue;
#pragma unroll
                for (int ni = 0; ni < 8; ni++) {
                    int col = n0 + wn * 64 + ni * 8 + tc;
                    float v0 = acc[mi][ni][hf * 2 + 0];
                    float v1 = acc[mi][ni][hf * 2 + 1];
                    if (EPI == 4) {
                        v0 += bias[col];
                        v1 += bias[col + 1];
                        v0 = 0.5f * v0 * (1.f + erff(v0 * 0.70710678118654752f));
                        v1 = 0.5f * v1 * (1.f + erff(v1 * 0.70710678118654752f));
                    } else {
                        v0 *= scale;
                        v1 *= scale;
                    }
                    __half hl[2] = {__float2half(v0), __float2half(v1)};
                    *(uint32_t*)&Ch[(long)row * Nfull + col] = *(uint32_t*)hl;
                }
            }
        return;
    }

    // EPI 2/3
    float s1[2][2] = {}, s2[2][2] = {};
#pragma unroll
    for (int mi = 0; mi < 2; mi++)
#pragma unroll
        for (int hf = 0; hf < 2; hf++) {
            int row = m0 + wm * 32 + mi * 16 + hf * 8 + tg;
            bool rok = row < M;
            long pr = (EPI == 2 && rok) ? (long)(row % SEQ) * 128 : 0;
#pragma unroll
            for (int ni = 0; ni < 8; ni++) {
                int col = n0 + wn * 64 + ni * 8 + tc;
                float v0 = acc[mi][ni][hf * 2 + 0] + bias[col];
                float v1 = acc[mi][ni][hf * 2 + 1] + bias[col + 1];
                if (rok) {
                    if (EPI == 2) {
                        v0 += pos[pr + col];
                        v1 += pos[pr + col + 1];
                    } else {
                        v0 += res[(long)row * Nfull + col];
                        v1 += res[(long)row * Nfull + col + 1];
                    }
                    *(float2*)&C[(long)row * Nfull + col] = make_float2(v0, v1);
                }
                acc[mi][ni][hf * 2 + 0] = v0;
                acc[mi][ni][hf * 2 + 1] = v1;
                s1[mi][hf] += v0 + v1;
                s2[mi][hf] += v0 * v0 + v1 * v1;
            }
        }
    if (lnout) {
#pragma unroll
        for (int mi = 0; mi < 2; mi++)
#pragma unroll
            for (int hf = 0; hf < 2; hf++) {
                float a = s1[mi][hf], b = s2[mi][hf];
                a += __shfl_xor_sync(~0u, a, 1);
                a += __shfl_xor_sync(~0u, a, 2);
                b += __shfl_xor_sync(~0u, b, 1);
                b += __shfl_xor_sync(~0u, b, 2);
                if ((lane & 3) == 0) {
                    int ri = wm * 32 + mi * 16 + hf * 8 + tg;
                    lnred[wn][ri][0] = a;
                    lnred[wn][ri][1] = b;
                }
            }
        __syncthreads();
#pragma unroll
        for (int mi = 0; mi < 2; mi++)
#pragma unroll
            for (int hf = 0; hf < 2; hf++) {
                int ri = wm * 32 + mi * 16 + hf * 8 + tg;
                int row = m0 + ri;
                if (row >= M) continue;
                float m1 = (lnred[0][ri][0] + lnred[1][ri][0]) * (1.f / 128.f);
                float m2 = (lnred[0][ri][1] + lnred[1][ri][1]) * (1.f / 128.f);
                float inv = rsqrtf(m2 - m1 * m1 + 1e-5f);
#pragma unroll
                for (int ni = 0; ni < 8; ni++) {
                    int col = wn * 64 + ni * 8 + tc;
                    float v0 = (acc[mi][ni][hf * 2 + 0] - m1) * inv * lnsc[col] + lnbi[col];
                    float v1 = (acc[mi][ni][hf * 2 + 1] - m1) * inv * lnsc[col + 1] + lnbi[col + 1];
                    __half hl[2] = {__float2half(v0), __float2half(v1)};
                    *(uint32_t*)&lnout[(long)row * 128 + col] = *(uint32_t*)hl;
                }
            }
    }
}

// =============== 2-stage chunked fp16 GEMM for K=512 (ff2), 2 CTAs/SM ========
#define CSTAGE_B 32768u

__global__ void __launch_bounds__(256, 2)
tgemmC(const __half* __restrict__ A, const __half* __restrict__ B,
       const float* __restrict__ bias, const float* __restrict__ res,
       float* __restrict__ C, const float* __restrict__ lnsc,
       const float* __restrict__ lnbi, __half* __restrict__ lnout,
       int M, int N, int K) {
    extern __shared__ char sm[];
    __shared__ float lnred[2][128][2];
    uint32_t sb = smem_u32(sm);
    int tid = threadIdx.x;
    int w = tid >> 5, lane = tid & 31;
    int wm = w & 3, wn = w >> 2;
    int m0 = blockIdx.y * 128, n0 = blockIdx.x * 128;
    int nk = K >> 6;

    float acc[2][8][4];
#pragma unroll
    for (int i = 0; i < 2; i++)
#pragma unroll
        for (int j = 0; j < 8; j++)
#pragma unroll
            for (int q = 0; q < 4; q++) acc[i][j][q] = 0.f;

    int rA[2], rB[4];
#pragma unroll
    for (int mi = 0; mi < 2; mi++) rA[mi] = wm * 32 + mi * 16 + (lane & 15);
#pragma unroll
    for (int ng = 0; ng < 4; ng++)
        rB[ng] = wn * 64 + ng * 16 + ((lane >> 4) << 3) + (lane & 7);
    int cA = lane >> 4;
    int cB = (lane >> 3) & 1;

    auto load_stage = [&](int c, int buf) {
#pragma unroll
        for (int it = 0; it < 8; it++) {
            int slot = it * 256 + tid;
            int t = it >> 2;
            int row = (slot >> 3) & 127;
            int chunk = slot & 7;
            const __half* src = t ? B : A;
            long grow = t ? (long)(n0 + row) : (long)(m0 + row);
            bool ok = t ? true : (m0 + row < M);
            if (!ok) grow = 0;
            const void* g = (const void*)(src + grow * K + ((long)c << 6) + chunk * 8);
            uint32_t saddr = sb + buf * CSTAGE_B + (uint32_t)t * 16384u + row * 128 +
                             ((chunk ^ (row & 7)) << 4);
            cpasync16(saddr, g, ok ? 16u : 0u);
        }
        CP_COMMIT();
    };

    load_stage(0, 0);

    for (int c = 0; c < nk; c++) {
        if (c + 1 < nk) {
            load_stage(c + 1, (c + 1) & 1);
            CP_WAIT(1);
        } else {
            CP_WAIT(0);
        }
        __syncthreads();

        uint32_t st = sb + (c & 1) * CSTAGE_B;
#pragma unroll
        for (int ks = 0; ks < 4; ks++) {
            int kc = ks * 2;
            uint32_t fa[2][4], fb[4][4];
#pragma unroll
            for (int mi = 0; mi < 2; mi++) {
                int row = rA[mi];
                ldsm4(fa[mi], st + row * 128 + ((((uint32_t)(kc + cA)) ^ (row & 7)) << 4));
            }
#pragma unroll
            for (int ng = 0; ng < 4; ng++) {
                int row = rB[ng];
                ldsm4(fb[ng], st + 16384u + row * 128 + ((((uint32_t)(kc + cB)) ^ (row & 7)) << 4));
            }
#pragma unroll
            for (int ng = 0; ng < 4; ng++)
#pragma unroll
                for (int mi = 0; mi < 2; mi++) {
                    mma16816(acc[mi][ng * 2],     fa[mi], fb[ng][0], fb[ng][1]);
                    mma16816(acc[mi][ng * 2 + 1], fa[mi], fb[ng][2], fb[ng][3]);
                }
        }
        __syncthreads();
    }

    int tg = lane >> 2;
    int tc = (lane & 3) * 2;
    float s1[2][2] = {}, s2[2][2] = {};
#pragma unroll
    for (int mi = 0; mi < 2; mi++)
#pragma unroll
        for (int hf = 0; hf < 2; hf++) {
            int row = m0 + wm * 32 + mi * 16 + hf * 8 + tg;
            bool rok = row < M;
#pragma unroll
            for (int ni = 0; ni < 8; ni++) {
                int col = n0 + wn * 64 + ni * 8 + tc;
                float v0 = acc[mi][ni][hf * 2 + 0] + bias[col];
                float v1 = acc[mi][ni][hf * 2 + 1] + bias[col + 1];
                if (rok) {
                    v0 += res[(long)row * N + col];
                    v1 += res[(long)row * N + col + 1];
                    *(float2*)&C[(long)row * N + col] = make_float2(v0, v1);
                }
                acc[mi][ni][hf * 2 + 0] = v0;
                acc[mi][ni][hf * 2 + 1] = v1;
                s1[mi][hf] += v0 + v1;
                s2[mi][hf] += v0 * v0 + v1 * v1;
            }
        }
    if (lnout && lnsc) {
#pragma unroll
        for (int mi = 0; mi < 2; mi++)
#pragma unroll
            for (int hf = 0; hf < 2; hf++) {
                float a = s1[mi][hf], b = s2[mi][hf];
                a += __shfl_xor_sync(~0u, a, 1);
                a += __shfl_xor_sync(~0u, a, 2);
                b += __shfl_xor_sync(~0u, b, 1);
                b += __shfl_xor_sync(~0u, b, 2);
                if ((lane & 3) == 0) {
                    int ri = wm * 32 + mi * 16 + hf * 8 + tg;
                    lnred[wn][ri][0] = a;
                    lnred[wn][ri][1] = b;
                }
            }
        __syncthreads();
#pragma unroll
        for (int mi = 0; mi < 2; mi++)
#pragma unroll
            for (int hf = 0; hf < 2; hf++) {
                int ri = wm * 32 + mi * 16 + hf * 8 + tg;
                int row = m0 + ri;
                if (row >= M) continue;
                float m1 = (lnred[0][ri][0] + lnred[1][ri][0]) * (1.f / 128.f);
                float m2 = (lnred[0][ri][1] + lnred[1][ri][1]) * (1.f / 128.f);
                float inv = rsqrtf(m2 - m1 * m1 + 1e-5f);
#pragma unroll
                for (int ni = 0; ni < 8; ni++) {
                    int col = wn * 64 + ni * 8 + tc;
                    float v0 = (acc[mi][ni][hf * 2 + 0] - m1) * inv * lnsc[col] + lnbi[col];
                    float v1 = (acc[mi][ni][hf * 2 + 1] - m1) * inv * lnsc[col + 1] + lnbi[col + 1];
                    __half hl[2] = {__float2half(v0), __float2half(v1)};
                    *(uint32_t*)&lnout[(long)row * 128 + col] = *(uint32_t*)hl;
                }
            }
    } else if (lnout) {
#pragma unroll
        for (int mi = 0; mi < 2; mi++)
#pragma unroll
            for (int hf = 0; hf < 2; hf++) {
                int row = m0 + wm * 32 + mi * 16 + hf * 8 + tg;
                if (row >= M) continue;
#pragma unroll
                for (int ni = 0; ni < 8; ni++) {
                    int col = n0 + wn * 64 + ni * 8 + tc;
                    __half hl[2] = {__float2half(acc[mi][ni][hf * 2 + 0]),
                                    __float2half(acc[mi][ni][hf * 2 + 1])};
                    *(uint32_t*)&lnout[(long)row * 128 + col] = *(uint32_t*)hl;
                }
            }
    }
}

// ---------------- MMA attention: warp-per-mtile, full keys, no cross-warp ----
// block = (window w, batch*head); 128 threads = 4 warps = 4 m16 query tiles.
// Q is pre-scaled by 0.25 in the qkv GEMM; softmax without max-subtraction
// (scores are O(1) here), masked cols -> exp(-1e30)=0.
__global__ void __launch_bounds__(128, 4)
attn_k(const __half* __restrict__ qkv, __half* __restrict__ o) {
    __shared__ __half q_s[64 * 24];
    __shared__ __half k_s[192 * 24];
    __shared__ __half v_s[192 * 24];
    int w = blockIdx.x, bh = blockIdx.y;
    int b = bh >> 3, h = bh & 7;
    int tid = threadIdx.x, warp = tid >> 5, lane = tid & 31;
    int jstart = (w > 0) ? 0 : S1;
    int jend = (w < S1 - 1) ? 3 * S1 : 2 * S1;
    int cnt = jend - jstart;
    long rb = (long)b * SEQ;
    const uint4* qg = (const uint4*)qkv;
    const uint4 z4 = make_uint4(0, 0, 0, 0);

    // staging: thread t -> k/v rows t, t+128; q row t (t<64)
#pragma unroll
    for (int rr = 0; rr < 2; rr++) {
        int r = tid + rr * 128;
        if (r < 192) {
            bool ok = r < cnt;
            long base = (rb + (long)(w - 1) * S1 + jstart + (ok ? r : 0)) * 48 + h * 2;
            uint4 ka = ok ? qg[base + 16] : z4;
            uint4 kc = ok ? qg[base + 17] : z4;
            uint4 va = ok ? qg[base + 32] : z4;
            uint4 vc = ok ? qg[base + 33] : z4;
            *(uint4*)&k_s[r * 24] = ka;
            *(uint4*)&k_s[r * 24 + 8] = kc;
            *(uint4*)&v_s[r * 24] = va;
            *(uint4*)&v_s[r * 24 + 8] = vc;
        }
    }
    if (tid < 64) {
        bool ok = tid < S1;
        long base = (rb + (long)w * S1 + (ok ? tid : 0)) * 48 + h * 2;
        uint4 qa = ok ? qg[base] : z4;
        uint4 qc = ok ? qg[base + 1] : z4;
        *(uint4*)&q_s[tid * 24] = qa;
        *(uint4*)&q_s[tid * 24 + 8] = qc;
    }
    __syncthreads();

    uint32_t qb = smem_u32(q_s), kbb = smem_u32(k_s), vbb = smem_u32(v_s);

    // Q A-fragment for this warp's m16 tile
    uint32_t a[4];
    ldsm4(a, qb + (uint32_t)(warp * 16 + ((lane >> 3) & 1) * 8 + (lane & 7)) * 48 +
              (lane >> 4) * 16);

    float lsum[2] = {0.f, 0.f};
    float oa[2][4] = {{0.f, 0.f, 0.f, 0.f}, {0.f, 0.f, 0.f, 0.f}};

#pragma unroll
    for (int chunk = 0; chunk < 2; chunk++) {
        int kb = chunk * 96;
        // S = Q K^T over 96 keys (12 n8 tiles)
        float s[12][4];
#pragma unroll
        for (int ti = 0; ti < 12; ti++)
#pragma unroll
            for (int e = 0; e < 4; e++) s[ti][e] = 0.f;
#pragma unroll
        for (int g = 0; g < 6; g++) {
            uint32_t r[4];
            ldsm4(r, kbb + (uint32_t)(kb + g * 16 + (lane >> 4) * 8 + (lane & 7)) * 48 +
                       ((lane >> 3) & 1) * 16);
            mma16816(s[g * 2],     a, r[0], r[1]);
            mma16816(s[g * 2 + 1], a, r[2], r[3]);
        }
        // mask + exp + rowsum + pack (no max subtraction)
        uint32_t ph[12][2];
#pragma unroll
        for (int ti = 0; ti < 12; ti++) {
            int cbase = kb + ti * 8 + (lane & 3) * 2;
            float p0 = (cbase     < cnt) ? __expf(s[ti][0]) : 0.f;
            float p1 = (cbase + 1 < cnt) ? __expf(s[ti][1]) : 0.f;
            float p2 = (cbase     < cnt) ? __expf(s[ti][2]) : 0.f;
            float p3 = (cbase + 1 < cnt) ? __expf(s[ti][3]) : 0.f;
            lsum[0] += p0 + p1;
            lsum[1] += p2 + p3;
            __half2 h01 = __floats2half2_rn(p0, p1);
            __half2 h23 = __floats2half2_rn(p2, p3);
            ph[ti][0] = *(uint32_t*)&h01;
            ph[ti][1] = *(uint32_t*)&h23;
        }
        // O += P V over this chunk
#pragma unroll
        for (int g = 0; g < 6; g++) {
            uint32_t r[4];
            ldsm4t(r, vbb + (uint32_t)(kb + g * 16 + ((lane >> 3) & 1) * 8 + (lane & 7)) * 48 +
                        (lane >> 4) * 16);
            uint32_t pa[4] = {ph[g * 2][0], ph[g * 2][1], ph[g * 2 + 1][0], ph[g * 2 + 1][1]};
            mma16816(oa[0], pa, r[0], r[1]);
            mma16816(oa[1], pa, r[2], r[3]);
        }
    }

    // full row sums within warp (cols split over lane&3 quads)
#pragma unroll
    for (int i = 0; i < 2; i++) {
        lsum[i] += __shfl_xor_sync(~0u, lsum[i], 1);
        lsum[i] += __shfl_xor_sync(~0u, lsum[i], 2);
    }
    float inv0 = 1.f / lsum[0];
    float inv1 = 1.f / lsum[1];

    // direct output: rows warp*16 + {tg, tg+8}; dims (lane&3)*2 + hf*8
    int tg = lane >> 2, tc = (lane & 3) * 2;
    int i0 = warp * 16 + tg;
    int i1 = i0 + 8;
    if (i0 < S1) {
        long orow = (rb + (long)w * S1 + i0) * 128 + h * 16;
        __half2 d0 = __floats2half2_rn(oa[0][0] * inv0, oa[0][1] * inv0);
        __half2 d1 = __floats2half2_rn(oa[1][0] * inv0, oa[1][1] * inv0);
        *(uint32_t*)&o[orow + tc] = *(uint32_t*)&d0;
        *(uint32_t*)&o[orow + 8 + tc] = *(uint32_t*)&d1;
    }
    if (i1 < S1) {
        long orow = (rb + (long)w * S1 + i1) * 128 + h * 16;
        __half2 d0 = __floats2half2_rn(oa[0][2] * inv1, oa[0][3] * inv1);
        __half2 d1 = __floats2half2_rn(oa[1][2] * inv1, oa[1][3] * inv1);
        *(uint32_t*)&o[orow + tc] = *(uint32_t*)&d0;
        *(uint32_t*)&o[orow + 8 + tc] = *(uint32_t*)&d1;
    }
}

// ---------------- launch ------------------------------------------------------
extern "C" void kernel_launch(void* const* d_in, const int* in_sizes, int n_in,
                              void* d_out, int out_size) {
    const float* x      = (const float*)d_in[0];
    const float* conv_w = (const float*)d_in[1];
    const float* conv_b = (const float*)d_in[2];
    const float* lt_w   = (const float*)d_in[3];
    const float* lt_b   = (const float*)d_in[4];
    const float* pos    = (const float*)d_in[5];
    const float* ln1_s  = (const float*)d_in[6];
    const float* ln1_b  = (const float*)d_in[7];
    const float* wq     = (const float*)d_in[8];
    const float* wk     = (const float*)d_in[9];
    const float* wv     = (const float*)d_in[10];
    const float* wo     = (const float*)d_in[11];
    const float* wo_b   = (const float*)d_in[12];
    const float* ln2_s  = (const float*)d_in[13];
    const float* ln2_b  = (const float*)d_in[14];
    const float* ff_w1  = (const float*)d_in[15];
    const float* ff_b1  = (const float*)d_in[16];
    const float* ff_w2  = (const float*)d_in[17];
    const float* ff_b2  = (const float*)d_in[18];
    const float* pre_w1 = (const float*)d_in[19];
    const float* pre_b1 = (const float*)d_in[20];
    const float* pre_w2 = (const float*)d_in[21];
    const float* pre_b2 = (const float*)d_in[22];
    float* out = (float*)d_out;

    static bool attr_done = false;
    if (!attr_done) {
        cudaFuncSetAttribute(tgemmA<0,2>, cudaFuncAttributeMaxDynamicSharedMemorySize, 65536);
        cudaFuncSetAttribute(tgemmA<2,1>, cudaFuncAttributeMaxDynamicSharedMemorySize, 32768);
        cudaFuncSetAttribute(tgemmA<3,2>, cudaFuncAttributeMaxDynamicSharedMemorySize, 65536);
        cudaFuncSetAttribute(tgemmA<4,2>, cudaFuncAttributeMaxDynamicSharedMemorySize, 65536);
        cudaFuncSetAttribute(tgemmA<5,2>, cudaFuncAttributeMaxDynamicSharedMemorySize, 65536);
        cudaFuncSetAttribute(tgemmC, cudaFuncAttributeMaxDynamicSharedMemorySize, 65536);
        attr_done = true;
    }

    __half *p, *lnb, *att, *ff, *hh, *wlt, *wqkv, *woh, *wf1, *wf2, *wp1, *qkvh;
    float *h;
    cudaGetSymbolAddress((void**)&p, g_p);       cudaGetSymbolAddress((void**)&h, g_h);
    cudaGetSymbolAddress((void**)&lnb, g_ln);    cudaGetSymbolAddress((void**)&qkvh, g_qkv);
    cudaGetSymbolAddress((void**)&att, g_att);   cudaGetSymbolAddress((void**)&ff, g_ff);
    cudaGetSymbolAddress((void**)&hh, g_hh);     cudaGetSymbolAddress((void**)&wlt, g_wlt);
    cudaGetSymbolAddress((void**)&wqkv, g_wqkv); cudaGetSymbolAddress((void**)&woh, g_wo);
    cudaGetSymbolAddress((void**)&wf1, g_wf1);   cudaGetSymbolAddress((void**)&wf2, g_wf2);
    cudaGetSymbolAddress((void**)&wp1, g_wp1);

    const int M = MROWS;

    conv_prep<<<(CONV_TOTAL + PREP_TOTAL + 255) / 256, 256>>>(
        x, conv_w, conv_b, p, lt_w, wq, wk, wv, wo, ff_w1, ff_w2, pre_w1,
        wlt, wqkv, woh, wf1, wf2, wp1);
    tgemmA<2,1><<<dim3(1, MTILES), 256, 32768>>>(p, wlt, lt_b, nullptr, pos, nullptr,
                                                 h, nullptr, ln1_s, ln1_b, lnb, M, 128);

    for (int i = 0; i < NLAYER; i++) {
        tgemmA<0,2><<<dim3(3, MTILES), 256, 65536>>>(lnb, wqkv + (long)i * 49152,
            nullptr, nullptr, nullptr, nullptr, nullptr, qkvh,
            nullptr, nullptr, nullptr, M, 384);
        attn_k<<<dim3(S1, BATCH * HEADS), 128>>>(qkvh, att);
        tgemmA<3,2><<<dim3(1, MTILES), 256, 65536>>>(att, woh + (long)i * 16384,
            wo_b + i * 128, h, nullptr, nullptr, h, nullptr,
            ln2_s + i * 128, ln2_b + i * 128, lnb, M, 128);
        tgemmA<4,2><<<dim3(4, MTILES), 256, 65536>>>(lnb, wf1 + (long)i * 65536,
            ff_b1 + i * 512, nullptr, nullptr, nullptr, nullptr, ff,
            nullptr, nullptr, nullptr, M, 512);
        bool last = (i == NLAYER - 1);
        tgemmC<<<dim3(1, MTILES), 256, 65536>>>(ff, wf2 + (long)i * 65536,
            ff_b2 + i * 128, h, h,
            last ? nullptr : ln1_s + (i + 1) * 128,
            last ? nullptr : ln1_b + (i + 1) * 128,
            last ? hh : lnb, M, 128, 512);
    }

    tgemmA<5,2><<<dim3(1, MTILES), 256, 65536>>>(hh, wp1, pre_b1, nullptr, pre_b2, pre_w2,
                                                 out, nullptr, nullptr, nullptr, nullptr, M, 128);
}

// round 16
// speedup vs baseline: 3.4766x; 1.0044x over previous
#include <cuda_runtime.h>
#include <cuda_fp16.h>
#include <cstdint>
#include <math.h>

#define BATCH 16
#define S1 61
#define SEQ 3721
#define DMODEL 128
#define HEADS 8
#define DH 16
#define NLAYER 4
#define FFDIM 512
#define PCH 49
#define MROWS (BATCH * SEQ) // 59536
#define MTILES ((MROWS + 127) / 128) // 466

// ---------------------------------------------------------------- scratch
__device__ __half g_p[MROWS * 64];
__device__ float  g_h[MROWS * 128];
__device__ __half g_ln[MROWS * 128];
__device__ __half g_qkv[(size_t)MROWS * 384];
__device__ __half g_att[MROWS * 128];
__device__ __half g_ff[(size_t)MROWS * 512];
__device__ __half g_hh[MROWS * 128];
__device__ __half g_wlt[128 * 64];
__device__ __half g_wqkv[NLAYER * 384 * 128];
__device__ __half g_wo[NLAYER * 128 * 128];
__device__ __half g_wf1[NLAYER * 512 * 128];
__device__ __half g_wf2[NLAYER * 128 * 512];
__device__ __half g_wp1[128 * 128];

// ---------------------------------------------------------------- helpers
__device__ __forceinline__ uint32_t smem_u32(const void* p) {
    uint32_t a;
    asm("{ .reg .u64 t; cvta.to.shared.u64 t, %1; cvt.u32.u64 %0, t; }" : "=r"(a) : "l"(p));
    return a;
}
__device__ __forceinline__ void ldsm4(uint32_t* r, uint32_t addr) {
    asm volatile("ldmatrix.sync.aligned.m8n8.x4.shared.b16 {%0,%1,%2,%3}, [%4];"
                 : "=r"(r[0]), "=r"(r[1]), "=r"(r[2]), "=r"(r[3]) : "r"(addr));
}
__device__ __forceinline__ void ldsm4t(uint32_t* r, uint32_t addr) {
    asm volatile("ldmatrix.sync.aligned.m8n8.x4.trans.shared.b16 {%0,%1,%2,%3}, [%4];"
                 : "=r"(r[0]), "=r"(r[1]), "=r"(r[2]), "=r"(r[3]) : "r"(addr));
}
__device__ __forceinline__ void mma16816(float* c, const uint32_t* a, uint32_t b0, uint32_t b1) {
    asm volatile("mma.sync.aligned.m16n8k16.row.col.f32.f16.f16.f32 "
                 "{%0,%1,%2,%3}, {%4,%5,%6,%7}, {%8,%9}, {%0,%1,%2,%3};"
                 : "+f"(c[0]), "+f"(c[1]), "+f"(c[2]), "+f"(c[3])
                 : "r"(a[0]), "r"(a[1]), "r"(a[2]), "r"(a[3]), "r"(b0), "r"(b1));
}
__device__ __forceinline__ void cpasync16(uint32_t saddr, const void* g, uint32_t ssz) {
    asm volatile("cp.async.cg.shared.global [%0], [%1], 16, %2;"
                 :: "r"(saddr), "l"(g), "r"(ssz));
}
#define CP_COMMIT() asm volatile("cp.async.commit_group;" ::: "memory")
#define CP_WAIT(n)  asm volatile("cp.async.wait_group %0;" :: "n"(n) : "memory")

// ------------- fused conv (7x7 same + relu -> fp16) AND weight prep ----------
#define CONV_TOTAL (MROWS * 64)
#define PREP_TOTAL (8192 + 196608 + 65536 + 262144 + 262144 + 16384)
__global__ void conv_prep(const float* __restrict__ x, const float* __restrict__ cw,
                          const float* __restrict__ cb, __half* __restrict__ p,
                          const float* __restrict__ lt_w, const float* __restrict__ wq,
                          const float* __restrict__ wk, const float* __restrict__ wv,
                          const float* __restrict__ wo, const float* __restrict__ ff_w1,
                          const float* __restrict__ ff_w2, const float* __restrict__ pre_w1,
                          __half* __restrict__ wlt, __half* __restrict__ wqkv,
                          __half* __restrict__ woh, __half* __restrict__ wf1,
                          __half* __restrict__ wf2, __half* __restrict__ wp1) {
    long t = (long)blockIdx.x * blockDim.x + threadIdx.x;
    if (t < CONV_TOTAL) {
        int o = (int)(t & 63);
        float sum = 0.f;
        if (o < PCH) {
            int s = (int)(t >> 6) % SEQ;
            int b = (int)(t >> 6) / SEQ;
            int y = s / S1, xx = s % S1;
            const float* xb = x + (long)b * SEQ;
            const float* wrow = cw + o * 49;
            sum = cb[o];
#pragma unroll
            for (int dy = 0; dy < 7; dy++) {
                int iy = y + dy - 3;
                if (iy < 0 || iy >= S1) continue;
#pragma unroll
                for (int dx = 0; dx < 7; dx++) {
                    int ix = xx + dx - 3;
                    if (ix < 0 || ix >= S1) continue;
                    sum += xb[iy * S1 + ix] * wrow[dy * 7 + dx];
                }
            }
            sum = fmaxf(sum, 0.f);
        }
        p[t] = __float2half(sum);
        return;
    }
    t -= CONV_TOTAL;
    if (t >= PREP_TOTAL) return;
    if (t < 8192) {
        int n = (int)(t >> 6), kk = (int)(t & 63);
        wlt[t] = __float2half(kk < 49 ? lt_w[kk * 128 + n] : 0.f);
        return;
    }
    t -= 8192;
    if (t < 196608) {
        int l = (int)(t / 49152), r = (int)(t % 49152);
        int n = r >> 7, kk = r & 127;
        int s = n >> 7, nn = n & 127;
        const float* W = (s == 0 ? wq : s == 1 ? wk : wv) + (long)l * 16384;
        wqkv[t] = __float2half(W[kk * 128 + nn]);
        return;
    }
    t -= 196608;
    if (t < 65536) {
        int l = (int)(t / 16384), r = (int)(t % 16384);
        int n = r >> 7, kk = r & 127;
        woh[t] = __float2half(wo[(long)l * 16384 + kk * 128 + n]);
        return;
    }
    t -= 65536;
    if (t < 262144) {
        int l = (int)(t / 65536), r = (int)(t % 65536);
        int n = r >> 7, kk = r & 127;
        wf1[t] = __float2half(ff_w1[(long)l * 65536 + (long)kk * 512 + n]);
        return;
    }
    t -= 262144;
    if (t < 262144) {
        int l = (int)(t / 65536), r = (int)(t % 65536);
        int n = r / 512, kk = r % 512;
        wf2[t] = __float2half(ff_w2[(long)l * 65536 + (long)kk * 128 + n]);
        return;
    }
    t -= 262144;
    if (t < 16384) {
        int n = (int)(t >> 7), kk = (int)(t & 127);
        wp1[t] = __float2half(pre_w1[kk * 128 + n]);
    }
}

// =============== A-resident fp16 GEMM (K<=128), n-tile = blockIdx.x ==========
template <int EPI, int NK>
__global__ void __launch_bounds__(256, 2)
tgemmA(const __half* __restrict__ A, const __half* __restrict__ B,
       const float* __restrict__ bias, const float* __restrict__ res,
       const float* __restrict__ pos, const float* __restrict__ w2,
       float* __restrict__ C, __half* __restrict__ Ch,
       const float* __restrict__ lnsc, const float* __restrict__ lnbi,
       __half* __restrict__ lnout, int M, int Nfull) {
    extern __shared__ char sm[];
    __shared__ float red[2][128];
    __shared__ float lnred[2][128][2];
    uint32_t sb = smem_u32(sm);
    const int K = NK * 64;
    const uint32_t ABYTES = (uint32_t)NK * 16384u;
    int tid = threadIdx.x;
    int w = tid >> 5, lane = tid & 31;
    int wm = w & 3, wn = w >> 2;
    int m0 = blockIdx.y * 128;
    int nt = blockIdx.x;

    int rA[2], rB[4];
#pragma unroll
    for (int mi = 0; mi < 2; mi++) rA[mi] = wm * 32 + mi * 16 + (lane & 15);
#pragma unroll
    for (int ng = 0; ng < 4; ng++)
        rB[ng] = wn * 64 + ng * 16 + ((lane >> 4) << 3) + (lane & 7);
    int cA = lane >> 4;
    int cB = (lane >> 3) & 1;

#pragma unroll
    for (int chunk = 0; chunk < NK; chunk++) {
#pragma unroll
        for (int t = 0; t < 4; t++) {
            int idx = t * 256 + tid;
            int row = idx >> 3, c16 = idx & 7;
            uint32_t soff = row * 128 + (((uint32_t)c16 ^ (row & 7)) << 4);
            long ga = m0 + row;
            bool ok = ga < M;
            if (!ok) ga = 0;
            cpasync16(sb + (uint32_t)chunk * 16384u + soff,
                      A + ga * K + chunk * 64 + c16 * 8, ok ? 16u : 0u);
            long gb = (long)(nt * 128 + row);
            cpasync16(sb + ABYTES + (uint32_t)chunk * 16384u + soff,
                      B + gb * K + chunk * 64 + c16 * 8, 16u);
        }
        CP_COMMIT();
    }

    float acc[2][8][4];
#pragma unroll
    for (int i = 0; i < 2; i++)
#pragma unroll
        for (int j = 0; j < 8; j++)
#pragma unroll
            for (int q = 0; q < 4; q++) acc[i][j][q] = 0.f;

#pragma unroll
    for (int chunk = 0; chunk < NK; chunk++) {
        if (NK == 2 && chunk == 0) CP_WAIT(1);
        else CP_WAIT(0);
        __syncthreads();
        uint32_t Ab = sb + (uint32_t)chunk * 16384u;
        uint32_t Bb = sb + ABYTES + (uint32_t)chunk * 16384u;
#pragma unroll
        for (int ks = 0; ks < 4; ks++) {
            int kc = ks * 2;
            uint32_t fa[2][4], fb[4][4];
#pragma unroll
            for (int mi = 0; mi < 2; mi++) {
                int row = rA[mi];
                ldsm4(fa[mi], Ab + row * 128 + ((((uint32_t)(kc + cA)) ^ (row & 7)) << 4));
            }
#pragma unroll
            for (int ng = 0; ng < 4; ng++) {
                int row = rB[ng];
                ldsm4(fb[ng], Bb + row * 128 + ((((uint32_t)(kc + cB)) ^ (row & 7)) << 4));
            }
#pragma unroll
            for (int ng = 0; ng < 4; ng++)
#pragma unroll
                for (int mi = 0; mi < 2; mi++) {
                    mma16816(acc[mi][ng * 2],     fa[mi], fb[ng][0], fb[ng][1]);
                    mma16816(acc[mi][ng * 2 + 1], fa[mi], fb[ng][2], fb[ng][3]);
                }
        }
    }
    __syncthreads();

    int n0 = nt * 128;
    int tg = lane >> 2;
    int tc = (lane & 3) * 2;

    if (EPI == 5) {
        float p[2][2] = {};
#pragma unroll
        for (int mi = 0; mi < 2; mi++)
#pragma unroll
            for (int ni = 0; ni < 8; ni++) {
                int col = wn * 64 + ni * 8 + tc;
                float b0 = bias[col], b1 = bias[col + 1];
                float w20 = w2[col], w21 = w2[col + 1];
                p[mi][0] += fmaxf(acc[mi][ni][0] + b0, 0.f) * w20 +
                            fmaxf(acc[mi][ni][1] + b1, 0.f) * w21;
                p[mi][1] += fmaxf(acc[mi][ni][2] + b0, 0.f) * w20 +
                            fmaxf(acc[mi][ni][3] + b1, 0.f) * w21;
            }
#pragma unroll
        for (int mi = 0; mi < 2; mi++)
#pragma unroll
            for (int hf = 0; hf < 2; hf++) {
                float v = p[mi][hf];
                v += __shfl_xor_sync(~0u, v, 1);
                v += __shfl_xor_sync(~0u, v, 2);
                if ((lane & 3) == 0) red[wn][wm * 32 + mi * 16 + hf * 8 + tg] = v;
            }
        __syncthreads();
        if (tid < 128) {
            int row = m0 + tid;
            if (row < M) C[row] = red[0][tid] + red[1][tid] + pos[0];
        }
        return;
    }

    if (EPI == 0 || EPI == 4) {
        float scale = (EPI == 0 && nt == 0) ? 0.25f : 1.f;
#pragma unroll
        for (int mi = 0; mi < 2; mi++)
#pragma unroll
            for (int hf = 0; hf < 2; hf++) {
                int row = m0 + wm * 32 + mi * 16 + hf * 8 + tg;
                if (row >= M) continue;
#pragma unroll
                for (int ni = 0; ni < 8; ni++) {
                    int col = n0 + wn * 64 + ni * 8 + tc;
                    float v0 = acc[mi][ni][hf * 2 + 0];
                    float v1 = acc[mi][ni][hf * 2 + 1];
                    if (EPI == 4) {
                        v0 += bias[col];
                        v1 += bias[col + 1];
                        v0 = 0.5f * v0 * (1.f + erff(v0 * 0.70710678118654752f));
                        v1 = 0.5f * v1 * (1.f + erff(v1 * 0.70710678118654752f));
                    } else {
                        v0 *= scale;
                        v1 *= scale;
                    }
                    __half hl[2] = {__float2half(v0), __float2half(v1)};
                    *(uint32_t*)&Ch[(long)row * Nfull + col] = *(uint32_t*)hl;
                }
            }
        return;
    }

    // EPI 2/3
    float s1[2][2] = {}, s2[2][2] = {};
#pragma unroll
    for (int mi = 0; mi < 2; mi++)
#pragma unroll
        for (int hf = 0; hf < 2; hf++) {
            int row = m0 + wm * 32 + mi * 16 + hf * 8 + tg;
            bool rok = row < M;
            long pr = (EPI == 2 && rok) ? (long)(row % SEQ) * 128 : 0;
#pragma unroll
            for (int ni = 0; ni < 8; ni++) {
                int col = n0 + wn * 64 + ni * 8 + tc;
                float v0 = acc[mi][ni][hf * 2 + 0] + bias[col];
                float v1 = acc[mi][ni][hf * 2 + 1] + bias[col + 1];
                if (rok) {
                    if (EPI == 2) {
                        v0 += pos[pr + col];
                        v1 += pos[pr + col + 1];
                    } else {
                        v0 += res[(long)row * Nfull + col];
                        v1 += res[(long)row * Nfull + col + 1];
                    }
                    *(float2*)&C[(long)row * Nfull + col] = make_float2(v0, v1);
                }
                acc[mi][ni][hf * 2 + 0] = v0;
                acc[mi][ni][hf * 2 + 1] = v1;
                s1[mi][hf] += v0 + v1;
                s2[mi][hf] += v0 * v0 + v1 * v1;
            }
        }
    if (lnout) {
#pragma unroll
        for (int mi = 0; mi < 2; mi++)
#pragma unroll
            for (int hf = 0; hf < 2; hf++) {
                float a = s1[mi][hf], b = s2[mi][hf];
                a += __shfl_xor_sync(~0u, a, 1);
                a += __shfl_xor_sync(~0u, a, 2);
                b += __shfl_xor_sync(~0u, b, 1);
                b += __shfl_xor_sync(~0u, b, 2);
                if ((lane & 3) == 0) {
                    int ri = wm * 32 + mi * 16 + hf * 8 + tg;
                    lnred[wn][ri][0] = a;
                    lnred[wn][ri][1] = b;
                }
            }
        __syncthreads();
#pragma unroll
        for (int mi = 0; mi < 2; mi++)
#pragma unroll
            for (int hf = 0; hf < 2; hf++) {
                int ri = wm * 32 + mi * 16 + hf * 8 + tg;
                int row = m0 + ri;
                if (row >= M) continue;
                float m1 = (lnred[0][ri][0] + lnred[1][ri][0]) * (1.f / 128.f);
                float m2 = (lnred[0][ri][1] + lnred[1][ri][1]) * (1.f / 128.f);
                float inv = rsqrtf(m2 - m1 * m1 + 1e-5f);
#pragma unroll
                for (int ni = 0; ni < 8; ni++) {
                    int col = wn * 64 + ni * 8 + tc;
                    float v0 = (acc[mi][ni][hf * 2 + 0] - m1) * inv * lnsc[col] + lnbi[col];
                    float v1 = (acc[mi][ni][hf * 2 + 1] - m1) * inv * lnsc[col + 1] + lnbi[col + 1];
                    __half hl[2] = {__float2half(v0), __float2half(v1)};
                    *(uint32_t*)&lnout[(long)row * 128 + col] = *(uint32_t*)hl;
                }
            }
    }
}

// =============== 2-stage chunked fp16 GEMM for K=512 (ff2), 2 CTAs/SM ========
#define CSTAGE_B 32768u

__global__ void __launch_bounds__(256, 2)
tgemmC(const __half* __restrict__ A, const __half* __restrict__ B,
       const float* __restrict__ bias, const float* __restrict__ res,
       float* __restrict__ C, const float* __restrict__ lnsc,
       const float* __restrict__ lnbi, __half* __restrict__ lnout,
       int M, int N, int K) {
    extern __shared__ char sm[];
    __shared__ float lnred[2][128][2];
    uint32_t sb = smem_u32(sm);
    int tid = threadIdx.x;
    int w = tid >> 5, lane = tid & 31;
    int wm = w & 3, wn = w >> 2;
    int m0 = blockIdx.y * 128, n0 = blockIdx.x * 128;
    int nk = K >> 6;

    float acc[2][8][4];
#pragma unroll
    for (int i = 0; i < 2; i++)
#pragma unroll
        for (int j = 0; j < 8; j++)
#pragma unroll
            for (int q = 0; q < 4; q++) acc[i][j][q] = 0.f;

    int rA[2], rB[4];
#pragma unroll
    for (int mi = 0; mi < 2; mi++) rA[mi] = wm * 32 + mi * 16 + (lane & 15);
#pragma unroll
    for (int ng = 0; ng < 4; ng++)
        rB[ng] = wn * 64 + ng * 16 + ((lane >> 4) << 3) + (lane & 7);
    int cA = lane >> 4;
    int cB = (lane >> 3) & 1;

    auto load_stage = [&](int c, int buf) {
#pragma unroll
        for (int it = 0; it < 8; it++) {
            int slot = it * 256 + tid;
            int t = it >> 2;
            int row = (slot >> 3) & 127;
            int chunk = slot & 7;
            const __half* src = t ? B : A;
            long grow = t ? (long)(n0 + row) : (long)(m0 + row);
            bool ok = t ? true : (m0 + row < M);
            if (!ok) grow = 0;
            const void* g = (const void*)(src + grow * K + ((long)c << 6) + chunk * 8);
            uint32_t saddr = sb + buf * CSTAGE_B + (uint32_t)t * 16384u + row * 128 +
                             ((chunk ^ (row & 7)) << 4);
            cpasync16(saddr, g, ok ? 16u : 0u);
        }
        CP_COMMIT();
    };

    load_stage(0, 0);

    for (int c = 0; c < nk; c++) {
        if (c + 1 < nk) {
            load_stage(c + 1, (c + 1) & 1);
            CP_WAIT(1);
        } else {
            CP_WAIT(0);
        }
        __syncthreads();

        uint32_t st = sb + (c & 1) * CSTAGE_B;
#pragma unroll
        for (int ks = 0; ks < 4; ks++) {
            int kc = ks * 2;
            uint32_t fa[2][4], fb[4][4];
#pragma unroll
            for (int mi = 0; mi < 2; mi++) {
                int row = rA[mi];
                ldsm4(fa[mi], st + row * 128 + ((((uint32_t)(kc + cA)) ^ (row & 7)) << 4));
            }
#pragma unroll
            for (int ng = 0; ng < 4; ng++) {
                int row = rB[ng];
                ldsm4(fb[ng], st + 16384u + row * 128 + ((((uint32_t)(kc + cB)) ^ (row & 7)) << 4));
            }
#pragma unroll
            for (int ng = 0; ng < 4; ng++)
#pragma unroll
                for (int mi = 0; mi < 2; mi++) {
                    mma16816(acc[mi][ng * 2],     fa[mi], fb[ng][0], fb[ng][1]);
                    mma16816(acc[mi][ng * 2 + 1], fa[mi], fb[ng][2], fb[ng][3]);
                }
        }
        __syncthreads();
    }

    int tg = lane >> 2;
    int tc = (lane & 3) * 2;
    float s1[2][2] = {}, s2[2][2] = {};
#pragma unroll
    for (int mi = 0; mi < 2; mi++)
#pragma unroll
        for (int hf = 0; hf < 2; hf++) {
            int row = m0 + wm * 32 + mi * 16 + hf * 8 + tg;
            bool rok = row < M;
#pragma unroll
            for (int ni = 0; ni < 8; ni++) {
                int col = n0 + wn * 64 + ni * 8 + tc;
                float v0 = acc[mi][ni][hf * 2 + 0] + bias[col];
                float v1 = acc[mi][ni][hf * 2 + 1] + bias[col + 1];
                if (rok) {
                    v0 += res[(long)row * N + col];
                    v1 += res[(long)row * N + col + 1];
                    *(float2*)&C[(long)row * N + col] = make_float2(v0, v1);
                }
                acc[mi][ni][hf * 2 + 0] = v0;
                acc[mi][ni][hf * 2 + 1] = v1;
                s1[mi][hf] += v0 + v1;
                s2[mi][hf] += v0 * v0 + v1 * v1;
            }
        }
    if (lnout && lnsc) {
#pragma unroll
        for (int mi = 0; mi < 2; mi++)
#pragma unroll
            for (int hf = 0; hf < 2; hf++) {
                float a = s1[mi][hf], b = s2[mi][hf];
                a += __shfl_xor_sync(~0u, a, 1);
                a += __shfl_xor_sync(~0u, a, 2);
                b += __shfl_xor_sync(~0u, b, 1);
                b += __shfl_xor_sync(~0u, b, 2);
                if ((lane & 3) == 0) {
                    int ri = wm * 32 + mi * 16 + hf * 8 + tg;
                    lnred[wn][ri][0] = a;
                    lnred[wn][ri][1] = b;
                }
            }
        __syncthreads();
#pragma unroll
        for (int mi = 0; mi < 2; mi++)
#pragma unroll
            for (int hf = 0; hf < 2; hf++) {
                int ri = wm * 32 + mi * 16 + hf * 8 + tg;
                int row = m0 + ri;
                if (row >= M) continue;
                float m1 = (lnred[0][ri][0] + lnred[1][ri][0]) * (1.f / 128.f);
                float m2 = (lnred[0][ri][1] + lnred[1][ri][1]) * (1.f / 128.f);
                float inv = rsqrtf(m2 - m1 * m1 + 1e-5f);
#pragma unroll
                for (int ni = 0; ni < 8; ni++) {
                    int col = wn * 64 + ni * 8 + tc;
                    float v0 = (acc[mi][ni][hf * 2 + 0] - m1) * inv * lnsc[col] + lnbi[col];
                    float v1 = (acc[mi][ni][hf * 2 + 1] - m1) * inv * lnsc[col + 1] + lnbi[col + 1];
                    __half hl[2] = {__float2half(v0), __float2half(v1)};
                    *(uint32_t*)&lnout[(long)row * 128 + col] = *(uint32_t*)hl;
                }
            }
    } else if (lnout) {
#pragma unroll
        for (int mi = 0; mi < 2; mi++)
#pragma unroll
            for (int hf = 0; hf < 2; hf++) {
                int row = m0 + wm * 32 + mi * 16 + hf * 8 + tg;
                if (row >= M) continue;
#pragma unroll
                for (int ni = 0; ni < 8; ni++) {
                    int col = n0 + wn * 64 + ni * 8 + tc;
                    __half hl[2] = {__float2half(acc[mi][ni][hf * 2 + 0]),
                                    __float2half(acc[mi][ni][hf * 2 + 1])};
                    *(uint32_t*)&lnout[(long)row * 128 + col] = *(uint32_t*)hl;
                }
            }
    }
}

// ---------------- MMA attention: warp-per-mtile, 48-key sub-chunks -----------
// 128 threads = 4 warps = 4 m16 query tiles; keys processed in 4 x 48 chunks
// to shrink live registers (occupancy). No max-subtraction; Q pre-scaled.
__global__ void __launch_bounds__(128, 6)
attn_k(const __half* __restrict__ qkv, __half* __restrict__ o) {
    __shared__ __half q_s[64 * 24];
    __shared__ __half k_s[192 * 24];
    __shared__ __half v_s[192 * 24];
    int w = blockIdx.x, bh = blockIdx.y;
    int b = bh >> 3, h = bh & 7;
    int tid = threadIdx.x, warp = tid >> 5, lane = tid & 31;
    int jstart = (w > 0) ? 0 : S1;
    int jend = (w < S1 - 1) ? 3 * S1 : 2 * S1;
    int cnt = jend - jstart;
    long rb = (long)b * SEQ;
    const uint4* qg = (const uint4*)qkv;
    const uint4 z4 = make_uint4(0, 0, 0, 0);

#pragma unroll
    for (int rr = 0; rr < 2; rr++) {
        int r = tid + rr * 128;
        if (r < 192) {
            bool ok = r < cnt;
            long base = (rb + (long)(w - 1) * S1 + jstart + (ok ? r : 0)) * 48 + h * 2;
            uint4 ka = ok ? qg[base + 16] : z4;
            uint4 kc = ok ? qg[base + 17] : z4;
            uint4 va = ok ? qg[base + 32] : z4;
            uint4 vc = ok ? qg[base + 33] : z4;
            *(uint4*)&k_s[r * 24] = ka;
            *(uint4*)&k_s[r * 24 + 8] = kc;
            *(uint4*)&v_s[r * 24] = va;
            *(uint4*)&v_s[r * 24 + 8] = vc;
        }
    }
    if (tid < 64) {
        bool ok = tid < S1;
        long base = (rb + (long)w * S1 + (ok ? tid : 0)) * 48 + h * 2;
        uint4 qa = ok ? qg[base] : z4;
        uint4 qc = ok ? qg[base + 1] : z4;
        *(uint4*)&q_s[tid * 24] = qa;
        *(uint4*)&q_s[tid * 24 + 8] = qc;
    }
    __syncthreads();

    uint32_t qb = smem_u32(q_s), kbb = smem_u32(k_s), vbb = smem_u32(v_s);

    uint32_t a[4];
    ldsm4(a, qb + (uint32_t)(warp * 16 + ((lane >> 3) & 1) * 8 + (lane & 7)) * 48 +
              (lane >> 4) * 16);

    float lsum[2] = {0.f, 0.f};
    float oa[2][4] = {{0.f, 0.f, 0.f, 0.f}, {0.f, 0.f, 0.f, 0.f}};

#pragma unroll
    for (int sub = 0; sub < 4; sub++) {
        int kb = sub * 48;
        // S = Q K^T over 48 keys (6 n8 tiles)
        float s[6][4];
#pragma unroll
        for (int ti = 0; ti < 6; ti++)
#pragma unroll
            for (int e = 0; e < 4; e++) s[ti][e] = 0.f;
#pragma unroll
        for (int g = 0; g < 3; g++) {
            uint32_t r[4];
            ldsm4(r, kbb + (uint32_t)(kb + g * 16 + (lane >> 4) * 8 + (lane & 7)) * 48 +
                       ((lane >> 3) & 1) * 16);
            mma16816(s[g * 2],     a, r[0], r[1]);
            mma16816(s[g * 2 + 1], a, r[2], r[3]);
        }
        // mask + exp + rowsum + pack
        uint32_t ph[6][2];
#pragma unroll
        for (int ti = 0; ti < 6; ti++) {
            int cbase = kb + ti * 8 + (lane & 3) * 2;
            float p0 = (cbase     < cnt) ? __expf(s[ti][0]) : 0.f;
            float p1 = (cbase + 1 < cnt) ? __expf(s[ti][1]) : 0.f;
            float p2 = (cbase     < cnt) ? __expf(s[ti][2]) : 0.f;
            float p3 = (cbase + 1 < cnt) ? __expf(s[ti][3]) : 0.f;
            lsum[0] += p0 + p1;
            lsum[1] += p2 + p3;
            __half2 h01 = __floats2half2_rn(p0, p1);
            __half2 h23 = __floats2half2_rn(p2, p3);
            ph[ti][0] = *(uint32_t*)&h01;
            ph[ti][1] = *(uint32_t*)&h23;
        }
        // O += P V
#pragma unroll
        for (int g = 0; g < 3; g++) {
            uint32_t r[4];
            ldsm4t(r, vbb + (uint32_t)(kb + g * 16 + ((lane >> 3) & 1) * 8 + (lane & 7)) * 48 +
                        (lane >> 4) * 16);
            uint32_t pa[4] = {ph[g * 2][0], ph[g * 2][1], ph[g * 2 + 1][0], ph[g * 2 + 1][1]};
            mma16816(oa[0], pa, r[0], r[1]);
            mma16816(oa[1], pa, r[2], r[3]);
        }
    }

#pragma unroll
    for (int i = 0; i < 2; i++) {
        lsum[i] += __shfl_xor_sync(~0u, lsum[i], 1);
        lsum[i] += __shfl_xor_sync(~0u, lsum[i], 2);
    }
    float inv0 = 1.f / lsum[0];
    float inv1 = 1.f / lsum[1];

    int tg = lane >> 2, tc = (lane & 3) * 2;
    int i0 = warp * 16 + tg;
    int i1 = i0 + 8;
    if (i0 < S1) {
        long orow = (rb + (long)w * S1 + i0) * 128 + h * 16;
        __half2 d0 = __floats2half2_rn(oa[0][0] * inv0, oa[0][1] * inv0);
        __half2 d1 = __floats2half2_rn(oa[1][0] * inv0, oa[1][1] * inv0);
        *(uint32_t*)&o[orow + tc] = *(uint32_t*)&d0;
        *(uint32_t*)&o[orow + 8 + tc] = *(uint32_t*)&d1;
    }
    if (i1 < S1) {
        long orow = (rb + (long)w * S1 + i1) * 128 + h * 16;
        __half2 d0 = __floats2half2_rn(oa[0][2] * inv1, oa[0][3] * inv1);
        __half2 d1 = __floats2half2_rn(oa[1][2] * inv1, oa[1][3] * inv1);
        *(uint32_t*)&o[orow + tc] = *(uint32_t*)&d0;
        *(uint32_t*)&o[orow + 8 + tc] = *(uint32_t*)&d1;
    }
}

// ---------------- launch ------------------------------------------------------
extern "C" void kernel_launch(void* const* d_in, const int* in_sizes, int n_in,
                              void* d_out, int out_size) {
    const float* x      = (const float*)d_in[0];
    const float* conv_w = (const float*)d_in[1];
    const float* conv_b = (const float*)d_in[2];
    const float* lt_w   = (const float*)d_in[3];
    const float* lt_b   = (const float*)d_in[4];
    const float* pos    = (const float*)d_in[5];
    const float* ln1_s  = (const float*)d_in[6];
    const float* ln1_b  = (const float*)d_in[7];
    const float* wq     = (const float*)d_in[8];
    const float* wk     = (const float*)d_in[9];
    const float* wv     = (const float*)d_in[10];
    const float* wo     = (const float*)d_in[11];
    const float* wo_b   = (const float*)d_in[12];
    const float* ln2_s  = (const float*)d_in[13];
    const float* ln2_b  = (const float*)d_in[14];
    const float* ff_w1  = (const float*)d_in[15];
    const float* ff_b1  = (const float*)d_in[16];
    const float* ff_w2  = (const float*)d_in[17];
    const float* ff_b2  = (const float*)d_in[18];
    const float* pre_w1 = (const float*)d_in[19];
    const float* pre_b1 = (const float*)d_in[20];
    const float* pre_w2 = (const float*)d_in[21];
    const float* pre_b2 = (const float*)d_in[22];
    float* out = (float*)d_out;

    static bool attr_done = false;
    if (!attr_done) {
        cudaFuncSetAttribute(tgemmA<0,2>, cudaFuncAttributeMaxDynamicSharedMemorySize, 65536);
        cudaFuncSetAttribute(tgemmA<2,1>, cudaFuncAttributeMaxDynamicSharedMemorySize, 32768);
        cudaFuncSetAttribute(tgemmA<3,2>, cudaFuncAttributeMaxDynamicSharedMemorySize, 65536);
        cudaFuncSetAttribute(tgemmA<4,2>, cudaFuncAttributeMaxDynamicSharedMemorySize, 65536);
        cudaFuncSetAttribute(tgemmA<5,2>, cudaFuncAttributeMaxDynamicSharedMemorySize, 65536);
        cudaFuncSetAttribute(tgemmC, cudaFuncAttributeMaxDynamicSharedMemorySize, 65536);
        attr_done = true;
    }

    __half *p, *lnb, *att, *ff, *hh, *wlt, *wqkv, *woh, *wf1, *wf2, *wp1, *qkvh;
    float *h;
    cudaGetSymbolAddress((void**)&p, g_p);       cudaGetSymbolAddress((void**)&h, g_h);
    cudaGetSymbolAddress((void**)&lnb, g_ln);    cudaGetSymbolAddress((void**)&qkvh, g_qkv);
    cudaGetSymbolAddress((void**)&att, g_att);   cudaGetSymbolAddress((void**)&ff, g_ff);
    cudaGetSymbolAddress((void**)&hh, g_hh);     cudaGetSymbolAddress((void**)&wlt, g_wlt);
    cudaGetSymbolAddress((void**)&wqkv, g_wqkv); cudaGetSymbolAddress((void**)&woh, g_wo);
    cudaGetSymbolAddress((void**)&wf1, g_wf1);   cudaGetSymbolAddress((void**)&wf2, g_wf2);
    cudaGetSymbolAddress((void**)&wp1, g_wp1);

    const int M = MROWS;

    conv_prep<<<(CONV_TOTAL + PREP_TOTAL + 255) / 256, 256>>>(
        x, conv_w, conv_b, p, lt_w, wq, wk, wv, wo, ff_w1, ff_w2, pre_w1,
        wlt, wqkv, woh, wf1, wf2, wp1);
    tgemmA<2,1><<<dim3(1, MTILES), 256, 32768>>>(p, wlt, lt_b, nullptr, pos, nullptr,
                                                 h, nullptr, ln1_s, ln1_b, lnb, M, 128);

    for (int i = 0; i < NLAYER; i++) {
        tgemmA<0,2><<<dim3(3, MTILES), 256, 65536>>>(lnb, wqkv + (long)i * 49152,
            nullptr, nullptr, nullptr, nullptr, nullptr, qkvh,
            nullptr, nullptr, nullptr, M, 384);
        attn_k<<<dim3(S1, BATCH * HEADS), 128>>>(qkvh, att);
        tgemmA<3,2><<<dim3(1, MTILES), 256, 65536>>>(att, woh + (long)i * 16384,
            wo_b + i * 128, h, nullptr, nullptr, h, nullptr,
            ln2_s + i * 128, ln2_b + i * 128, lnb, M, 128);
        tgemmA<4,2><<<dim3(4, MTILES), 256, 65536>>>(lnb, wf1 + (long)i * 65536,
            ff_b1 + i * 512, nullptr, nullptr, nullptr, nullptr, ff,
            nullptr, nullptr, nullptr, M, 512);
        bool last = (i == NLAYER - 1);
        tgemmC<<<dim3(1, MTILES), 256, 65536>>>(ff, wf2 + (long)i * 65536,
            ff_b2 + i * 128, h, h,
            last ? nullptr : ln1_s + (i + 1) * 128,
            last ? nullptr : ln1_b + (i + 1) * 128,
            last ? hh : lnb, M, 128, 512);
    }

    tgemmA<5,2><<<dim3(1, MTILES), 256, 65536>>>(hh, wp1, pre_b1, nullptr, pre_b2, pre_w2,
                                                 out, nullptr, nullptr, nullptr, nullptr, M, 128);
}

// round 17
// speedup vs baseline: 3.5219x; 1.0130x over previous
#include <cuda_runtime.h>
#include <cuda_fp16.h>
#include <cstdint>
#include <math.h>

#define BATCH 16
#define S1 61
#define SEQ 3721
#define DMODEL 128
#define HEADS 8
#define DH 16
#define NLAYER 4
#define FFDIM 512
#define PCH 49
#define MROWS (BATCH * SEQ) // 59536
#define MTILES ((MROWS + 127) / 128) // 466

// ---------------------------------------------------------------- scratch
__device__ __half g_p[MROWS * 64];
__device__ float  g_h[MROWS * 128];
__device__ __half g_ln[MROWS * 128];
__device__ __half g_qkv[(size_t)MROWS * 384];
__device__ __half g_att[MROWS * 128];
__device__ __half g_ff[(size_t)MROWS * 512];
__device__ __half g_hh[MROWS * 128];
__device__ __half g_wlt[128 * 64];
__device__ __half g_wqkv[NLAYER * 384 * 128];
__device__ __half g_wo[NLAYER * 128 * 128];
__device__ __half g_wf1[NLAYER * 512 * 128];
__device__ __half g_wf2[NLAYER * 128 * 512];
__device__ __half g_wp1[128 * 128];

// ---------------------------------------------------------------- helpers
__device__ __forceinline__ uint32_t smem_u32(const void* p) {
    uint32_t a;
    asm("{ .reg .u64 t; cvta.to.shared.u64 t, %1; cvt.u32.u64 %0, t; }" : "=r"(a) : "l"(p));
    return a;
}
__device__ __forceinline__ void ldsm4(uint32_t* r, uint32_t addr) {
    asm volatile("ldmatrix.sync.aligned.m8n8.x4.shared.b16 {%0,%1,%2,%3}, [%4];"
                 : "=r"(r[0]), "=r"(r[1]), "=r"(r[2]), "=r"(r[3]) : "r"(addr));
}
__device__ __forceinline__ void ldsm4t(uint32_t* r, uint32_t addr) {
    asm volatile("ldmatrix.sync.aligned.m8n8.x4.trans.shared.b16 {%0,%1,%2,%3}, [%4];"
                 : "=r"(r[0]), "=r"(r[1]), "=r"(r[2]), "=r"(r[3]) : "r"(addr));
}
__device__ __forceinline__ void mma16816(float* c, const uint32_t* a, uint32_t b0, uint32_t b1) {
    asm volatile("mma.sync.aligned.m16n8k16.row.col.f32.f16.f16.f32 "
                 "{%0,%1,%2,%3}, {%4,%5,%6,%7}, {%8,%9}, {%0,%1,%2,%3};"
                 : "+f"(c[0]), "+f"(c[1]), "+f"(c[2]), "+f"(c[3])
                 : "r"(a[0]), "r"(a[1]), "r"(a[2]), "r"(a[3]), "r"(b0), "r"(b1));
}
__device__ __forceinline__ void cpasync16(uint32_t saddr, const void* g, uint32_t ssz) {
    asm volatile("cp.async.cg.shared.global [%0], [%1], 16, %2;"
                 :: "r"(saddr), "l"(g), "r"(ssz));
}
#define CP_COMMIT() asm volatile("cp.async.commit_group;" ::: "memory")
#define CP_WAIT(n)  asm volatile("cp.async.wait_group %0;" :: "n"(n) : "memory")

// ------------- fused conv (7x7 same + relu -> fp16) AND weight prep ----------
#define CONV_TOTAL (MROWS * 64)
#define PREP_TOTAL (8192 + 196608 + 65536 + 262144 + 262144 + 16384)
__global__ void conv_prep(const float* __restrict__ x, const float* __restrict__ cw,
                          const float* __restrict__ cb, __half* __restrict__ p,
                          const float* __restrict__ lt_w, const float* __restrict__ wq,
                          const float* __restrict__ wk, const float* __restrict__ wv,
                          const float* __restrict__ wo, const float* __restrict__ ff_w1,
                          const float* __restrict__ ff_w2, const float* __restrict__ pre_w1,
                          __half* __restrict__ wlt, __half* __restrict__ wqkv,
                          __half* __restrict__ woh, __half* __restrict__ wf1,
                          __half* __restrict__ wf2, __half* __restrict__ wp1) {
    long t = (long)blockIdx.x * blockDim.x + threadIdx.x;
    if (t < CONV_TOTAL) {
        int o = (int)(t & 63);
        float sum = 0.f;
        if (o < PCH) {
            int s = (int)(t >> 6) % SEQ;
            int b = (int)(t >> 6) / SEQ;
            int y = s / S1, xx = s % S1;
            const float* xb = x + (long)b * SEQ;
            const float* wrow = cw + o * 49;
            sum = cb[o];
#pragma unroll
            for (int dy = 0; dy < 7; dy++) {
                int iy = y + dy - 3;
                if (iy < 0 || iy >= S1) continue;
#pragma unroll
                for (int dx = 0; dx < 7; dx++) {
                    int ix = xx + dx - 3;
                    if (ix < 0 || ix >= S1) continue;
                    sum += xb[iy * S1 + ix] * wrow[dy * 7 + dx];
                }
            }
            sum = fmaxf(sum, 0.f);
        }
        p[t] = __float2half(sum);
        return;
    }
    t -= CONV_TOTAL;
    if (t >= PREP_TOTAL) return;
    if (t < 8192) {
        int n = (int)(t >> 6), kk = (int)(t & 63);
        wlt[t] = __float2half(kk < 49 ? lt_w[kk * 128 + n] : 0.f);
        return;
    }
    t -= 8192;
    if (t < 196608) {
        int l = (int)(t / 49152), r = (int)(t % 49152);
        int n = r >> 7, kk = r & 127;
        int s = n >> 7, nn = n & 127;
        const float* W = (s == 0 ? wq : s == 1 ? wk : wv) + (long)l * 16384;
        wqkv[t] = __float2half(W[kk * 128 + nn]);
        return;
    }
    t -= 196608;
    if (t < 65536) {
        int l = (int)(t / 16384), r = (int)(t % 16384);
        int n = r >> 7, kk = r & 127;
        woh[t] = __float2half(wo[(long)l * 16384 + kk * 128 + n]);
        return;
    }
    t -= 65536;
    if (t < 262144) {
        int l = (int)(t / 65536), r = (int)(t % 65536);
        int n = r >> 7, kk = r & 127;
        wf1[t] = __float2half(ff_w1[(long)l * 65536 + (long)kk * 512 + n]);
        return;
    }
    t -= 262144;
    if (t < 262144) {
        int l = (int)(t / 65536), r = (int)(t % 65536);
        int n = r / 512, kk = r % 512;
        wf2[t] = __float2half(ff_w2[(long)l * 65536 + (long)kk * 128 + n]);
        return;
    }
    t -= 262144;
    if (t < 16384) {
        int n = (int)(t >> 7), kk = (int)(t & 127);
        wp1[t] = __float2half(pre_w1[kk * 128 + n]);
    }
}

// =============== A-resident fp16 GEMM (K<=128), n-tile = blockIdx.x ==========
template <int EPI, int NK>
__global__ void __launch_bounds__(256, 2)
tgemmA(const __half* __restrict__ A, const __half* __restrict__ B,
       const float* __restrict__ bias, const float* __restrict__ res,
       const float* __restrict__ pos, const float* __restrict__ w2,
       float* __restrict__ C, __half* __restrict__ Ch,
       const float* __restrict__ lnsc, const float* __restrict__ lnbi,
       __half* __restrict__ lnout, int M, int Nfull) {
    extern __shared__ char sm[];
    __shared__ float red[2][128];
    __shared__ float lnred[2][128][2];
    uint32_t sb = smem_u32(sm);
    const int K = NK * 64;
    const uint32_t ABYTES = (uint32_t)NK * 16384u;
    int tid = threadIdx.x;
    int w = tid >> 5, lane = tid & 31;
    int wm = w & 3, wn = w >> 2;
    int m0 = blockIdx.y * 128;
    int nt = blockIdx.x;

    int rA[2], rB[4];
#pragma unroll
    for (int mi = 0; mi < 2; mi++) rA[mi] = wm * 32 + mi * 16 + (lane & 15);
#pragma unroll
    for (int ng = 0; ng < 4; ng++)
        rB[ng] = wn * 64 + ng * 16 + ((lane >> 4) << 3) + (lane & 7);
    int cA = lane >> 4;
    int cB = (lane >> 3) & 1;

#pragma unroll
    for (int chunk = 0; chunk < NK; chunk++) {
#pragma unroll
        for (int t = 0; t < 4; t++) {
            int idx = t * 256 + tid;
            int row = idx >> 3, c16 = idx & 7;
            uint32_t soff = row * 128 + (((uint32_t)c16 ^ (row & 7)) << 4);
            long ga = m0 + row;
            bool ok = ga < M;
            if (!ok) ga = 0;
            cpasync16(sb + (uint32_t)chunk * 16384u + soff,
                      A + ga * K + chunk * 64 + c16 * 8, ok ? 16u : 0u);
            long gb = (long)(nt * 128 + row);
            cpasync16(sb + ABYTES + (uint32_t)chunk * 16384u + soff,
                      B + gb * K + chunk * 64 + c16 * 8, 16u);
        }
        CP_COMMIT();
    }

    float acc[2][8][4];
#pragma unroll
    for (int i = 0; i < 2; i++)
#pragma unroll
        for (int j = 0; j < 8; j++)
#pragma unroll
            for (int q = 0; q < 4; q++) acc[i][j][q] = 0.f;

#pragma unroll
    for (int chunk = 0; chunk < NK; chunk++) {
        if (NK == 2 && chunk == 0) CP_WAIT(1);
        else CP_WAIT(0);
        __syncthreads();
        uint32_t Ab = sb + (uint32_t)chunk * 16384u;
        uint32_t Bb = sb + ABYTES + (uint32_t)chunk * 16384u;
#pragma unroll
        for (int ks = 0; ks < 4; ks++) {
            int kc = ks * 2;
            uint32_t fa[2][4], fb[4][4];
#pragma unroll
            for (int mi = 0; mi < 2; mi++) {
                int row = rA[mi];
                ldsm4(fa[mi], Ab + row * 128 + ((((uint32_t)(kc + cA)) ^ (row & 7)) << 4));
            }
#pragma unroll
            for (int ng = 0; ng < 4; ng++) {
                int row = rB[ng];
                ldsm4(fb[ng], Bb + row * 128 + ((((uint32_t)(kc + cB)) ^ (row & 7)) << 4));
            }
#pragma unroll
            for (int ng = 0; ng < 4; ng++)
#pragma unroll
                for (int mi = 0; mi < 2; mi++) {
                    mma16816(acc[mi][ng * 2],     fa[mi], fb[ng][0], fb[ng][1]);
                    mma16816(acc[mi][ng * 2 + 1], fa[mi], fb[ng][2], fb[ng][3]);
                }
        }
    }
    __syncthreads();

    int n0 = nt * 128;
    int tg = lane >> 2;
    int tc = (lane & 3) * 2;

    if (EPI == 5) {
        float p[2][2] = {};
#pragma unroll
        for (int mi = 0; mi < 2; mi++)
#pragma unroll
            for (int ni = 0; ni < 8; ni++) {
                int col = wn * 64 + ni * 8 + tc;
                float b0 = bias[col], b1 = bias[col + 1];
                float w20 = w2[col], w21 = w2[col + 1];
                p[mi][0] += fmaxf(acc[mi][ni][0] + b0, 0.f) * w20 +
                            fmaxf(acc[mi][ni][1] + b1, 0.f) * w21;
                p[mi][1] += fmaxf(acc[mi][ni][2] + b0, 0.f) * w20 +
                            fmaxf(acc[mi][ni][3] + b1, 0.f) * w21;
            }
#pragma unroll
        for (int mi = 0; mi < 2; mi++)
#pragma unroll
            for (int hf = 0; hf < 2; hf++) {
                float v = p[mi][hf];
                v += __shfl_xor_sync(~0u, v, 1);
                v += __shfl_xor_sync(~0u, v, 2);
                if ((lane & 3) == 0) red[wn][wm * 32 + mi * 16 + hf * 8 + tg] = v;
            }
        __syncthreads();
        if (tid < 128) {
            int row = m0 + tid;
            if (row < M) C[row] = red[0][tid] + red[1][tid] + pos[0];
        }
        return;
    }

    if (EPI == 0 || EPI == 4) {
        float scale = (EPI == 0 && nt == 0) ? 0.25f : 1.f;
#pragma unroll
        for (int mi = 0; mi < 2; mi++)
#pragma unroll
            for (int hf = 0; hf < 2; hf++) {
                int row = m0 + wm * 32 + mi * 16 + hf * 8 + tg;
                if (row >= M) continue;
#pragma unroll
                for (int ni = 0; ni < 8; ni++) {
                    int col = n0 + wn * 64 + ni * 8 + tc;
                    float v0 = acc[mi][ni][hf * 2 + 0];
                    float v1 = acc[mi][ni][hf * 2 + 1];
                    if (EPI == 4) {
                        v0 += bias[col];
                        v1 += bias[col + 1];
                        v0 = 0.5f * v0 * (1.f + erff(v0 * 0.70710678118654752f));
                        v1 = 0.5f * v1 * (1.f + erff(v1 * 0.70710678118654752f));
                    } else {
                        v0 *= scale;
                        v1 *= scale;
                    }
                    __half hl[2] = {__float2half(v0), __float2half(v1)};
                    *(uint32_t*)&Ch[(long)row * Nfull + col] = *(uint32_t*)hl;
                }
            }
        return;
    }

    // EPI 2/3
    float s1[2][2] = {}, s2[2][2] = {};
#pragma unroll
    for (int mi = 0; mi < 2; mi++)
#pragma unroll
        for (int hf = 0; hf < 2; hf++) {
            int row = m0 + wm * 32 + mi * 16 + hf * 8 + tg;
            bool rok = row < M;
            long pr = (EPI == 2 && rok) ? (long)(row % SEQ) * 128 : 0;
#pragma unroll
            for (int ni = 0; ni < 8; ni++) {
                int col = n0 + wn * 64 + ni * 8 + tc;
                float v0 = acc[mi][ni][hf * 2 + 0] + bias[col];
                float v1 = acc[mi][ni][hf * 2 + 1] + bias[col + 1];
                if (rok) {
                    if (EPI == 2) {
                        v0 += pos[pr + col];
                        v1 += pos[pr + col + 1];
                    } else {
                        v0 += res[(long)row * Nfull + col];
                        v1 += res[(long)row * Nfull + col + 1];
                    }
                    *(float2*)&C[(long)row * Nfull + col] = make_float2(v0, v1);
                }
                acc[mi][ni][hf * 2 + 0] = v0;
                acc[mi][ni][hf * 2 + 1] = v1;
                s1[mi][hf] += v0 + v1;
                s2[mi][hf] += v0 * v0 + v1 * v1;
            }
        }
    if (lnout) {
#pragma unroll
        for (int mi = 0; mi < 2; mi++)
#pragma unroll
            for (int hf = 0; hf < 2; hf++) {
                float a = s1[mi][hf], b = s2[mi][hf];
                a += __shfl_xor_sync(~0u, a, 1);
                a += __shfl_xor_sync(~0u, a, 2);
                b += __shfl_xor_sync(~0u, b, 1);
                b += __shfl_xor_sync(~0u, b, 2);
                if ((lane & 3) == 0) {
                    int ri = wm * 32 + mi * 16 + hf * 8 + tg;
                    lnred[wn][ri][0] = a;
                    lnred[wn][ri][1] = b;
                }
            }
        __syncthreads();
#pragma unroll
        for (int mi = 0; mi < 2; mi++)
#pragma unroll
            for (int hf = 0; hf < 2; hf++) {
                int ri = wm * 32 + mi * 16 + hf * 8 + tg;
                int row = m0 + ri;
                if (row >= M) continue;
                float m1 = (lnred[0][ri][0] + lnred[1][ri][0]) * (1.f / 128.f);
                float m2 = (lnred[0][ri][1] + lnred[1][ri][1]) * (1.f / 128.f);
                float inv = rsqrtf(m2 - m1 * m1 + 1e-5f);
#pragma unroll
                for (int ni = 0; ni < 8; ni++) {
                    int col = wn * 64 + ni * 8 + tc;
                    float v0 = (acc[mi][ni][hf * 2 + 0] - m1) * inv * lnsc[col] + lnbi[col];
                    float v1 = (acc[mi][ni][hf * 2 + 1] - m1) * inv * lnsc[col + 1] + lnbi[col + 1];
                    __half hl[2] = {__float2half(v0), __float2half(v1)};
                    *(uint32_t*)&lnout[(long)row * 128 + col] = *(uint32_t*)hl;
                }
            }
    }
}

// =============== 2-stage chunked fp16 GEMM for K=512 (ff2), 2 CTAs/SM ========
#define CSTAGE_B 32768u

__global__ void __launch_bounds__(256, 2)
tgemmC(const __half* __restrict__ A, const __half* __restrict__ B,
       const float* __restrict__ bias, const float* __restrict__ res,
       float* __restrict__ C, const float* __restrict__ lnsc,
       const float* __restrict__ lnbi, __half* __restrict__ lnout,
       int M, int N, int K) {
    extern __shared__ char sm[];
    __shared__ float lnred[2][128][2];
    uint32_t sb = smem_u32(sm);
    int tid = threadIdx.x;
    int w = tid >> 5, lane = tid & 31;
    int wm = w & 3, wn = w >> 2;
    int m0 = blockIdx.y * 128, n0 = blockIdx.x * 128;
    int nk = K >> 6;

    float acc[2][8][4];
#pragma unroll
    for (int i = 0; i < 2; i++)
#pragma unroll
        for (int j = 0; j < 8; j++)
#pragma unroll
            for (int q = 0; q < 4; q++) acc[i][j][q] = 0.f;

    int rA[2], rB[4];
#pragma unroll
    for (int mi = 0; mi < 2; mi++) rA[mi] = wm * 32 + mi * 16 + (lane & 15);
#pragma unroll
    for (int ng = 0; ng < 4; ng++)
        rB[ng] = wn * 64 + ng * 16 + ((lane >> 4) << 3) + (lane & 7);
    int cA = lane >> 4;
    int cB = (lane >> 3) & 1;

    auto load_stage = [&](int c, int buf) {
#pragma unroll
        for (int it = 0; it < 8; it++) {
            int slot = it * 256 + tid;
            int t = it >> 2;
            int row = (slot >> 3) & 127;
            int chunk = slot & 7;
            const __half* src = t ? B : A;
            long grow = t ? (long)(n0 + row) : (long)(m0 + row);
            bool ok = t ? true : (m0 + row < M);
            if (!ok) grow = 0;
            const void* g = (const void*)(src + grow * K + ((long)c << 6) + chunk * 8);
            uint32_t saddr = sb + buf * CSTAGE_B + (uint32_t)t * 16384u + row * 128 +
                             ((chunk ^ (row & 7)) << 4);
            cpasync16(saddr, g, ok ? 16u : 0u);
        }
        CP_COMMIT();
    };

    load_stage(0, 0);

    for (int c = 0; c < nk; c++) {
        if (c + 1 < nk) {
            load_stage(c + 1, (c + 1) & 1);
            CP_WAIT(1);
        } else {
            CP_WAIT(0);
        }
        __syncthreads();

        uint32_t st = sb + (c & 1) * CSTAGE_B;
#pragma unroll
        for (int ks = 0; ks < 4; ks++) {
            int kc = ks * 2;
            uint32_t fa[2][4], fb[4][4];
#pragma unroll
            for (int mi = 0; mi < 2; mi++) {
                int row = rA[mi];
                ldsm4(fa[mi], st + row * 128 + ((((uint32_t)(kc + cA)) ^ (row & 7)) << 4));
            }
#pragma unroll
            for (int ng = 0; ng < 4; ng++) {
                int row = rB[ng];
                ldsm4(fb[ng], st + 16384u + row * 128 + ((((uint32_t)(kc + cB)) ^ (row & 7)) << 4));
            }
#pragma unroll
            for (int ng = 0; ng < 4; ng++)
#pragma unroll
                for (int mi = 0; mi < 2; mi++) {
                    mma16816(acc[mi][ng * 2],     fa[mi], fb[ng][0], fb[ng][1]);
                    mma16816(acc[mi][ng * 2 + 1], fa[mi], fb[ng][2], fb[ng][3]);
                }
        }
        __syncthreads();
    }

    int tg = lane >> 2;
    int tc = (lane & 3) * 2;
    float s1[2][2] = {}, s2[2][2] = {};
#pragma unroll
    for (int mi = 0; mi < 2; mi++)
#pragma unroll
        for (int hf = 0; hf < 2; hf++) {
            int row = m0 + wm * 32 + mi * 16 + hf * 8 + tg;
            bool rok = row < M;
#pragma unroll
            for (int ni = 0; ni < 8; ni++) {
                int col = n0 + wn * 64 + ni * 8 + tc;
                float v0 = acc[mi][ni][hf * 2 + 0] + bias[col];
                float v1 = acc[mi][ni][hf * 2 + 1] + bias[col + 1];
                if (rok) {
                    v0 += res[(long)row * N + col];
                    v1 += res[(long)row * N + col + 1];
                    *(float2*)&C[(long)row * N + col] = make_float2(v0, v1);
                }
                acc[mi][ni][hf * 2 + 0] = v0;
                acc[mi][ni][hf * 2 + 1] = v1;
                s1[mi][hf] += v0 + v1;
                s2[mi][hf] += v0 * v0 + v1 * v1;
            }
        }
    if (lnout && lnsc) {
#pragma unroll
        for (int mi = 0; mi < 2; mi++)
#pragma unroll
            for (int hf = 0; hf < 2; hf++) {
                float a = s1[mi][hf], b = s2[mi][hf];
                a += __shfl_xor_sync(~0u, a, 1);
                a += __shfl_xor_sync(~0u, a, 2);
                b += __shfl_xor_sync(~0u, b, 1);
                b += __shfl_xor_sync(~0u, b, 2);
                if ((lane & 3) == 0) {
                    int ri = wm * 32 + mi * 16 + hf * 8 + tg;
                    lnred[wn][ri][0] = a;
                    lnred[wn][ri][1] = b;
                }
            }
        __syncthreads();
#pragma unroll
        for (int mi = 0; mi < 2; mi++)
#pragma unroll
            for (int hf = 0; hf < 2; hf++) {
                int ri = wm * 32 + mi * 16 + hf * 8 + tg;
                int row = m0 + ri;
                if (row >= M) continue;
                float m1 = (lnred[0][ri][0] + lnred[1][ri][0]) * (1.f / 128.f);
                float m2 = (lnred[0][ri][1] + lnred[1][ri][1]) * (1.f / 128.f);
                float inv = rsqrtf(m2 - m1 * m1 + 1e-5f);
#pragma unroll
                for (int ni = 0; ni < 8; ni++) {
                    int col = wn * 64 + ni * 8 + tc;
                    float v0 = (acc[mi][ni][hf * 2 + 0] - m1) * inv * lnsc[col] + lnbi[col];
                    float v1 = (acc[mi][ni][hf * 2 + 1] - m1) * inv * lnsc[col + 1] + lnbi[col + 1];
                    __half hl[2] = {__float2half(v0), __float2half(v1)};
                    *(uint32_t*)&lnout[(long)row * 128 + col] = *(uint32_t*)hl;
                }
            }
    } else if (lnout) {
#pragma unroll
        for (int mi = 0; mi < 2; mi++)
#pragma unroll
            for (int hf = 0; hf < 2; hf++) {
                int row = m0 + wm * 32 + mi * 16 + hf * 8 + tg;
                if (row >= M) continue;
#pragma unroll
                for (int ni = 0; ni < 8; ni++) {
                    int col = n0 + wn * 64 + ni * 8 + tc;
                    __half hl[2] = {__float2half(acc[mi][ni][hf * 2 + 0]),
                                    __float2half(acc[mi][ni][hf * 2 + 1])};
                    *(uint32_t*)&lnout[(long)row * 128 + col] = *(uint32_t*)hl;
                }
            }
    }
}

// ---------------- MMA attention: maskless via zero-K/V + sum correction ------
// Padded K rows are 0 -> masked scores = 0 -> exp = 1 exactly; padded V rows
// are 0 -> no numerator pollution. Correct denominator by subtracting
// (192 - cnt) once per row. No per-element masking ALU at all.
__global__ void __launch_bounds__(128, 6)
attn_k(const __half* __restrict__ qkv, __half* __restrict__ o) {
    __shared__ __half q_s[64 * 24];
    __shared__ __half k_s[192 * 24];
    __shared__ __half v_s[192 * 24];
    int w = blockIdx.x, bh = blockIdx.y;
    int b = bh >> 3, h = bh & 7;
    int tid = threadIdx.x, warp = tid >> 5, lane = tid & 31;
    int jstart = (w > 0) ? 0 : S1;
    int jend = (w < S1 - 1) ? 3 * S1 : 2 * S1;
    int cnt = jend - jstart;
    long rb = (long)b * SEQ;
    const uint4* qg = (const uint4*)qkv;
    const uint4 z4 = make_uint4(0, 0, 0, 0);

#pragma unroll
    for (int rr = 0; rr < 2; rr++) {
        int r = tid + rr * 128;
        if (r < 192) {
            bool ok = r < cnt;
            long base = (rb + (long)(w - 1) * S1 + jstart + (ok ? r : 0)) * 48 + h * 2;
            uint4 ka = ok ? qg[base + 16] : z4;
            uint4 kc = ok ? qg[base + 17] : z4;
            uint4 va = ok ? qg[base + 32] : z4;
            uint4 vc = ok ? qg[base + 33] : z4;
            *(uint4*)&k_s[r * 24] = ka;
            *(uint4*)&k_s[r * 24 + 8] = kc;
            *(uint4*)&v_s[r * 24] = va;
            *(uint4*)&v_s[r * 24 + 8] = vc;
        }
    }
    if (tid < 64) {
        bool ok = tid < S1;
        long base = (rb + (long)w * S1 + (ok ? tid : 0)) * 48 + h * 2;
        uint4 qa = ok ? qg[base] : z4;
        uint4 qc = ok ? qg[base + 1] : z4;
        *(uint4*)&q_s[tid * 24] = qa;
        *(uint4*)&q_s[tid * 24 + 8] = qc;
    }
    __syncthreads();

    uint32_t qb = smem_u32(q_s), kbb = smem_u32(k_s), vbb = smem_u32(v_s);

    uint32_t a[4];
    ldsm4(a, qb + (uint32_t)(warp * 16 + ((lane >> 3) & 1) * 8 + (lane & 7)) * 48 +
              (lane >> 4) * 16);

    float lsum[2] = {0.f, 0.f};
    float oa[2][4] = {{0.f, 0.f, 0.f, 0.f}, {0.f, 0.f, 0.f, 0.f}};

#pragma unroll
    for (int sub = 0; sub < 4; sub++) {
        int kb = sub * 48;
        float s[6][4];
#pragma unroll
        for (int ti = 0; ti < 6; ti++)
#pragma unroll
            for (int e = 0; e < 4; e++) s[ti][e] = 0.f;
#pragma unroll
        for (int g = 0; g < 3; g++) {
            uint32_t r[4];
            ldsm4(r, kbb + (uint32_t)(kb + g * 16 + (lane >> 4) * 8 + (lane & 7)) * 48 +
                       ((lane >> 3) & 1) * 16);
            mma16816(s[g * 2],     a, r[0], r[1]);
            mma16816(s[g * 2 + 1], a, r[2], r[3]);
        }
        // maskless exp + rowsum + pack
        uint32_t ph[6][2];
#pragma unroll
        for (int ti = 0; ti < 6; ti++) {
            float p0 = __expf(s[ti][0]);
            float p1 = __expf(s[ti][1]);
            float p2 = __expf(s[ti][2]);
            float p3 = __expf(s[ti][3]);
            lsum[0] += p0 + p1;
            lsum[1] += p2 + p3;
            __half2 h01 = __floats2half2_rn(p0, p1);
            __half2 h23 = __floats2half2_rn(p2, p3);
            ph[ti][0] = *(uint32_t*)&h01;
            ph[ti][1] = *(uint32_t*)&h23;
        }
#pragma unroll
        for (int g = 0; g < 3; g++) {
            uint32_t r[4];
            ldsm4t(r, vbb + (uint32_t)(kb + g * 16 + ((lane >> 3) & 1) * 8 + (lane & 7)) * 48 +
                        (lane >> 4) * 16);
            uint32_t pa[4] = {ph[g * 2][0], ph[g * 2][1], ph[g * 2 + 1][0], ph[g * 2 + 1][1]};
            mma16816(oa[0], pa, r[0], r[1]);
            mma16816(oa[1], pa, r[2], r[3]);
        }
    }

#pragma unroll
    for (int i = 0; i < 2; i++) {
        lsum[i] += __shfl_xor_sync(~0u, lsum[i], 1);
        lsum[i] += __shfl_xor_sync(~0u, lsum[i], 2);
    }
    // denominator correction: each of (192 - cnt) padded columns added exp(0)=1
    float corr = (float)(192 - cnt);
    float inv0 = 1.f / (lsum[0] - corr);
    float inv1 = 1.f / (lsum[1] - corr);

    int tg = lane >> 2, tc = (lane & 3) * 2;
    int i0 = warp * 16 + tg;
    int i1 = i0 + 8;
    if (i0 < S1) {
        long orow = (rb + (long)w * S1 + i0) * 128 + h * 16;
        __half2 d0 = __floats2half2_rn(oa[0][0] * inv0, oa[0][1] * inv0);
        __half2 d1 = __floats2half2_rn(oa[1][0] * inv0, oa[1][1] * inv0);
        *(uint32_t*)&o[orow + tc] = *(uint32_t*)&d0;
        *(uint32_t*)&o[orow + 8 + tc] = *(uint32_t*)&d1;
    }
    if (i1 < S1) {
        long orow = (rb + (long)w * S1 + i1) * 128 + h * 16;
        __half2 d0 = __floats2half2_rn(oa[0][2] * inv1, oa[0][3] * inv1);
        __half2 d1 = __floats2half2_rn(oa[1][2] * inv1, oa[1][3] * inv1);
        *(uint32_t*)&o[orow + tc] = *(uint32_t*)&d0;
        *(uint32_t*)&o[orow + 8 + tc] = *(uint32_t*)&d1;
    }
}

// ---------------- launch ------------------------------------------------------
extern "C" void kernel_launch(void* const* d_in, const int* in_sizes, int n_in,
                              void* d_out, int out_size) {
    const float* x      = (const float*)d_in[0];
    const float* conv_w = (const float*)d_in[1];
    const float* conv_b = (const float*)d_in[2];
    const float* lt_w   = (const float*)d_in[3];
    const float* lt_b   = (const float*)d_in[4];
    const float* pos    = (const float*)d_in[5];
    const float* ln1_s  = (const float*)d_in[6];
    const float* ln1_b  = (const float*)d_in[7];
    const float* wq     = (const float*)d_in[8];
    const float* wk     = (const float*)d_in[9];
    const float* wv     = (const float*)d_in[10];
    const float* wo     = (const float*)d_in[11];
    const float* wo_b   = (const float*)d_in[12];
    const float* ln2_s  = (const float*)d_in[13];
    const float* ln2_b  = (const float*)d_in[14];
    const float* ff_w1  = (const float*)d_in[15];
    const float* ff_b1  = (const float*)d_in[16];
    const float* ff_w2  = (const float*)d_in[17];
    const float* ff_b2  = (const float*)d_in[18];
    const float* pre_w1 = (const float*)d_in[19];
    const float* pre_b1 = (const float*)d_in[20];
    const float* pre_w2 = (const float*)d_in[21];
    const float* pre_b2 = (const float*)d_in[22];
    float* out = (float*)d_out;

    static bool attr_done = false;
    if (!attr_done) {
        cudaFuncSetAttribute(tgemmA<0,2>, cudaFuncAttributeMaxDynamicSharedMemorySize, 65536);
        cudaFuncSetAttribute(tgemmA<2,1>, cudaFuncAttributeMaxDynamicSharedMemorySize, 32768);
        cudaFuncSetAttribute(tgemmA<3,2>, cudaFuncAttributeMaxDynamicSharedMemorySize, 65536);
        cudaFuncSetAttribute(tgemmA<4,2>, cudaFuncAttributeMaxDynamicSharedMemorySize, 65536);
        cudaFuncSetAttribute(tgemmA<5,2>, cudaFuncAttributeMaxDynamicSharedMemorySize, 65536);
        cudaFuncSetAttribute(tgemmC, cudaFuncAttributeMaxDynamicSharedMemorySize, 65536);
        attr_done = true;
    }

    __half *p, *lnb, *att, *ff, *hh, *wlt, *wqkv, *woh, *wf1, *wf2, *wp1, *qkvh;
    float *h;
    cudaGetSymbolAddress((void**)&p, g_p);       cudaGetSymbolAddress((void**)&h, g_h);
    cudaGetSymbolAddress((void**)&lnb, g_ln);    cudaGetSymbolAddress((void**)&qkvh, g_qkv);
    cudaGetSymbolAddress((void**)&att, g_att);   cudaGetSymbolAddress((void**)&ff, g_ff);
    cudaGetSymbolAddress((void**)&hh, g_hh);     cudaGetSymbolAddress((void**)&wlt, g_wlt);
    cudaGetSymbolAddress((void**)&wqkv, g_wqkv); cudaGetSymbolAddress((void**)&woh, g_wo);
    cudaGetSymbolAddress((void**)&wf1, g_wf1);   cudaGetSymbolAddress((void**)&wf2, g_wf2);
    cudaGetSymbolAddress((void**)&wp1, g_wp1);

    const int M = MROWS;

    conv_prep<<<(CONV_TOTAL + PREP_TOTAL + 255) / 256, 256>>>(
        x, conv_w, conv_b, p, lt_w, wq, wk, wv, wo, ff_w1, ff_w2, pre_w1,
        wlt, wqkv, woh, wf1, wf2, wp1);
    tgemmA<2,1><<<dim3(1, MTILES), 256, 32768>>>(p, wlt, lt_b, nullptr, pos, nullptr,
                                                 h, nullptr, ln1_s, ln1_b, lnb, M, 128);

    for (int i = 0; i < NLAYER; i++) {
        tgemmA<0,2><<<dim3(3, MTILES), 256, 65536>>>(lnb, wqkv + (long)i * 49152,
            nullptr, nullptr, nullptr, nullptr, nullptr, qkvh,
            nullptr, nullptr, nullptr, M, 384);
        attn_k<<<dim3(S1, BATCH * HEADS), 128>>>(qkvh, att);
        tgemmA<3,2><<<dim3(1, MTILES), 256, 65536>>>(att, woh + (long)i * 16384,
            wo_b + i * 128, h, nullptr, nullptr, h, nullptr,
            ln2_s + i * 128, ln2_b + i * 128, lnb, M, 128);
        tgemmA<4,2><<<dim3(4, MTILES), 256, 65536>>>(lnb, wf1 + (long)i * 65536,
            ff_b1 + i * 512, nullptr, nullptr, nullptr, nullptr, ff,
            nullptr, nullptr, nullptr, M, 512);
        bool last = (i == NLAYER - 1);
        tgemmC<<<dim3(1, MTILES), 256, 65536>>>(ff, wf2 + (long)i * 65536,
            ff_b2 + i * 128, h, h,
            last ? nullptr : ln1_s + (i + 1) * 128,
            last ? nullptr : ln1_b + (i + 1) * 128,
            last ? hh : lnb, M, 128, 512);
    }

    tgemmA<5,2><<<dim3(1, MTILES), 256, 65536>>>(hh, wp1, pre_b1, nullptr, pre_b2, pre_w2,
                                                 out, nullptr, nullptr, nullptr, nullptr, M, 128);
}